// round 2
// baseline (speedup 1.0000x reference)
#include <cuda_runtime.h>
#include <math.h>

// ---------------- problem constants ----------------
namespace {
constexpr int B_   = 4;
constexpr int S_   = 1024;
constexpr int DIM_ = 2048;
constexpr int H_   = 16;
constexpr int QKSP_ = 192;   // NOPE(128) + ROPE(64)
constexpr int KVR_  = 512;
constexpr int M_    = B_ * S_;          // 4096 tokens
constexpr float TWO_SCALE = 0.14396396f; // 2 / sqrt(193)
}

// ---------------- scratch (device globals; no allocs allowed) ----------------
__device__ float g_q   [(size_t)M_ * H_ * QKSP_];        // (B,S,H,192)
__device__ float g_kva [(size_t)M_ * 576];               // (B,S,576)
__device__ float g_kvn [(size_t)M_ * 513];               // (B,S,513)  [t, sp]
__device__ float g_kpe [(size_t)M_ * 64];                // (B,S,64) roped
__device__ float g_kv2 [(size_t)M_ * H_ * 256];          // (B,S,H,256)
__device__ float g_qaug[(size_t)B_ * H_ * S_ * 193];     // (B,H,S,193)  [-qt, q]
__device__ float g_kaug[(size_t)B_ * H_ * S_ * 193];     // (B,H,S,193)  [+kt, k]
__device__ float g_vT  [(size_t)B_ * H_ * 129 * S_];     // (B,H,129,S)  [vt; v]^T
__device__ float g_probs[(size_t)B_ * H_ * S_ * S_];     // (B,H,S,S)
__device__ float g_avg [(size_t)B_ * H_ * S_ * 129];     // (B,H,S,129)
__device__ float g_cent[(size_t)M_ * 2064];              // (B,S,H*129)

// ---------------- reductions ----------------
__device__ __forceinline__ float block_sum_256(float v, float* sh) {
    int tid = threadIdx.x;
#pragma unroll
    for (int o = 16; o; o >>= 1) v += __shfl_xor_sync(0xffffffffu, v, o);
    __syncthreads();                      // protect sh from previous use
    if ((tid & 31) == 0) sh[tid >> 5] = v;
    __syncthreads();
    if (tid < 32) {
        float t = (tid < 8) ? sh[tid] : 0.f;
#pragma unroll
        for (int o = 4; o; o >>= 1) t += __shfl_xor_sync(0xffffffffu, t, o);
        if (tid == 0) sh[0] = t;
    }
    __syncthreads();
    return sh[0];
}

__device__ __forceinline__ float warp_sum(float v) {
#pragma unroll
    for (int o = 16; o; o >>= 1) v += __shfl_xor_sync(0xffffffffu, v, o);
    return v;
}

// ---------------- generic batched TN SGEMM ----------------
// C[m,n] = sum_k A[m,k] * W[n,k] (+ bias[n]).  A: M x K (lda), W: N x K (ldw),
// C: M x N (ldc). Batched over blockIdx.z with element strides sA/sW/sC.
// CAUSAL=true skips tiles entirely above the diagonal (M==N assumed there).
template <bool CAUSAL>
__global__ void __launch_bounds__(256)
gemm_tn_kernel(const float* __restrict__ A, int lda, long sA,
               const float* __restrict__ W, int ldw, long sW,
               float* __restrict__ C, int ldc, long sC,
               const float* __restrict__ bias,
               int M, int N, int K)
{
    constexpr int BM = 128, BN = 128, BK = 16, TM = 8, TN = 8;
    __shared__ float As[BK][BM + 4];
    __shared__ float Ws[BK][BN + 4];

    const int bm = blockIdx.y * BM;
    const int bn = blockIdx.x * BN;
    if (CAUSAL && bn > bm + BM - 1) return;

    const int z = blockIdx.z;
    A += (long)z * sA;  W += (long)z * sW;  C += (long)z * sC;

    const int tid = threadIdx.x;
    const int tx = tid & 15;         // 0..15 -> N
    const int ty = tid >> 4;         // 0..15 -> M

    float acc[TM][TN] = {};

    for (int k0 = 0; k0 < K; k0 += BK) {
#pragma unroll
        for (int i = tid; i < BM * BK; i += 256) {
            int m = i >> 4, kk = i & 15;
            int gm = bm + m, gk = k0 + kk;
            As[kk][m] = (gm < M && gk < K) ? A[(long)gm * lda + gk] : 0.f;
        }
#pragma unroll
        for (int i = tid; i < BN * BK; i += 256) {
            int n = i >> 4, kk = i & 15;
            int gn = bn + n, gk = k0 + kk;
            Ws[kk][n] = (gn < N && gk < K) ? W[(long)gn * ldw + gk] : 0.f;
        }
        __syncthreads();
#pragma unroll
        for (int kk = 0; kk < BK; ++kk) {
            float4 a0 = *(const float4*)(&As[kk][ty * TM]);
            float4 a1 = *(const float4*)(&As[kk][ty * TM + 4]);
            float4 b0 = *(const float4*)(&Ws[kk][tx * TN]);
            float4 b1 = *(const float4*)(&Ws[kk][tx * TN + 4]);
            float ar[TM] = {a0.x, a0.y, a0.z, a0.w, a1.x, a1.y, a1.z, a1.w};
            float wr[TN] = {b0.x, b0.y, b0.z, b0.w, b1.x, b1.y, b1.z, b1.w};
#pragma unroll
            for (int i = 0; i < TM; ++i)
#pragma unroll
                for (int j = 0; j < TN; ++j)
                    acc[i][j] = fmaf(ar[i], wr[j], acc[i][j]);
        }
        __syncthreads();
    }

#pragma unroll
    for (int i = 0; i < TM; ++i) {
        int gm = bm + ty * TM + i;
        if (gm >= M) continue;
#pragma unroll
        for (int j = 0; j < TN; ++j) {
            int gn = bn + tx * TN + j;
            if (gn >= N) continue;
            float v = acc[i][j];
            if (bias) v += bias[gn];
            C[(long)gm * ldc + gn] = v;
        }
    }
}

// ---------------- RMSNorm(kv) + project + k_pe RoPE ----------------
__global__ void __launch_bounds__(256)
rmsnorm_kpe_kernel(const float* __restrict__ kva, const float* __restrict__ w,
                   const float* __restrict__ fc, const float* __restrict__ fs,
                   float* __restrict__ kvn, float* __restrict__ kpe)
{
    const int tok = blockIdx.x;
    const int s = tok & (S_ - 1);
    const float* in = kva + (size_t)tok * 576;
    const int tid = threadIdx.x;
    __shared__ float sp[512];
    __shared__ float sh[8];

    float local = 0.f;
    for (int i = tid; i < 512; i += 256) { float v = in[i]; local += v * v; }
    float tot = block_sum_256(local, sh);
    float r = rsqrtf(tot * (1.0f / 512.f) + 1e-6f);

    float l2 = 0.f;
    for (int i = tid; i < 512; i += 256) {
        float v = in[i] * r * w[i];
        sp[i] = v;
        l2 += v * v;
    }
    float tot2 = block_sum_256(l2, sh);

    float* out = kvn + (size_t)tok * 513;
    if (tid == 0) out[0] = sqrtf(tot2 + 1.f);
    for (int i = tid; i < 512; i += 256) out[1 + i] = sp[i];

    if (tid < 32) {
        float x1 = in[512 + 2 * tid], x2 = in[512 + 2 * tid + 1];
        float c = fc[s * 32 + tid], sn = fs[s * 32 + tid];
        kpe[(size_t)tok * 64 + 2 * tid]     = x1 * c - x2 * sn;
        kpe[(size_t)tok * 64 + 2 * tid + 1] = x1 * sn + x2 * c;
    }
}

// ---------------- Q: RoPE + project -> (B,H,S,193) with slot0 = -qt ----------------
__global__ void __launch_bounds__(256)
post_q_kernel(const float* __restrict__ q, const float* __restrict__ fc,
              const float* __restrict__ fs, float* __restrict__ qaug)
{
    int gw = (blockIdx.x * blockDim.x + threadIdx.x) >> 5;
    int lane = threadIdx.x & 31;
    if (gw >= M_ * H_) return;
    int h = gw % H_;
    int tok = gw / H_;
    int b = tok / S_, s = tok & (S_ - 1);

    const float* qr = q + ((size_t)tok * H_ + h) * QKSP_;
    float c = fc[s * 32 + lane], sn = fs[s * 32 + lane];
    float x1 = qr[128 + 2 * lane], x2 = qr[128 + 2 * lane + 1];
    float r0 = x1 * c - x2 * sn;
    float r1 = x1 * sn + x2 * c;

    float ss = r0 * r0 + r1 * r1;
    for (int d = lane; d < 128; d += 32) { float v = qr[d]; ss += v * v; }
    ss = warp_sum(ss);

    float* out = qaug + (((size_t)b * H_ + h) * S_ + s) * 193;
    if (lane == 0) out[0] = -sqrtf(ss + 1.f);
    for (int d = lane; d < 128; d += 32) out[1 + d] = qr[d];
    out[1 + 128 + 2 * lane]     = r0;
    out[1 + 128 + 2 * lane + 1] = r1;
}

// ---------------- K/V: assemble k=[k_nope, k_pe], project; v -> vT ----------------
__global__ void __launch_bounds__(256)
post_kv_kernel(const float* __restrict__ kv2, const float* __restrict__ kpe,
               float* __restrict__ kaug, float* __restrict__ vT)
{
    int gw = (blockIdx.x * blockDim.x + threadIdx.x) >> 5;
    int lane = threadIdx.x & 31;
    if (gw >= M_ * H_) return;
    int h = gw % H_;
    int tok = gw / H_;
    int b = tok / S_, s = tok & (S_ - 1);

    const float* row = kv2 + ((size_t)tok * H_ + h) * 256;
    const float* pe  = kpe + (size_t)tok * 64;

    float ss = 0.f;
    for (int d = lane; d < 128; d += 32) { float v = row[d]; ss += v * v; }
    for (int d = lane; d < 64;  d += 32) { float v = pe[d];  ss += v * v; }
    ss = warp_sum(ss);

    float* ko = kaug + (((size_t)b * H_ + h) * S_ + s) * 193;
    if (lane == 0) ko[0] = sqrtf(ss + 1.f);
    for (int d = lane; d < 128; d += 32) ko[1 + d] = row[d];
    for (int d = lane; d < 64;  d += 32) ko[129 + d] = pe[d];

    float sv = 0.f;
    for (int d = lane; d < 128; d += 32) { float v = row[128 + d]; sv += v * v; }
    sv = warp_sum(sv);

    float* vo = vT + ((size_t)b * H_ + h) * 129 * S_;
    if (lane == 0) vo[s] = sqrtf(sv + 1.f);
    for (int d = lane; d < 128; d += 32) vo[(size_t)(1 + d) * S_ + s] = row[128 + d];
}

// ---------------- causal softmax over raw q~.k~ scores (in place) ----------------
__global__ void __launch_bounds__(256)
softmax_kernel(float* __restrict__ P)
{
    const int row = blockIdx.x;          // (b*H + h)*S + s
    const int s = row & (S_ - 1);
    float* p = P + (size_t)row * S_;
    const int tid = threadIdx.x;
    __shared__ float sh[8];

    float mx = -1e30f;
    for (int t = tid; t <= s; t += 256) mx = fmaxf(mx, p[t]);
#pragma unroll
    for (int o = 16; o; o >>= 1) mx = fmaxf(mx, __shfl_xor_sync(0xffffffffu, mx, o));
    if ((tid & 31) == 0) sh[tid >> 5] = mx;
    __syncthreads();
    if (tid < 32) {
        float v = (tid < 8) ? sh[tid] : -1e30f;
#pragma unroll
        for (int o = 4; o; o >>= 1) v = fmaxf(v, __shfl_xor_sync(0xffffffffu, v, o));
        if (tid == 0) sh[0] = v;
    }
    __syncthreads();
    mx = sh[0];
    __syncthreads();

    float sum = 0.f;
    for (int t = tid; t <= s; t += 256) {
        float e = __expf(TWO_SCALE * (p[t] - mx));
        p[t] = e;
        sum += e;
    }
    float tot = block_sum_256(sum, sh);
    float inv = 1.f / tot;
    for (int t = tid; t <= s; t += 256) p[t] *= inv;
    for (int t = s + 1 + tid; t < S_; t += 256) p[t] = 0.f;
}

// ---------------- centroid normalization -> (B,S,H*129) ----------------
__global__ void __launch_bounds__(256)
cent_kernel(const float* __restrict__ avg, float* __restrict__ cent)
{
    int gw = (blockIdx.x * blockDim.x + threadIdx.x) >> 5;
    int lane = threadIdx.x & 31;
    if (gw >= M_ * H_) return;
    int h = gw % H_;
    int tok = gw / H_;
    int b = tok / S_, s = tok & (S_ - 1);

    const float* a = avg + (((size_t)b * H_ + h) * S_ + s) * 129;
    float a0 = a[0];
    float ss = 0.f;
    for (int d = lane; d < 128; d += 32) { float v = a[1 + d]; ss += v * v; }
    ss = warp_sum(ss);
    float neg = a0 * a0 - ss;
    float denom = rsqrtf(fmaxf(fabsf(neg), 1e-8f));

    float* o = cent + (size_t)tok * 2064 + h * 129;
    if (lane == 0) o[0] = a0 * denom;
    for (int d = lane; d < 128; d += 32) o[1 + d] = a[1 + d] * denom;
}

// ---------------- final Lorentz time component of the output ----------------
__global__ void __launch_bounds__(256)
final_t_kernel(float* __restrict__ out)
{
    const int row = blockIdx.x;
    float* p = out + (size_t)row * 2048;
    const int tid = threadIdx.x;
    __shared__ float sh[8];
    float local = 0.f;
    for (int i = 1 + tid; i < 2048; i += 256) { float v = p[i]; local += v * v; }
    float tot = block_sum_256(local, sh);
    if (tid == 0) p[0] = sqrtf(tot + 1.f);
}

// ---------------- launcher ----------------
extern "C" void kernel_launch(void* const* d_in, const int* in_sizes, int n_in,
                              void* d_out, int out_size)
{
    (void)in_sizes; (void)n_in; (void)out_size;
    const float* x      = (const float*)d_in[0];
    const float* fc     = (const float*)d_in[1];
    const float* fs     = (const float*)d_in[2];
    /* d_in[3] = mask (causal; hardcoded) */
    const float* wq_w   = (const float*)d_in[4];
    const float* wq_b   = (const float*)d_in[5];
    const float* wkva_w = (const float*)d_in[6];
    const float* wkva_b = (const float*)d_in[7];
    const float* kvnw   = (const float*)d_in[8];
    const float* wkvb_w = (const float*)d_in[9];
    const float* wkvb_b = (const float*)d_in[10];
    const float* wo_w   = (const float*)d_in[11];
    const float* wo_b   = (const float*)d_in[12];
    float* out = (float*)d_out;

    float *q, *kva, *kvn, *kpe, *kv2, *qaug, *kaug, *vT, *probs, *avg, *cent;
    cudaGetSymbolAddress((void**)&q,    g_q);
    cudaGetSymbolAddress((void**)&kva,  g_kva);
    cudaGetSymbolAddress((void**)&kvn,  g_kvn);
    cudaGetSymbolAddress((void**)&kpe,  g_kpe);
    cudaGetSymbolAddress((void**)&kv2,  g_kv2);
    cudaGetSymbolAddress((void**)&qaug, g_qaug);
    cudaGetSymbolAddress((void**)&kaug, g_kaug);
    cudaGetSymbolAddress((void**)&vT,   g_vT);
    cudaGetSymbolAddress((void**)&probs,g_probs);
    cudaGetSymbolAddress((void**)&avg,  g_avg);
    cudaGetSymbolAddress((void**)&cent, g_cent);

    dim3 blk(256);

    // 1. Q projection: (4096 x 2048) @ (3072 x 2048)^T
    gemm_tn_kernel<false><<<dim3(24, 32, 1), blk>>>(
        x, DIM_, 0, wq_w, DIM_, 0, q, H_ * QKSP_, 0, wq_b, M_, H_ * QKSP_, DIM_);

    // 2. KV-A projection: (4096 x 2048) @ (576 x 2048)^T
    gemm_tn_kernel<false><<<dim3(5, 32, 1), blk>>>(
        x, DIM_, 0, wkva_w, DIM_, 0, kva, 576, 0, wkva_b, M_, 576, DIM_);

    // 3. RMSNorm + project(kv) + k_pe RoPE
    rmsnorm_kpe_kernel<<<M_, blk>>>(kva, kvnw, fc, fs, kvn, kpe);

    // 4. KV-B projection: (4096 x 513) @ (4096 x 513)^T
    gemm_tn_kernel<false><<<dim3(32, 32, 1), blk>>>(
        kvn, 513, 0, wkvb_w, 513, 0, kv2, H_ * 256, 0, wkvb_b, M_, H_ * 256, 513);

    // 5/6. build augmented q~, k~, v~^T
    post_q_kernel<<<(M_ * H_) / 8, blk>>>(q, fc, fs, qaug);
    post_kv_kernel<<<(M_ * H_) / 8, blk>>>(kv2, kpe, kaug, vT);

    // 7. batched causal scores: per (b,h)  q~(1024x193) @ k~(1024x193)^T
    gemm_tn_kernel<true><<<dim3(8, 8, B_ * H_), blk>>>(
        qaug, 193, (long)S_ * 193, kaug, 193, (long)S_ * 193,
        probs, S_, (long)S_ * S_, nullptr, S_, S_, 193);

    // 8. causal softmax
    softmax_kernel<<<B_ * H_ * S_, blk>>>(probs);

    // 9. batched PV: per (b,h)  P(1024x1024) @ vT(129x1024)^T
    gemm_tn_kernel<false><<<dim3(2, 8, B_ * H_), blk>>>(
        probs, S_, (long)S_ * S_, vT, S_, (long)129 * S_,
        avg, 129, (long)S_ * 129, nullptr, S_, 129, S_);

    // 10. centroid normalize -> (B,S,2064)
    cent_kernel<<<(M_ * H_) / 8, blk>>>(avg, cent);

    // 11. output projection -> d_out columns [1..2047]
    gemm_tn_kernel<false><<<dim3(16, 32, 1), blk>>>(
        cent, 2064, 0, wo_w, 2064, 0, out + 1, 2048, 0, wo_b, M_, 2047, 2064);

    // 12. output time component -> column 0
    final_t_kernel<<<M_, blk>>>(out);
}

// round 4
// speedup vs baseline: 2.4767x; 2.4767x over previous
#include <cuda_runtime.h>
#include <cuda_bf16.h>
#include <math.h>
#include <stdint.h>

namespace {
constexpr int B_ = 4, S_ = 1024, H_ = 16;
constexpr int M_ = B_ * S_;
constexpr float TWO_SCALE = 0.14396396f;
constexpr int KQA = 256, KVN = 576, KCT = 2112;
constexpr int PITCH = 40;                 // bf16 elems per smem row (32 + 8 pad) = 80B
constexpr int ARRB = 128 * PITCH * 2;     // one operand array per stage: 10240 B
constexpr int STGB = 4 * ARRB;            // Ah,Al,Bh,Bl: 40960 B
constexpr size_t DSMEM = 2 * STGB;        // 81920 B
}

__device__ float g_q[(size_t)M_ * 3072];
__device__ float g_kva[(size_t)M_ * 576];
__device__ float g_kpe[(size_t)M_ * 64];
__device__ float g_kv2[(size_t)M_ * 4096];
__device__ float g_probs[(size_t)64 * S_ * S_];
__device__ float g_avg[(size_t)64 * S_ * 129];
__device__ __nv_bfloat16 g_xh[(size_t)M_ * 2048], g_xl[(size_t)M_ * 2048];
__device__ __nv_bfloat16 g_wqh[(size_t)3072 * 2048], g_wql[(size_t)3072 * 2048];
__device__ __nv_bfloat16 g_wkvah[(size_t)640 * 2048], g_wkval[(size_t)640 * 2048];
__device__ __nv_bfloat16 g_kvnh[(size_t)M_ * KVN], g_kvnl[(size_t)M_ * KVN];
__device__ __nv_bfloat16 g_wkvbh[(size_t)4096 * KVN], g_wkvbl[(size_t)4096 * KVN];
__device__ __nv_bfloat16 g_qah[(size_t)64 * S_ * KQA], g_qal[(size_t)64 * S_ * KQA];
__device__ __nv_bfloat16 g_kah[(size_t)64 * S_ * KQA], g_kal[(size_t)64 * S_ * KQA];
__device__ __nv_bfloat16 g_vth[(size_t)64 * 256 * S_], g_vtl[(size_t)64 * 256 * S_];
__device__ __nv_bfloat16 g_ph[(size_t)64 * S_ * S_], g_pl[(size_t)64 * S_ * S_];
__device__ __nv_bfloat16 g_ch[(size_t)M_ * KCT], g_cl[(size_t)M_ * KCT];
__device__ __nv_bfloat16 g_woh[(size_t)2048 * KCT], g_wol[(size_t)2048 * KCT];

__device__ __forceinline__ uint32_t cvta_smem(const void* p) {
    uint32_t a;
    asm("{ .reg .u64 t; cvta.to.shared.u64 t, %1; cvt.u32.u64 %0, t; }" : "=r"(a) : "l"(p));
    return a;
}
#define CPASYNC16(s, g) asm volatile("cp.async.cg.shared.global [%0], [%1], 16;" :: "r"(s), "l"(g) : "memory")
#define CPCOMMIT()      asm volatile("cp.async.commit_group;" ::: "memory")
#define CPWAIT(n)       asm volatile("cp.async.wait_group %0;" :: "n"(n) : "memory")

__device__ __forceinline__ void ldsm_x4(uint32_t* r, uint32_t a) {
    asm volatile("ldmatrix.sync.aligned.m8n8.x4.shared.b16 {%0,%1,%2,%3}, [%4];"
                 : "=r"(r[0]), "=r"(r[1]), "=r"(r[2]), "=r"(r[3]) : "r"(a));
}
__device__ __forceinline__ void ldsm_x2(uint32_t* r, uint32_t a) {
    asm volatile("ldmatrix.sync.aligned.m8n8.x2.shared.b16 {%0,%1}, [%2];"
                 : "=r"(r[0]), "=r"(r[1]) : "r"(a));
}
__device__ __forceinline__ void mma16816(float* d, const uint32_t* a, const uint32_t* b) {
    asm volatile("mma.sync.aligned.m16n8k16.row.col.f32.bf16.bf16.f32 "
                 "{%0,%1,%2,%3}, {%4,%5,%6,%7}, {%8,%9}, {%0,%1,%2,%3};"
                 : "+f"(d[0]), "+f"(d[1]), "+f"(d[2]), "+f"(d[3])
                 : "r"(a[0]), "r"(a[1]), "r"(a[2]), "r"(a[3]), "r"(b[0]), "r"(b[1]));
}

// ============ bf16-split GEMM via mma.sync ============
// C[m,n] = sum_k A[m,k]*B[n,k] (+bias[n]); CMODE: 0 dense, 1 causal tile-skip, 2 causal K-cap.
template <int CMODE>
__global__ void __launch_bounds__(256, 1)
gemm_mma(const __nv_bfloat16* __restrict__ Ah, const __nv_bfloat16* __restrict__ Al,
         long long sA, int lda,
         const __nv_bfloat16* __restrict__ Bh, const __nv_bfloat16* __restrict__ Bl,
         long long sB, int ldb,
         float* __restrict__ C, long long sC, int ldc,
         const float* __restrict__ bias, int Nreal, int K)
{
    if (CMODE == 1 && blockIdx.x > blockIdx.y) return;
    const int bm = blockIdx.y * 128, bn = blockIdx.x * 128;
    const int Keff = (CMODE == 2) ? min(K, bm + 128) : K;
    const int nch = Keff >> 5;
    const long long z = blockIdx.z;
    Ah += z * sA; Al += z * sA; Bh += z * sB; Bl += z * sB; C += z * sC;

    extern __shared__ __align__(16) char smem[];
    const uint32_t sbase = cvta_smem(smem);
    const int tid = threadIdx.x, wid = tid >> 5, lane = tid & 31;
    const int wm = (wid >> 2) * 64, wn = (wid & 3) * 32;

    float acc[4][4][4] = {};
    const __nv_bfloat16* srcs[4] = {Ah, Al, Bh, Bl};

    // ---- stage loader: 4 arrays x 128 rows x 64B into padded smem ----
    auto load_stage = [&](int s, int c) {
        const long long k0 = (long long)c * 32;
#pragma unroll
        for (int arr = 0; arr < 4; ++arr) {
            const __nv_bfloat16* src = srcs[arr];
            const int ld = (arr < 2) ? lda : ldb;
            const int ro = (arr < 2) ? bm : bn;
            const uint32_t base = sbase + (uint32_t)s * STGB + (uint32_t)arr * ARRB;
#pragma unroll
            for (int j = 0; j < 2; ++j) {
                const int cid = tid + j * 256;       // 0..511
                const int row = cid >> 2, ch = cid & 3;
                const __nv_bfloat16* g = src + (long long)(ro + row) * ld + k0 + ch * 8;
                CPASYNC16(base + (uint32_t)(row * 80 + ch * 16), g);
            }
        }
        CPCOMMIT();
    };

    load_stage(0, 0);
    for (int c = 0; c < nch; ++c) {
        if (c + 1 < nch) { load_stage((c + 1) & 1, c + 1); CPWAIT(1); }
        else             { CPWAIT(0); }
        __syncthreads();

        const uint32_t st = sbase + (uint32_t)(c & 1) * STGB;
#pragma unroll
        for (int ks = 0; ks < 2; ++ks) {
            uint32_t ah[4][4], al[4][4], bh[4][2], bl[4][2];
            const int arow = wm + (lane & 15);
            const int acol = ks * 16 + (lane >> 4) * 8;
#pragma unroll
            for (int mf = 0; mf < 4; ++mf) {
                const uint32_t off = (uint32_t)((arow + mf * 16) * 80 + acol * 2);
                ldsm_x4(ah[mf], st + off);
                ldsm_x4(al[mf], st + ARRB + off);
            }
            const int brow = wn + (lane & 7);
            const int bcol = ks * 16 + ((lane >> 3) & 1) * 8;
#pragma unroll
            for (int nf = 0; nf < 4; ++nf) {
                const uint32_t off = (uint32_t)((brow + nf * 8) * 80 + bcol * 2);
                ldsm_x2(bh[nf], st + 2 * ARRB + off);
                ldsm_x2(bl[nf], st + 3 * ARRB + off);
            }
#pragma unroll
            for (int mf = 0; mf < 4; ++mf)
#pragma unroll
                for (int nf = 0; nf < 4; ++nf) {
                    mma16816(acc[mf][nf], ah[mf], bh[nf]);
                    mma16816(acc[mf][nf], ah[mf], bl[nf]);
                    mma16816(acc[mf][nf], al[mf], bh[nf]);
                }
        }
        __syncthreads();
    }

    // ---- epilogue ----
#pragma unroll
    for (int mf = 0; mf < 4; ++mf) {
        const long long r0 = bm + wm + mf * 16 + (lane >> 2);
#pragma unroll
        for (int nf = 0; nf < 4; ++nf) {
            const int col = bn + wn + nf * 8 + (lane & 3) * 2;
            const float b0 = bias ? bias[min(col, Nreal - 1)] : 0.f;
            const float b1 = bias ? bias[min(col + 1, Nreal - 1)] : 0.f;
            if (col < Nreal) {
                C[r0 * ldc + col] = acc[mf][nf][0] + b0;
                C[(r0 + 8) * ldc + col] = acc[mf][nf][2] + b0;
            }
            if (col + 1 < Nreal) {
                C[r0 * ldc + col + 1] = acc[mf][nf][1] + b1;
                C[(r0 + 8) * ldc + col + 1] = acc[mf][nf][3] + b1;
            }
        }
    }
}

// ---------- elementwise ----------
__device__ __forceinline__ float warp_sum(float v) {
#pragma unroll
    for (int o = 16; o; o >>= 1) v += __shfl_xor_sync(0xffffffffu, v, o);
    return v;
}
__device__ __forceinline__ float block_sum_256(float v, float* sh) {
    int tid = threadIdx.x;
#pragma unroll
    for (int o = 16; o; o >>= 1) v += __shfl_xor_sync(0xffffffffu, v, o);
    __syncthreads();
    if ((tid & 31) == 0) sh[tid >> 5] = v;
    __syncthreads();
    if (tid < 32) {
        float t = (tid < 8) ? sh[tid] : 0.f;
#pragma unroll
        for (int o = 4; o; o >>= 1) t += __shfl_xor_sync(0xffffffffu, t, o);
        if (tid == 0) sh[0] = t;
    }
    __syncthreads();
    return sh[0];
}
__device__ __forceinline__ void bsplit(float v, __nv_bfloat16* hi, __nv_bfloat16* lo, long long i) {
    __nv_bfloat16 h = __float2bfloat16(v);
    hi[i] = h;
    lo[i] = __float2bfloat16(v - __bfloat162float(h));
}

__global__ void __launch_bounds__(256)
convert_split(const float* __restrict__ src, int lds,
              __nv_bfloat16* __restrict__ hi, __nv_bfloat16* __restrict__ lo,
              int ldd, int cols)
{
    const int r = blockIdx.y, c = blockIdx.x * 256 + threadIdx.x;
    if (c < cols) bsplit(src[(long long)r * lds + c], hi, lo, (long long)r * ldd + c);
}

__global__ void __launch_bounds__(256)
rmsnorm_kpe_kernel(const float* __restrict__ kva, const float* __restrict__ w,
                   const float* __restrict__ fc, const float* __restrict__ fs,
                   __nv_bfloat16* __restrict__ kvnh, __nv_bfloat16* __restrict__ kvnl,
                   float* __restrict__ kpe)
{
    const int tok = blockIdx.x, s = tok & (S_ - 1), tid = threadIdx.x;
    const float* in = kva + (size_t)tok * 576;
    __shared__ float sp[512];
    __shared__ float sh[8];
    float local = 0.f;
    for (int i = tid; i < 512; i += 256) { float v = in[i]; local += v * v; }
    float r = rsqrtf(block_sum_256(local, sh) * (1.0f / 512.f) + 1e-6f);
    float l2 = 0.f;
    for (int i = tid; i < 512; i += 256) {
        float v = in[i] * r * w[i];
        sp[i] = v;
        l2 += v * v;
    }
    float tot2 = block_sum_256(l2, sh);
    const long long ob = (long long)tok * KVN;
    if (tid == 0) bsplit(sqrtf(tot2 + 1.f), kvnh, kvnl, ob);
    for (int i = tid; i < 512; i += 256) bsplit(sp[i], kvnh, kvnl, ob + 1 + i);
    if (tid < 32) {
        float x1 = in[512 + 2 * tid], x2 = in[512 + 2 * tid + 1];
        float c = fc[s * 32 + tid], sn = fs[s * 32 + tid];
        kpe[(size_t)tok * 64 + 2 * tid]     = x1 * c - x2 * sn;
        kpe[(size_t)tok * 64 + 2 * tid + 1] = x1 * sn + x2 * c;
    }
}

__global__ void __launch_bounds__(256)
post_q_kernel(const float* __restrict__ q, const float* __restrict__ fc,
              const float* __restrict__ fs,
              __nv_bfloat16* __restrict__ qh, __nv_bfloat16* __restrict__ ql)
{
    const int gw = (blockIdx.x * blockDim.x + threadIdx.x) >> 5, lane = threadIdx.x & 31;
    if (gw >= M_ * H_) return;
    const int h = gw % H_, tok = gw / H_, b = tok / S_, s = tok & (S_ - 1);
    const float* qr = q + ((size_t)tok * H_ + h) * 192;
    const float c = fc[s * 32 + lane], sn = fs[s * 32 + lane];
    const float x1 = qr[128 + 2 * lane], x2 = qr[128 + 2 * lane + 1];
    const float r0 = x1 * c - x2 * sn, r1 = x1 * sn + x2 * c;
    float ss = r0 * r0 + r1 * r1;
    for (int d = lane; d < 128; d += 32) { float v = qr[d]; ss += v * v; }
    ss = warp_sum(ss);
    const long long ob = (((long long)b * H_ + h) * S_ + s) * KQA;
    if (lane == 0) bsplit(-sqrtf(ss + 1.f), qh, ql, ob);
    for (int d = lane; d < 128; d += 32) bsplit(qr[d], qh, ql, ob + 1 + d);
    bsplit(r0, qh, ql, ob + 129 + 2 * lane);
    bsplit(r1, qh, ql, ob + 129 + 2 * lane + 1);
}

__global__ void __launch_bounds__(256)
post_kv_kernel(const float* __restrict__ kv2, const float* __restrict__ kpe,
               __nv_bfloat16* __restrict__ kh, __nv_bfloat16* __restrict__ kl,
               __nv_bfloat16* __restrict__ vh, __nv_bfloat16* __restrict__ vl)
{
    const int gw = (blockIdx.x * blockDim.x + threadIdx.x) >> 5, lane = threadIdx.x & 31;
    if (gw >= M_ * H_) return;
    const int h = gw % H_, tok = gw / H_, b = tok / S_, s = tok & (S_ - 1);
    const float* row = kv2 + ((size_t)tok * H_ + h) * 256;
    const float* pe = kpe + (size_t)tok * 64;
    float ss = 0.f;
    for (int d = lane; d < 128; d += 32) { float v = row[d]; ss += v * v; }
    for (int d = lane; d < 64; d += 32) { float v = pe[d]; ss += v * v; }
    ss = warp_sum(ss);
    const long long kb = (((long long)b * H_ + h) * S_ + s) * KQA;
    if (lane == 0) bsplit(sqrtf(ss + 1.f), kh, kl, kb);
    for (int d = lane; d < 128; d += 32) bsplit(row[d], kh, kl, kb + 1 + d);
    for (int d = lane; d < 64; d += 32) bsplit(pe[d], kh, kl, kb + 129 + d);
    float sv = 0.f;
    for (int d = lane; d < 128; d += 32) { float v = row[128 + d]; sv += v * v; }
    sv = warp_sum(sv);
    const long long vb = ((long long)b * H_ + h) * 256 * S_;
    if (lane == 0) bsplit(sqrtf(sv + 1.f), vh, vl, vb + s);
    for (int d = lane; d < 128; d += 32)
        bsplit(row[128 + d], vh, vl, vb + (long long)(1 + d) * S_ + s);
}

__global__ void __launch_bounds__(256)
softmax_kernel(float* __restrict__ P, __nv_bfloat16* __restrict__ ph,
               __nv_bfloat16* __restrict__ pl)
{
    const int row = blockIdx.x, s = row & (S_ - 1), tid = threadIdx.x;
    float* p = P + (size_t)row * S_;
    const long long ob = (long long)row * S_;
    __shared__ float sh[8];
    float mx = -1e30f;
    for (int t = tid; t <= s; t += 256) mx = fmaxf(mx, p[t]);
#pragma unroll
    for (int o = 16; o; o >>= 1) mx = fmaxf(mx, __shfl_xor_sync(0xffffffffu, mx, o));
    if ((tid & 31) == 0) sh[tid >> 5] = mx;
    __syncthreads();
    if (tid < 32) {
        float v = (tid < 8) ? sh[tid] : -1e30f;
#pragma unroll
        for (int o = 4; o; o >>= 1) v = fmaxf(v, __shfl_xor_sync(0xffffffffu, v, o));
        if (tid == 0) sh[0] = v;
    }
    __syncthreads();
    mx = sh[0];
    __syncthreads();
    float sum = 0.f;
    for (int t = tid; t <= s; t += 256) {
        float e = __expf(TWO_SCALE * (p[t] - mx));
        p[t] = e;
        sum += e;
    }
    const float inv = 1.f / block_sum_256(sum, sh);
    for (int t = tid; t <= s; t += 256) bsplit(p[t] * inv, ph, pl, ob + t);
    const __nv_bfloat16 z = __float2bfloat16(0.f);
    for (int t = s + 1 + tid; t < S_; t += 256) { ph[ob + t] = z; pl[ob + t] = z; }
}

__global__ void __launch_bounds__(256)
cent_kernel(const float* __restrict__ avg,
            __nv_bfloat16* __restrict__ ch, __nv_bfloat16* __restrict__ cl)
{
    const int gw = (blockIdx.x * blockDim.x + threadIdx.x) >> 5, lane = threadIdx.x & 31;
    if (gw >= M_ * H_) return;
    const int h = gw % H_, tok = gw / H_, b = tok / S_, s = tok & (S_ - 1);
    const float* a = avg + (((long long)b * H_ + h) * S_ + s) * 129;
    const float a0 = a[0];
    float ss = 0.f;
    for (int d = lane; d < 128; d += 32) { float v = a[1 + d]; ss += v * v; }
    ss = warp_sum(ss);
    const float denom = rsqrtf(fmaxf(fabsf(a0 * a0 - ss), 1e-8f));
    const long long ob = (long long)tok * KCT + h * 129;
    if (lane == 0) bsplit(a0 * denom, ch, cl, ob);
    for (int d = lane; d < 128; d += 32) bsplit(a[1 + d] * denom, ch, cl, ob + 1 + d);
}

__global__ void __launch_bounds__(256)
final_t_kernel(float* __restrict__ out)
{
    const int row = blockIdx.x, tid = threadIdx.x;
    float* p = out + (size_t)row * 2048;
    __shared__ float sh[8];
    float local = 0.f;
    for (int i = 1 + tid; i < 2048; i += 256) { float v = p[i]; local += v * v; }
    float tot = block_sum_256(local, sh);
    if (tid == 0) p[0] = sqrtf(tot + 1.f);
}

extern "C" void kernel_launch(void* const* d_in, const int* in_sizes, int n_in,
                              void* d_out, int out_size)
{
    (void)in_sizes; (void)n_in; (void)out_size;
    const float* x      = (const float*)d_in[0];
    const float* fc     = (const float*)d_in[1];
    const float* fs     = (const float*)d_in[2];
    const float* wq_w   = (const float*)d_in[4];
    const float* wq_b   = (const float*)d_in[5];
    const float* wkva_w = (const float*)d_in[6];
    const float* wkva_b = (const float*)d_in[7];
    const float* kvnw   = (const float*)d_in[8];
    const float* wkvb_w = (const float*)d_in[9];
    const float* wkvb_b = (const float*)d_in[10];
    const float* wo_w   = (const float*)d_in[11];
    const float* wo_b   = (const float*)d_in[12];
    float* out = (float*)d_out;

    float *q, *kva, *kpe, *kv2, *probs, *avg;
    cudaGetSymbolAddress((void**)&q, g_q);
    cudaGetSymbolAddress((void**)&kva, g_kva);
    cudaGetSymbolAddress((void**)&kpe, g_kpe);
    cudaGetSymbolAddress((void**)&kv2, g_kv2);
    cudaGetSymbolAddress((void**)&probs, g_probs);
    cudaGetSymbolAddress((void**)&avg, g_avg);
    __nv_bfloat16 *xh, *xl, *wqh, *wql, *wkvah, *wkval, *kvnh, *kvnl, *wkvbh, *wkvbl;
    __nv_bfloat16 *qah, *qal, *kah, *kal, *vth, *vtl, *ph, *pl, *ch, *cl, *woh, *wol;
    cudaGetSymbolAddress((void**)&xh, g_xh);       cudaGetSymbolAddress((void**)&xl, g_xl);
    cudaGetSymbolAddress((void**)&wqh, g_wqh);     cudaGetSymbolAddress((void**)&wql, g_wql);
    cudaGetSymbolAddress((void**)&wkvah, g_wkvah); cudaGetSymbolAddress((void**)&wkval, g_wkval);
    cudaGetSymbolAddress((void**)&kvnh, g_kvnh);   cudaGetSymbolAddress((void**)&kvnl, g_kvnl);
    cudaGetSymbolAddress((void**)&wkvbh, g_wkvbh); cudaGetSymbolAddress((void**)&wkvbl, g_wkvbl);
    cudaGetSymbolAddress((void**)&qah, g_qah);     cudaGetSymbolAddress((void**)&qal, g_qal);
    cudaGetSymbolAddress((void**)&kah, g_kah);     cudaGetSymbolAddress((void**)&kal, g_kal);
    cudaGetSymbolAddress((void**)&vth, g_vth);     cudaGetSymbolAddress((void**)&vtl, g_vtl);
    cudaGetSymbolAddress((void**)&ph, g_ph);       cudaGetSymbolAddress((void**)&pl, g_pl);
    cudaGetSymbolAddress((void**)&ch, g_ch);       cudaGetSymbolAddress((void**)&cl, g_cl);
    cudaGetSymbolAddress((void**)&woh, g_woh);     cudaGetSymbolAddress((void**)&wol, g_wol);

    cudaFuncSetAttribute(gemm_mma<0>, cudaFuncAttributeMaxDynamicSharedMemorySize, (int)DSMEM);
    cudaFuncSetAttribute(gemm_mma<1>, cudaFuncAttributeMaxDynamicSharedMemorySize, (int)DSMEM);
    cudaFuncSetAttribute(gemm_mma<2>, cudaFuncAttributeMaxDynamicSharedMemorySize, (int)DSMEM);

    const dim3 blk(256);
    convert_split<<<dim3(8, M_), blk>>>(x, 2048, xh, xl, 2048, 2048);
    convert_split<<<dim3(8, 3072), blk>>>(wq_w, 2048, wqh, wql, 2048, 2048);
    convert_split<<<dim3(8, 576), blk>>>(wkva_w, 2048, wkvah, wkval, 2048, 2048);
    convert_split<<<dim3(3, 4096), blk>>>(wkvb_w, 513, wkvbh, wkvbl, KVN, 513);
    convert_split<<<dim3(9, 2047), blk>>>(wo_w, 2064, woh, wol, KCT, 2064);

    // Q proj: (4096x2048) @ (3072x2048)^T
    gemm_mma<0><<<dim3(24, 32, 1), blk, DSMEM>>>(xh, xl, 0, 2048, wqh, wql, 0, 2048,
                                                 q, 0, 3072, wq_b, 3072, 2048);
    // KV-A proj: (4096x2048) @ (576x2048)^T (weights padded to 640 rows)
    gemm_mma<0><<<dim3(5, 32, 1), blk, DSMEM>>>(xh, xl, 0, 2048, wkvah, wkval, 0, 2048,
                                                kva, 0, 576, wkva_b, 576, 2048);
    rmsnorm_kpe_kernel<<<M_, blk>>>(kva, kvnw, fc, fs, kvnh, kvnl, kpe);
    // KV-B proj: (4096x576) @ (4096x576)^T
    gemm_mma<0><<<dim3(32, 32, 1), blk, DSMEM>>>(kvnh, kvnl, 0, KVN, wkvbh, wkvbl, 0, KVN,
                                                 kv2, 0, 4096, wkvb_b, 4096, KVN);
    post_q_kernel<<<(M_ * H_) / 8, blk>>>(q, fc, fs, qah, qal);
    post_kv_kernel<<<(M_ * H_) / 8, blk>>>(kv2, kpe, kah, kal, vth, vtl);
    // scores (causal tile-skip): per (b,h) q~(1024x256) @ k~(1024x256)^T
    gemm_mma<1><<<dim3(8, 8, 64), blk, DSMEM>>>(qah, qal, (long long)S_ * KQA, KQA,
                                                kah, kal, (long long)S_ * KQA, KQA,
                                                probs, (long long)S_ * S_, S_,
                                                nullptr, S_, KQA);
    softmax_kernel<<<64 * S_, blk>>>(probs, ph, pl);
    // PV (causal K-cap): per (b,h) P(1024x1024) @ vT(256x1024)^T -> avg(1024x129)
    gemm_mma<2><<<dim3(2, 8, 64), blk, DSMEM>>>(ph, pl, (long long)S_ * S_, S_,
                                                vth, vtl, (long long)256 * S_, S_,
                                                avg, (long long)S_ * 129, 129,
                                                nullptr, 129, S_);
    cent_kernel<<<(M_ * H_) / 8, blk>>>(avg, ch, cl);
    // out proj: (4096x2112) @ (2047x2112)^T -> out[:,1:]
    gemm_mma<0><<<dim3(16, 32, 1), blk, DSMEM>>>(ch, cl, 0, KCT, woh, wol, 0, KCT,
                                                 out + 1, 0, 2048, wo_b, 2047, KCT);
    final_t_kernel<<<M_, blk>>>(out);
}

// round 5
// speedup vs baseline: 2.8149x; 1.1365x over previous
#include <cuda_runtime.h>
#include <cuda_bf16.h>
#include <math.h>
#include <stdint.h>

namespace {
constexpr int B_ = 4, S_ = 1024, H_ = 16;
constexpr int M_ = B_ * S_;
constexpr float TWO_SCALE = 0.14396396f;            // 2/sqrt(193)
constexpr float SC2 = 0.14396396f * 1.44269504f;    // *log2(e)
constexpr int KQA = 256, KVN = 576, KCT = 2112, VROWS = 136;
constexpr size_t DSMEM = 2 * 4 * 128 * 80;          // gemm: 2 stages x 4 arrays x 128x80B = 81920
constexpr size_t DSMEM_F = 81920 + 2 * 36992;       // + V hi/lo tiles (136 x 272B) = 155904
}

__device__ float g_q[(size_t)M_ * 3072];
__device__ float g_kva[(size_t)M_ * 576];
__device__ float g_kpe[(size_t)M_ * 64];
__device__ float g_kv2[(size_t)M_ * 4096];
__device__ __nv_bfloat16 g_xh[(size_t)M_ * 2048], g_xl[(size_t)M_ * 2048];
__device__ __nv_bfloat16 g_wqh[(size_t)3072 * 2048], g_wql[(size_t)3072 * 2048];
__device__ __nv_bfloat16 g_wkvah[(size_t)640 * 2048], g_wkval[(size_t)640 * 2048];
__device__ __nv_bfloat16 g_kvnh[(size_t)M_ * KVN], g_kvnl[(size_t)M_ * KVN];
__device__ __nv_bfloat16 g_wkvbh[(size_t)4096 * KVN], g_wkvbl[(size_t)4096 * KVN];
__device__ __nv_bfloat16 g_qah[(size_t)64 * S_ * KQA], g_qal[(size_t)64 * S_ * KQA];
__device__ __nv_bfloat16 g_kah[(size_t)64 * S_ * KQA], g_kal[(size_t)64 * S_ * KQA];
__device__ __nv_bfloat16 g_vth[(size_t)64 * VROWS * S_], g_vtl[(size_t)64 * VROWS * S_];
__device__ __nv_bfloat16 g_ch[(size_t)M_ * KCT], g_cl[(size_t)M_ * KCT];
__device__ __nv_bfloat16 g_woh[(size_t)2048 * KCT], g_wol[(size_t)2048 * KCT];

__device__ __forceinline__ uint32_t cvta_smem(const void* p) {
    uint32_t a;
    asm("{ .reg .u64 t; cvta.to.shared.u64 t, %1; cvt.u32.u64 %0, t; }" : "=r"(a) : "l"(p));
    return a;
}
#define CPASYNC16(s, g) asm volatile("cp.async.cg.shared.global [%0], [%1], 16;" :: "r"(s), "l"(g) : "memory")
#define CPCOMMIT()      asm volatile("cp.async.commit_group;" ::: "memory")
#define CPWAIT(n)       asm volatile("cp.async.wait_group %0;" :: "n"(n) : "memory")

__device__ __forceinline__ void ldsm_x4(uint32_t* r, uint32_t a) {
    asm volatile("ldmatrix.sync.aligned.m8n8.x4.shared.b16 {%0,%1,%2,%3}, [%4];"
                 : "=r"(r[0]), "=r"(r[1]), "=r"(r[2]), "=r"(r[3]) : "r"(a));
}
__device__ __forceinline__ void ldsm_x2(uint32_t* r, uint32_t a) {
    asm volatile("ldmatrix.sync.aligned.m8n8.x2.shared.b16 {%0,%1}, [%2];"
                 : "=r"(r[0]), "=r"(r[1]) : "r"(a));
}
__device__ __forceinline__ void mma16816(float* d, const uint32_t* a, const uint32_t* b) {
    asm volatile("mma.sync.aligned.m16n8k16.row.col.f32.bf16.bf16.f32 "
                 "{%0,%1,%2,%3}, {%4,%5,%6,%7}, {%8,%9}, {%0,%1,%2,%3};"
                 : "+f"(d[0]), "+f"(d[1]), "+f"(d[2]), "+f"(d[3])
                 : "r"(a[0]), "r"(a[1]), "r"(a[2]), "r"(a[3]), "r"(b[0]), "r"(b[1]));
}
__device__ __forceinline__ uint32_t pack_split(float x, float y, uint32_t& lo) {
    __nv_bfloat162 h = __floats2bfloat162_rn(x, y);
    __nv_bfloat162 l = __floats2bfloat162_rn(x - __bfloat162float(h.x),
                                             y - __bfloat162float(h.y));
    lo = *reinterpret_cast<uint32_t*>(&l);
    return *reinterpret_cast<uint32_t*>(&h);
}
__device__ __forceinline__ float warp_sum(float v) {
#pragma unroll
    for (int o = 16; o; o >>= 1) v += __shfl_xor_sync(0xffffffffu, v, o);
    return v;
}
__device__ __forceinline__ float block_sum_256(float v, float* sh) {
    int tid = threadIdx.x;
#pragma unroll
    for (int o = 16; o; o >>= 1) v += __shfl_xor_sync(0xffffffffu, v, o);
    __syncthreads();
    if ((tid & 31) == 0) sh[tid >> 5] = v;
    __syncthreads();
    if (tid < 32) {
        float t = (tid < 8) ? sh[tid] : 0.f;
#pragma unroll
        for (int o = 4; o; o >>= 1) t += __shfl_xor_sync(0xffffffffu, t, o);
        if (tid == 0) sh[0] = t;
    }
    __syncthreads();
    return sh[0];
}
__device__ __forceinline__ void bsplit(float v, __nv_bfloat16* hi, __nv_bfloat16* lo, long long i) {
    __nv_bfloat16 h = __float2bfloat16(v);
    hi[i] = h;
    lo[i] = __float2bfloat16(v - __bfloat162float(h));
}

// ============ dense bf16-split GEMM (projections) ============
__global__ void __launch_bounds__(256, 1)
gemm_mma(const __nv_bfloat16* __restrict__ Ah, const __nv_bfloat16* __restrict__ Al, int lda,
         const __nv_bfloat16* __restrict__ Bh, const __nv_bfloat16* __restrict__ Bl, int ldb,
         float* __restrict__ C, int ldc,
         const float* __restrict__ bias, int Nreal, int K)
{
    const int bm = blockIdx.y * 128, bn = blockIdx.x * 128;
    const int nch = K >> 5;
    extern __shared__ __align__(16) char smem[];
    const uint32_t sbase = cvta_smem(smem);
    const int tid = threadIdx.x, wid = tid >> 5, lane = tid & 31;
    const int wm = (wid >> 2) * 64, wn = (wid & 3) * 32;

    float acc[4][4][4] = {};
    const __nv_bfloat16* srcs[4] = {Ah, Al, Bh, Bl};

    auto load_stage = [&](int s, int c) {
        const long long k0 = (long long)c * 32;
#pragma unroll
        for (int arr = 0; arr < 4; ++arr) {
            const __nv_bfloat16* src = srcs[arr];
            const int ld = (arr < 2) ? lda : ldb;
            const int ro = (arr < 2) ? bm : bn;
            const uint32_t base = sbase + (uint32_t)s * 40960u + (uint32_t)arr * 10240u;
#pragma unroll
            for (int j = 0; j < 2; ++j) {
                const int cid = tid + j * 256;
                const int row = cid >> 2, ch = cid & 3;
                CPASYNC16(base + (uint32_t)(row * 80 + ch * 16),
                          src + (long long)(ro + row) * ld + k0 + ch * 8);
            }
        }
        CPCOMMIT();
    };

    load_stage(0, 0);
    for (int c = 0; c < nch; ++c) {
        if (c + 1 < nch) { load_stage((c + 1) & 1, c + 1); CPWAIT(1); }
        else             { CPWAIT(0); }
        __syncthreads();
        const uint32_t st = sbase + (uint32_t)(c & 1) * 40960u;
#pragma unroll
        for (int ks = 0; ks < 2; ++ks) {
            uint32_t ah[4][4], al[4][4], bh[4][2], bl[4][2];
            const int arow = wm + (lane & 15);
            const int acol = ks * 16 + (lane >> 4) * 8;
#pragma unroll
            for (int mf = 0; mf < 4; ++mf) {
                const uint32_t off = (uint32_t)((arow + mf * 16) * 80 + acol * 2);
                ldsm_x4(ah[mf], st + off);
                ldsm_x4(al[mf], st + 10240u + off);
            }
            const int brow = wn + (lane & 7);
            const int bcol = ks * 16 + ((lane >> 3) & 1) * 8;
#pragma unroll
            for (int nf = 0; nf < 4; ++nf) {
                const uint32_t off = (uint32_t)((brow + nf * 8) * 80 + bcol * 2);
                ldsm_x2(bh[nf], st + 20480u + off);
                ldsm_x2(bl[nf], st + 30720u + off);
            }
#pragma unroll
            for (int mf = 0; mf < 4; ++mf)
#pragma unroll
                for (int nf = 0; nf < 4; ++nf) {
                    mma16816(acc[mf][nf], ah[mf], bh[nf]);
                    mma16816(acc[mf][nf], ah[mf], bl[nf]);
                    mma16816(acc[mf][nf], al[mf], bh[nf]);
                }
        }
        __syncthreads();
    }
#pragma unroll
    for (int mf = 0; mf < 4; ++mf) {
        const long long r0 = bm + wm + mf * 16 + (lane >> 2);
#pragma unroll
        for (int nf = 0; nf < 4; ++nf) {
            const int col = bn + wn + nf * 8 + (lane & 3) * 2;
            const float b0 = bias ? bias[min(col, Nreal - 1)] : 0.f;
            const float b1 = bias ? bias[min(col + 1, Nreal - 1)] : 0.f;
            if (col < Nreal) {
                C[r0 * ldc + col] = acc[mf][nf][0] + b0;
                C[(r0 + 8) * ldc + col] = acc[mf][nf][2] + b0;
            }
            if (col + 1 < Nreal) {
                C[r0 * ldc + col + 1] = acc[mf][nf][1] + b1;
                C[(r0 + 8) * ldc + col + 1] = acc[mf][nf][3] + b1;
            }
        }
    }
}

// ============ fused flash-attention + Lorentz centroid ============
// grid (8, 64): x -> q-block (descending), y -> (b*H + h)
__global__ void __launch_bounds__(256, 1)
fused_attn(const __nv_bfloat16* __restrict__ qh, const __nv_bfloat16* __restrict__ ql,
           const __nv_bfloat16* __restrict__ kh, const __nv_bfloat16* __restrict__ kl,
           const __nv_bfloat16* __restrict__ vh, const __nv_bfloat16* __restrict__ vl,
           __nv_bfloat16* __restrict__ ch, __nv_bfloat16* __restrict__ cl)
{
    const int iq = 7 - (int)blockIdx.x;
    const int bh = (int)blockIdx.y;
    const long long qkbase = (long long)bh * S_ * KQA;
    const long long vgbase = (long long)bh * VROWS * S_;
    extern __shared__ __align__(16) char smem[];
    const uint32_t sbase = cvta_smem(smem);
    const uint32_t vsH = sbase + 81920u, vsL = vsH + 36992u;
    const int tid = threadIdx.x, w = tid >> 5, lane = tid & 31;

    float O[17][4] = {};
    float m0 = -1e30f, m1 = -1e30f, l0 = 0.f, l1 = 0.f;

    for (int j = 0; j <= iq; ++j) {
        // issue chunk 0 (Q/K, k=0..31), then V tile as its own group
        {
            const __nv_bfloat16* srcs[4] = {qh + qkbase + (long long)iq * 128 * KQA,
                                            ql + qkbase + (long long)iq * 128 * KQA,
                                            kh + qkbase + (long long)j * 128 * KQA,
                                            kl + qkbase + (long long)j * 128 * KQA};
#pragma unroll
            for (int arr = 0; arr < 4; ++arr)
#pragma unroll
                for (int t2 = 0; t2 < 2; ++t2) {
                    const int cid = tid + t2 * 256;
                    const int row = cid >> 2, seg = cid & 3;
                    CPASYNC16(sbase + arr * 10240u + (uint32_t)(row * 80 + seg * 16),
                              srcs[arr] + (long long)row * KQA + seg * 8);
                }
            CPCOMMIT();
            for (int idx = tid; idx < 2176; idx += 256) {
                const int row = idx >> 4, seg = idx & 15;
                const long long g = vgbase + (long long)row * S_ + j * 128 + seg * 8;
                CPASYNC16(vsH + (uint32_t)(row * 272 + seg * 16), vh + g);
                CPASYNC16(vsL + (uint32_t)(row * 272 + seg * 16), vl + g);
            }
            CPCOMMIT();
        }
        float acc[16][4] = {};
        for (int c = 0; c < 7; ++c) {
            if (c < 6) {   // prefetch next chunk
                const int s = (c + 1) & 1;
                const long long k0 = (long long)(c + 1) * 32;
                const __nv_bfloat16* srcs[4] = {qh + qkbase + (long long)iq * 128 * KQA,
                                                ql + qkbase + (long long)iq * 128 * KQA,
                                                kh + qkbase + (long long)j * 128 * KQA,
                                                kl + qkbase + (long long)j * 128 * KQA};
#pragma unroll
                for (int arr = 0; arr < 4; ++arr)
#pragma unroll
                    for (int t2 = 0; t2 < 2; ++t2) {
                        const int cid = tid + t2 * 256;
                        const int row = cid >> 2, seg = cid & 3;
                        CPASYNC16(sbase + (uint32_t)s * 40960u + arr * 10240u +
                                      (uint32_t)(row * 80 + seg * 16),
                                  srcs[arr] + (long long)row * KQA + k0 + seg * 8);
                    }
                CPCOMMIT();
                if (c == 0) CPWAIT(2); else CPWAIT(1);   // allow V (+next chunk) pending
            } else {
                CPWAIT(0);                                // V resident before PV
            }
            __syncthreads();
            const uint32_t st = sbase + (uint32_t)(c & 1) * 40960u;
#pragma unroll
            for (int ks = 0; ks < 2; ++ks) {
                uint32_t ah[4], al[4];
                const uint32_t aoff =
                    (uint32_t)((w * 16 + (lane & 15)) * 80 + (ks * 16 + (lane >> 4) * 8) * 2);
                ldsm_x4(ah, st + aoff);
                ldsm_x4(al, st + 10240u + aoff);
#pragma unroll
                for (int nf = 0; nf < 16; ++nf) {
                    const uint32_t boff =
                        (uint32_t)((nf * 8 + (lane & 7)) * 80 +
                                   (ks * 16 + ((lane >> 3) & 1) * 8) * 2);
                    uint32_t bh2[2], bl2[2];
                    ldsm_x2(bh2, st + 20480u + boff);
                    ldsm_x2(bl2, st + 30720u + boff);
                    mma16816(acc[nf], ah, bh2);
                    mma16816(acc[nf], ah, bl2);
                    mma16816(acc[nf], al, bh2);
                }
            }
            __syncthreads();
        }
        if (j == iq) {   // diagonal tile mask
            const int rt0 = w * 16 + (lane >> 2), rt1 = rt0 + 8;
#pragma unroll
            for (int nf = 0; nf < 16; ++nf) {
                const int ct = nf * 8 + (lane & 3) * 2;
                if (ct > rt0)     acc[nf][0] = -1e30f;
                if (ct + 1 > rt0) acc[nf][1] = -1e30f;
                if (ct > rt1)     acc[nf][2] = -1e30f;
                if (ct + 1 > rt1) acc[nf][3] = -1e30f;
            }
        }
        // online softmax (quad shuffles only)
        float mx0 = -1e30f, mx1 = -1e30f;
#pragma unroll
        for (int nf = 0; nf < 16; ++nf) {
            mx0 = fmaxf(mx0, fmaxf(acc[nf][0], acc[nf][1]));
            mx1 = fmaxf(mx1, fmaxf(acc[nf][2], acc[nf][3]));
        }
        mx0 = fmaxf(mx0, __shfl_xor_sync(~0u, mx0, 1));
        mx0 = fmaxf(mx0, __shfl_xor_sync(~0u, mx0, 2));
        mx1 = fmaxf(mx1, __shfl_xor_sync(~0u, mx1, 1));
        mx1 = fmaxf(mx1, __shfl_xor_sync(~0u, mx1, 2));
        const float mn0 = fmaxf(m0, mx0), mn1 = fmaxf(m1, mx1);
        const float a0 = exp2f((m0 - mn0) * SC2), a1 = exp2f((m1 - mn1) * SC2);
        l0 *= a0; l1 *= a1;
#pragma unroll
        for (int nf = 0; nf < 17; ++nf) {
            O[nf][0] *= a0; O[nf][1] *= a0; O[nf][2] *= a1; O[nf][3] *= a1;
        }
        float s0 = 0.f, s1 = 0.f;
#pragma unroll
        for (int nf = 0; nf < 16; ++nf) {
            acc[nf][0] = exp2f((acc[nf][0] - mn0) * SC2);
            acc[nf][1] = exp2f((acc[nf][1] - mn0) * SC2);
            acc[nf][2] = exp2f((acc[nf][2] - mn1) * SC2);
            acc[nf][3] = exp2f((acc[nf][3] - mn1) * SC2);
            s0 += acc[nf][0] + acc[nf][1];
            s1 += acc[nf][2] + acc[nf][3];
        }
        s0 += __shfl_xor_sync(~0u, s0, 1); s0 += __shfl_xor_sync(~0u, s0, 2);
        s1 += __shfl_xor_sync(~0u, s1, 1); s1 += __shfl_xor_sync(~0u, s1, 2);
        l0 += s0; l1 += s1; m0 = mn0; m1 = mn1;
        // PV: P (C-frag) -> A-frag bf16 hi/lo in registers, 3-term
#pragma unroll
        for (int kf = 0; kf < 8; ++kf) {
            uint32_t Ph[4], Pl[4];
            Ph[0] = pack_split(acc[2 * kf][0], acc[2 * kf][1], Pl[0]);
            Ph[1] = pack_split(acc[2 * kf][2], acc[2 * kf][3], Pl[1]);
            Ph[2] = pack_split(acc[2 * kf + 1][0], acc[2 * kf + 1][1], Pl[2]);
            Ph[3] = pack_split(acc[2 * kf + 1][2], acc[2 * kf + 1][3], Pl[3]);
#pragma unroll
            for (int nf = 0; nf < 17; ++nf) {
                const uint32_t voff =
                    (uint32_t)((nf * 8 + (lane & 7)) * 272 +
                               (kf * 16 + ((lane >> 3) & 1) * 8) * 2);
                uint32_t vh2[2], vl2[2];
                ldsm_x2(vh2, vsH + voff);
                ldsm_x2(vl2, vsL + voff);
                mma16816(O[nf], Ph, vh2);
                mma16816(O[nf], Ph, vl2);
                mma16816(O[nf], Pl, vh2);
            }
        }
        __syncthreads();   // V/stage reuse next j
    }
    // epilogue: avg = O/l, Lorentz centroid normalize, write ch/cl
    const float i0 = 1.f / l0, i1 = 1.f / l1;
    float ss0 = 0.f, ss1 = 0.f;
#pragma unroll
    for (int nf = 0; nf < 17; ++nf) {
        O[nf][0] *= i0; O[nf][1] *= i0; O[nf][2] *= i1; O[nf][3] *= i1;
        ss0 += O[nf][0] * O[nf][0] + O[nf][1] * O[nf][1];
        ss1 += O[nf][2] * O[nf][2] + O[nf][3] * O[nf][3];
    }
    ss0 += __shfl_xor_sync(~0u, ss0, 1); ss0 += __shfl_xor_sync(~0u, ss0, 2);
    ss1 += __shfl_xor_sync(~0u, ss1, 1); ss1 += __shfl_xor_sync(~0u, ss1, 2);
    const float t0 = __shfl_sync(~0u, O[0][0], lane & ~3);
    const float t1 = __shfl_sync(~0u, O[0][2], lane & ~3);
    const float d0 = rsqrtf(fmaxf(fabsf(2.f * t0 * t0 - ss0), 1e-8f));
    const float d1 = rsqrtf(fmaxf(fabsf(2.f * t1 * t1 - ss1), 1e-8f));
    const int hh = bh & 15;
    const long long tok0 = (long long)(bh >> 4) * 1024 + iq * 128 + w * 16 + (lane >> 2);
    const long long o0 = tok0 * KCT + hh * 129, o1 = (tok0 + 8) * KCT + hh * 129;
#pragma unroll
    for (int nf = 0; nf < 17; ++nf) {
        const int cc = nf * 8 + (lane & 3) * 2;
        if (cc < 129) {
            bsplit(O[nf][0] * d0, ch, cl, o0 + cc);
            bsplit(O[nf][2] * d1, ch, cl, o1 + cc);
        }
        if (cc + 1 < 129) {
            bsplit(O[nf][1] * d0, ch, cl, o0 + cc + 1);
            bsplit(O[nf][3] * d1, ch, cl, o1 + cc + 1);
        }
    }
}

// ---------- elementwise ----------
__global__ void __launch_bounds__(256)
convert_split(const float* __restrict__ src, int lds,
              __nv_bfloat16* __restrict__ hi, __nv_bfloat16* __restrict__ lo,
              int ldd, int cols)
{
    const int r = blockIdx.y, c = blockIdx.x * 256 + threadIdx.x;
    if (c < cols) bsplit(src[(long long)r * lds + c], hi, lo, (long long)r * ldd + c);
}

__global__ void __launch_bounds__(256)
rmsnorm_kpe_kernel(const float* __restrict__ kva, const float* __restrict__ w,
                   const float* __restrict__ fc, const float* __restrict__ fs,
                   __nv_bfloat16* __restrict__ kvnh, __nv_bfloat16* __restrict__ kvnl,
                   float* __restrict__ kpe)
{
    const int tok = blockIdx.x, s = tok & (S_ - 1), tid = threadIdx.x;
    const float* in = kva + (size_t)tok * 576;
    __shared__ float sp[512];
    __shared__ float sh[8];
    float local = 0.f;
    for (int i = tid; i < 512; i += 256) { float v = in[i]; local += v * v; }
    float r = rsqrtf(block_sum_256(local, sh) * (1.0f / 512.f) + 1e-6f);
    float l2 = 0.f;
    for (int i = tid; i < 512; i += 256) {
        float v = in[i] * r * w[i];
        sp[i] = v;
        l2 += v * v;
    }
    float tot2 = block_sum_256(l2, sh);
    const long long ob = (long long)tok * KVN;
    if (tid == 0) bsplit(sqrtf(tot2 + 1.f), kvnh, kvnl, ob);
    for (int i = tid; i < 512; i += 256) bsplit(sp[i], kvnh, kvnl, ob + 1 + i);
    if (tid < 32) {
        float x1 = in[512 + 2 * tid], x2 = in[512 + 2 * tid + 1];
        float c = fc[s * 32 + tid], sn = fs[s * 32 + tid];
        kpe[(size_t)tok * 64 + 2 * tid]     = x1 * c - x2 * sn;
        kpe[(size_t)tok * 64 + 2 * tid + 1] = x1 * sn + x2 * c;
    }
}

__global__ void __launch_bounds__(256)
post_q_kernel(const float* __restrict__ q, const float* __restrict__ fc,
              const float* __restrict__ fs,
              __nv_bfloat16* __restrict__ qhp, __nv_bfloat16* __restrict__ qlp)
{
    const int gw = (blockIdx.x * blockDim.x + threadIdx.x) >> 5, lane = threadIdx.x & 31;
    if (gw >= M_ * H_) return;
    const int h = gw % H_, tok = gw / H_, b = tok / S_, s = tok & (S_ - 1);
    const float* qr = q + ((size_t)tok * H_ + h) * 192;
    const float c = fc[s * 32 + lane], sn = fs[s * 32 + lane];
    const float x1 = qr[128 + 2 * lane], x2 = qr[128 + 2 * lane + 1];
    const float r0 = x1 * c - x2 * sn, r1 = x1 * sn + x2 * c;
    float ss = r0 * r0 + r1 * r1;
    for (int d = lane; d < 128; d += 32) { float v = qr[d]; ss += v * v; }
    ss = warp_sum(ss);
    const long long ob = (((long long)b * H_ + h) * S_ + s) * KQA;
    if (lane == 0) bsplit(-sqrtf(ss + 1.f), qhp, qlp, ob);
    for (int d = lane; d < 128; d += 32) bsplit(qr[d], qhp, qlp, ob + 1 + d);
    bsplit(r0, qhp, qlp, ob + 129 + 2 * lane);
    bsplit(r1, qhp, qlp, ob + 129 + 2 * lane + 1);
}

__global__ void __launch_bounds__(256)
post_kv_kernel(const float* __restrict__ kv2, const float* __restrict__ kpe,
               __nv_bfloat16* __restrict__ khp, __nv_bfloat16* __restrict__ klp,
               __nv_bfloat16* __restrict__ vhp, __nv_bfloat16* __restrict__ vlp)
{
    const int gw = (blockIdx.x * blockDim.x + threadIdx.x) >> 5, lane = threadIdx.x & 31;
    if (gw >= M_ * H_) return;
    const int h = gw % H_, tok = gw / H_, b = tok / S_, s = tok & (S_ - 1);
    const float* row = kv2 + ((size_t)tok * H_ + h) * 256;
    const float* pe = kpe + (size_t)tok * 64;
    float ss = 0.f;
    for (int d = lane; d < 128; d += 32) { float v = row[d]; ss += v * v; }
    for (int d = lane; d < 64; d += 32) { float v = pe[d]; ss += v * v; }
    ss = warp_sum(ss);
    const long long kb = (((long long)b * H_ + h) * S_ + s) * KQA;
    if (lane == 0) bsplit(sqrtf(ss + 1.f), khp, klp, kb);
    for (int d = lane; d < 128; d += 32) bsplit(row[d], khp, klp, kb + 1 + d);
    for (int d = lane; d < 64; d += 32) bsplit(pe[d], khp, klp, kb + 129 + d);
    float sv = 0.f;
    for (int d = lane; d < 128; d += 32) { float v = row[128 + d]; sv += v * v; }
    sv = warp_sum(sv);
    const long long vb = ((long long)b * H_ + h) * VROWS * S_;
    if (lane == 0) bsplit(sqrtf(sv + 1.f), vhp, vlp, vb + s);
    for (int d = lane; d < 128; d += 32)
        bsplit(row[128 + d], vhp, vlp, vb + (long long)(1 + d) * S_ + s);
}

__global__ void __launch_bounds__(256)
final_t_kernel(float* __restrict__ out)
{
    const int row = blockIdx.x, tid = threadIdx.x;
    float* p = out + (size_t)row * 2048;
    __shared__ float sh[8];
    float local = 0.f;
    for (int i = 1 + tid; i < 2048; i += 256) { float v = p[i]; local += v * v; }
    float tot = block_sum_256(local, sh);
    if (tid == 0) p[0] = sqrtf(tot + 1.f);
}

extern "C" void kernel_launch(void* const* d_in, const int* in_sizes, int n_in,
                              void* d_out, int out_size)
{
    (void)in_sizes; (void)n_in; (void)out_size;
    const float* x      = (const float*)d_in[0];
    const float* fc     = (const float*)d_in[1];
    const float* fs     = (const float*)d_in[2];
    const float* wq_w   = (const float*)d_in[4];
    const float* wq_b   = (const float*)d_in[5];
    const float* wkva_w = (const float*)d_in[6];
    const float* wkva_b = (const float*)d_in[7];
    const float* kvnw   = (const float*)d_in[8];
    const float* wkvb_w = (const float*)d_in[9];
    const float* wkvb_b = (const float*)d_in[10];
    const float* wo_w   = (const float*)d_in[11];
    const float* wo_b   = (const float*)d_in[12];
    float* out = (float*)d_out;

    float *q, *kva, *kpe, *kv2;
    cudaGetSymbolAddress((void**)&q, g_q);
    cudaGetSymbolAddress((void**)&kva, g_kva);
    cudaGetSymbolAddress((void**)&kpe, g_kpe);
    cudaGetSymbolAddress((void**)&kv2, g_kv2);
    __nv_bfloat16 *xh, *xl, *wqh, *wql, *wkvah, *wkval, *kvnh, *kvnl, *wkvbh, *wkvbl;
    __nv_bfloat16 *qah, *qal, *kah, *kal, *vth, *vtl, *ch, *cl, *woh, *wol;
    cudaGetSymbolAddress((void**)&xh, g_xh);       cudaGetSymbolAddress((void**)&xl, g_xl);
    cudaGetSymbolAddress((void**)&wqh, g_wqh);     cudaGetSymbolAddress((void**)&wql, g_wql);
    cudaGetSymbolAddress((void**)&wkvah, g_wkvah); cudaGetSymbolAddress((void**)&wkval, g_wkval);
    cudaGetSymbolAddress((void**)&kvnh, g_kvnh);   cudaGetSymbolAddress((void**)&kvnl, g_kvnl);
    cudaGetSymbolAddress((void**)&wkvbh, g_wkvbh); cudaGetSymbolAddress((void**)&wkvbl, g_wkvbl);
    cudaGetSymbolAddress((void**)&qah, g_qah);     cudaGetSymbolAddress((void**)&qal, g_qal);
    cudaGetSymbolAddress((void**)&kah, g_kah);     cudaGetSymbolAddress((void**)&kal, g_kal);
    cudaGetSymbolAddress((void**)&vth, g_vth);     cudaGetSymbolAddress((void**)&vtl, g_vtl);
    cudaGetSymbolAddress((void**)&ch, g_ch);       cudaGetSymbolAddress((void**)&cl, g_cl);
    cudaGetSymbolAddress((void**)&woh, g_woh);     cudaGetSymbolAddress((void**)&wol, g_wol);

    cudaFuncSetAttribute(gemm_mma, cudaFuncAttributeMaxDynamicSharedMemorySize, (int)DSMEM);
    cudaFuncSetAttribute(fused_attn, cudaFuncAttributeMaxDynamicSharedMemorySize, (int)DSMEM_F);

    const dim3 blk(256);
    convert_split<<<dim3(8, M_), blk>>>(x, 2048, xh, xl, 2048, 2048);
    convert_split<<<dim3(8, 3072), blk>>>(wq_w, 2048, wqh, wql, 2048, 2048);
    convert_split<<<dim3(8, 576), blk>>>(wkva_w, 2048, wkvah, wkval, 2048, 2048);
    convert_split<<<dim3(3, 4096), blk>>>(wkvb_w, 513, wkvbh, wkvbl, KVN, 513);
    convert_split<<<dim3(9, 2047), blk>>>(wo_w, 2064, woh, wol, KCT, 2064);

    gemm_mma<<<dim3(24, 32), blk, DSMEM>>>(xh, xl, 2048, wqh, wql, 2048,
                                           q, 3072, wq_b, 3072, 2048);
    gemm_mma<<<dim3(5, 32), blk, DSMEM>>>(xh, xl, 2048, wkvah, wkval, 2048,
                                          kva, 576, wkva_b, 576, 2048);
    rmsnorm_kpe_kernel<<<M_, blk>>>(kva, kvnw, fc, fs, kvnh, kvnl, kpe);
    gemm_mma<<<dim3(32, 32), blk, DSMEM>>>(kvnh, kvnl, KVN, wkvbh, wkvbl, KVN,
                                           kv2, 4096, wkvb_b, 4096, KVN);
    post_q_kernel<<<(M_ * H_) / 8, blk>>>(q, fc, fs, qah, qal);
    post_kv_kernel<<<(M_ * H_) / 8, blk>>>(kv2, kpe, kah, kal, vth, vtl);
    fused_attn<<<dim3(8, 64), blk, DSMEM_F>>>(qah, qal, kah, kal, vth, vtl, ch, cl);
    gemm_mma<<<dim3(16, 32), blk, DSMEM>>>(ch, cl, KCT, woh, wol, KCT,
                                           out + 1, 2048, wo_b, 2047, KCT);
    final_t_kernel<<<M_, blk>>>(out);
}

// round 6
// speedup vs baseline: 3.4473x; 1.2247x over previous
#include <cuda_runtime.h>
#include <cuda_bf16.h>
#include <cuda_fp16.h>
#include <math.h>
#include <stdint.h>

namespace {
constexpr int B_ = 4, S_ = 1024, H_ = 16;
constexpr int M_ = B_ * S_;
constexpr float SC2 = 0.14396396f * 1.44269504f;    // 2/sqrt(193) * log2(e)
constexpr int KQA = 256, KVN = 576, KCT = 2112, VROWS = 136;
constexpr size_t DSMEM_H = 2 * 3 * 10240;           // fp16 gemm: 2 stages x 3 arrays
constexpr size_t DSMEM_F = 81920 + 2 * 36992;       // attn: 2x4 arrays + V hi/lo tiles
}

// fp32 scratch
__device__ float g_q[(size_t)M_ * 3072];
__device__ float g_kva[(size_t)M_ * 576];
__device__ float g_kpe[(size_t)M_ * 64];
__device__ float g_kv2[(size_t)M_ * 4096];
// fp16 (projection GEMMs): activations hi/lo, weights hi only
__device__ __half g_xh[(size_t)M_ * 2048], g_xl[(size_t)M_ * 2048];
__device__ __half g_wqh[(size_t)3072 * 2048];
__device__ __half g_wkvah[(size_t)640 * 2048];
__device__ __half g_kvnh[(size_t)M_ * KVN], g_kvnl[(size_t)M_ * KVN];
__device__ __half g_wkvbh[(size_t)4096 * KVN];
__device__ __half g_ch[(size_t)M_ * KCT], g_cl[(size_t)M_ * KCT];
__device__ __half g_woh[(size_t)2048 * KCT];
// bf16 (attention, 3-term split)
__device__ __nv_bfloat16 g_qah[(size_t)64 * S_ * KQA], g_qal[(size_t)64 * S_ * KQA];
__device__ __nv_bfloat16 g_kah[(size_t)64 * S_ * KQA], g_kal[(size_t)64 * S_ * KQA];
__device__ __nv_bfloat16 g_vth[(size_t)64 * VROWS * S_], g_vtl[(size_t)64 * VROWS * S_];

__device__ __forceinline__ uint32_t cvta_smem(const void* p) {
    uint32_t a;
    asm("{ .reg .u64 t; cvta.to.shared.u64 t, %1; cvt.u32.u64 %0, t; }" : "=r"(a) : "l"(p));
    return a;
}
#define CPASYNC16(s, g) asm volatile("cp.async.cg.shared.global [%0], [%1], 16;" :: "r"(s), "l"(g) : "memory")
#define CPCOMMIT()      asm volatile("cp.async.commit_group;" ::: "memory")
#define CPWAIT(n)       asm volatile("cp.async.wait_group %0;" :: "n"(n) : "memory")

__device__ __forceinline__ void ldsm_x4(uint32_t* r, uint32_t a) {
    asm volatile("ldmatrix.sync.aligned.m8n8.x4.shared.b16 {%0,%1,%2,%3}, [%4];"
                 : "=r"(r[0]), "=r"(r[1]), "=r"(r[2]), "=r"(r[3]) : "r"(a));
}
__device__ __forceinline__ void ldsm_x2(uint32_t* r, uint32_t a) {
    asm volatile("ldmatrix.sync.aligned.m8n8.x2.shared.b16 {%0,%1}, [%2];"
                 : "=r"(r[0]), "=r"(r[1]) : "r"(a));
}
__device__ __forceinline__ void mma_bf16(float* d, const uint32_t* a, const uint32_t* b) {
    asm volatile("mma.sync.aligned.m16n8k16.row.col.f32.bf16.bf16.f32 "
                 "{%0,%1,%2,%3}, {%4,%5,%6,%7}, {%8,%9}, {%0,%1,%2,%3};"
                 : "+f"(d[0]), "+f"(d[1]), "+f"(d[2]), "+f"(d[3])
                 : "r"(a[0]), "r"(a[1]), "r"(a[2]), "r"(a[3]), "r"(b[0]), "r"(b[1]));
}
__device__ __forceinline__ void mma_f16(float* d, const uint32_t* a, const uint32_t* b) {
    asm volatile("mma.sync.aligned.m16n8k16.row.col.f32.f16.f16.f32 "
                 "{%0,%1,%2,%3}, {%4,%5,%6,%7}, {%8,%9}, {%0,%1,%2,%3};"
                 : "+f"(d[0]), "+f"(d[1]), "+f"(d[2]), "+f"(d[3])
                 : "r"(a[0]), "r"(a[1]), "r"(a[2]), "r"(a[3]), "r"(b[0]), "r"(b[1]));
}
__device__ __forceinline__ uint32_t pack_split(float x, float y, uint32_t& lo) {
    __nv_bfloat162 h = __floats2bfloat162_rn(x, y);
    __nv_bfloat162 l = __floats2bfloat162_rn(x - __bfloat162float(h.x),
                                             y - __bfloat162float(h.y));
    lo = *reinterpret_cast<uint32_t*>(&l);
    return *reinterpret_cast<uint32_t*>(&h);
}
__device__ __forceinline__ float warp_sum(float v) {
#pragma unroll
    for (int o = 16; o; o >>= 1) v += __shfl_xor_sync(0xffffffffu, v, o);
    return v;
}
__device__ __forceinline__ float block_sum_256(float v, float* sh) {
    int tid = threadIdx.x;
#pragma unroll
    for (int o = 16; o; o >>= 1) v += __shfl_xor_sync(0xffffffffu, v, o);
    __syncthreads();
    if ((tid & 31) == 0) sh[tid >> 5] = v;
    __syncthreads();
    if (tid < 32) {
        float t = (tid < 8) ? sh[tid] : 0.f;
#pragma unroll
        for (int o = 4; o; o >>= 1) t += __shfl_xor_sync(0xffffffffu, t, o);
        if (tid == 0) sh[0] = t;
    }
    __syncthreads();
    return sh[0];
}
__device__ __forceinline__ void bsplit(float v, __nv_bfloat16* hi, __nv_bfloat16* lo, long long i) {
    __nv_bfloat16 h = __float2bfloat16(v);
    hi[i] = h;
    lo[i] = __float2bfloat16(v - __bfloat162float(h));
}
__device__ __forceinline__ void hsplit(float v, __half* hi, __half* lo, long long i) {
    __half h = __float2half_rn(v);
    hi[i] = h;
    lo[i] = __float2half_rn(v - __half2float(h));
}

// ============ fp16 2-term GEMM (projections): C = (Ah+Al) @ Bh^T + bias ============
__global__ void __launch_bounds__(256, 1)
gemm_h2(const __half* __restrict__ Ah, const __half* __restrict__ Al, int lda,
        const __half* __restrict__ Bh, int ldb,
        float* __restrict__ C, int ldc,
        const float* __restrict__ bias, int Nreal, int K)
{
    const int bm = blockIdx.y * 128, bn = blockIdx.x * 128;
    const int nch = K >> 5;
    extern __shared__ __align__(16) char smem[];
    const uint32_t sbase = cvta_smem(smem);
    const int tid = threadIdx.x, wid = tid >> 5, lane = tid & 31;
    const int wm = (wid >> 2) * 64, wn = (wid & 3) * 32;

    float acc[4][4][4] = {};
    const __half* srcs[3] = {Ah, Al, Bh};

    auto load_stage = [&](int s, int c) {
        const long long k0 = (long long)c * 32;
#pragma unroll
        for (int arr = 0; arr < 3; ++arr) {
            const __half* src = srcs[arr];
            const int ld = (arr < 2) ? lda : ldb;
            const int ro = (arr < 2) ? bm : bn;
            const uint32_t base = sbase + (uint32_t)s * 30720u + (uint32_t)arr * 10240u;
#pragma unroll
            for (int j = 0; j < 2; ++j) {
                const int cid = tid + j * 256;
                const int row = cid >> 2, ch = cid & 3;
                CPASYNC16(base + (uint32_t)(row * 80 + ch * 16),
                          src + (long long)(ro + row) * ld + k0 + ch * 8);
            }
        }
        CPCOMMIT();
    };

    load_stage(0, 0);
    for (int c = 0; c < nch; ++c) {
        if (c + 1 < nch) { load_stage((c + 1) & 1, c + 1); CPWAIT(1); }
        else             { CPWAIT(0); }
        __syncthreads();
        const uint32_t st = sbase + (uint32_t)(c & 1) * 30720u;
#pragma unroll
        for (int ks = 0; ks < 2; ++ks) {
            uint32_t ah[4][4], al[4][4], bh[4][2];
            const int arow = wm + (lane & 15);
            const int acol = ks * 16 + (lane >> 4) * 8;
#pragma unroll
            for (int mf = 0; mf < 4; ++mf) {
                const uint32_t off = (uint32_t)((arow + mf * 16) * 80 + acol * 2);
                ldsm_x4(ah[mf], st + off);
                ldsm_x4(al[mf], st + 10240u + off);
            }
            const int brow = wn + (lane & 7);
            const int bcol = ks * 16 + ((lane >> 3) & 1) * 8;
#pragma unroll
            for (int nf = 0; nf < 4; ++nf) {
                const uint32_t off = (uint32_t)((brow + nf * 8) * 80 + bcol * 2);
                ldsm_x2(bh[nf], st + 20480u + off);
            }
#pragma unroll
            for (int mf = 0; mf < 4; ++mf)
#pragma unroll
                for (int nf = 0; nf < 4; ++nf) {
                    mma_f16(acc[mf][nf], ah[mf], bh[nf]);
                    mma_f16(acc[mf][nf], al[mf], bh[nf]);
                }
        }
        __syncthreads();
    }
#pragma unroll
    for (int mf = 0; mf < 4; ++mf) {
        const long long r0 = bm + wm + mf * 16 + (lane >> 2);
#pragma unroll
        for (int nf = 0; nf < 4; ++nf) {
            const int col = bn + wn + nf * 8 + (lane & 3) * 2;
            const float b0 = bias ? bias[min(col, Nreal - 1)] : 0.f;
            const float b1 = bias ? bias[min(col + 1, Nreal - 1)] : 0.f;
            if (col < Nreal) {
                C[r0 * ldc + col] = acc[mf][nf][0] + b0;
                C[(r0 + 8) * ldc + col] = acc[mf][nf][2] + b0;
            }
            if (col + 1 < Nreal) {
                C[r0 * ldc + col + 1] = acc[mf][nf][1] + b1;
                C[(r0 + 8) * ldc + col + 1] = acc[mf][nf][3] + b1;
            }
        }
    }
}

// ============ fused flash-attention + Lorentz centroid (bf16 3-term) ============
// grid (8, 64): x -> q-block (descending), y -> (b*H + h)
__global__ void __launch_bounds__(256, 1)
fused_attn(const __nv_bfloat16* __restrict__ qh, const __nv_bfloat16* __restrict__ ql,
           const __nv_bfloat16* __restrict__ kh, const __nv_bfloat16* __restrict__ kl,
           const __nv_bfloat16* __restrict__ vh, const __nv_bfloat16* __restrict__ vl,
           __half* __restrict__ ch, __half* __restrict__ cl)
{
    const int iq = 7 - (int)blockIdx.x;
    const int bh = (int)blockIdx.y;
    const long long qkbase = (long long)bh * S_ * KQA;
    const long long vgbase = (long long)bh * VROWS * S_;
    extern __shared__ __align__(16) char smem[];
    const uint32_t sbase = cvta_smem(smem);
    const uint32_t vsH = sbase + 81920u, vsL = vsH + 36992u;
    const int tid = threadIdx.x, w = tid >> 5, lane = tid & 31;

    float O[17][4] = {};
    float m0 = -1e30f, m1 = -1e30f, l0 = 0.f, l1 = 0.f;

    for (int j = 0; j <= iq; ++j) {
        {
            const __nv_bfloat16* srcs[4] = {qh + qkbase + (long long)iq * 128 * KQA,
                                            ql + qkbase + (long long)iq * 128 * KQA,
                                            kh + qkbase + (long long)j * 128 * KQA,
                                            kl + qkbase + (long long)j * 128 * KQA};
#pragma unroll
            for (int arr = 0; arr < 4; ++arr)
#pragma unroll
                for (int t2 = 0; t2 < 2; ++t2) {
                    const int cid = tid + t2 * 256;
                    const int row = cid >> 2, seg = cid & 3;
                    CPASYNC16(sbase + arr * 10240u + (uint32_t)(row * 80 + seg * 16),
                              srcs[arr] + (long long)row * KQA + seg * 8);
                }
            CPCOMMIT();
            for (int idx = tid; idx < 2176; idx += 256) {
                const int row = idx >> 4, seg = idx & 15;
                const long long g = vgbase + (long long)row * S_ + j * 128 + seg * 8;
                CPASYNC16(vsH + (uint32_t)(row * 272 + seg * 16), vh + g);
                CPASYNC16(vsL + (uint32_t)(row * 272 + seg * 16), vl + g);
            }
            CPCOMMIT();
        }
        float acc[16][4] = {};
        for (int c = 0; c < 7; ++c) {
            if (c < 6) {
                const int s = (c + 1) & 1;
                const long long k0 = (long long)(c + 1) * 32;
                const __nv_bfloat16* srcs[4] = {qh + qkbase + (long long)iq * 128 * KQA,
                                                ql + qkbase + (long long)iq * 128 * KQA,
                                                kh + qkbase + (long long)j * 128 * KQA,
                                                kl + qkbase + (long long)j * 128 * KQA};
#pragma unroll
                for (int arr = 0; arr < 4; ++arr)
#pragma unroll
                    for (int t2 = 0; t2 < 2; ++t2) {
                        const int cid = tid + t2 * 256;
                        const int row = cid >> 2, seg = cid & 3;
                        CPASYNC16(sbase + (uint32_t)s * 40960u + arr * 10240u +
                                      (uint32_t)(row * 80 + seg * 16),
                                  srcs[arr] + (long long)row * KQA + k0 + seg * 8);
                    }
                CPCOMMIT();
                if (c == 0) CPWAIT(2); else CPWAIT(1);
            } else {
                CPWAIT(0);
            }
            __syncthreads();
            const uint32_t st = sbase + (uint32_t)(c & 1) * 40960u;
#pragma unroll
            for (int ks = 0; ks < 2; ++ks) {
                uint32_t ah[4], al[4];
                const uint32_t aoff =
                    (uint32_t)((w * 16 + (lane & 15)) * 80 + (ks * 16 + (lane >> 4) * 8) * 2);
                ldsm_x4(ah, st + aoff);
                ldsm_x4(al, st + 10240u + aoff);
#pragma unroll
                for (int nf = 0; nf < 16; ++nf) {
                    const uint32_t boff =
                        (uint32_t)((nf * 8 + (lane & 7)) * 80 +
                                   (ks * 16 + ((lane >> 3) & 1) * 8) * 2);
                    uint32_t bh2[2], bl2[2];
                    ldsm_x2(bh2, st + 20480u + boff);
                    ldsm_x2(bl2, st + 30720u + boff);
                    mma_bf16(acc[nf], ah, bh2);
                    mma_bf16(acc[nf], ah, bl2);
                    mma_bf16(acc[nf], al, bh2);
                }
            }
            __syncthreads();
        }
        if (j == iq) {
            const int rt0 = w * 16 + (lane >> 2), rt1 = rt0 + 8;
#pragma unroll
            for (int nf = 0; nf < 16; ++nf) {
                const int ct = nf * 8 + (lane & 3) * 2;
                if (ct > rt0)     acc[nf][0] = -1e30f;
                if (ct + 1 > rt0) acc[nf][1] = -1e30f;
                if (ct > rt1)     acc[nf][2] = -1e30f;
                if (ct + 1 > rt1) acc[nf][3] = -1e30f;
            }
        }
        float mx0 = -1e30f, mx1 = -1e30f;
#pragma unroll
        for (int nf = 0; nf < 16; ++nf) {
            mx0 = fmaxf(mx0, fmaxf(acc[nf][0], acc[nf][1]));
            mx1 = fmaxf(mx1, fmaxf(acc[nf][2], acc[nf][3]));
        }
        mx0 = fmaxf(mx0, __shfl_xor_sync(~0u, mx0, 1));
        mx0 = fmaxf(mx0, __shfl_xor_sync(~0u, mx0, 2));
        mx1 = fmaxf(mx1, __shfl_xor_sync(~0u, mx1, 1));
        mx1 = fmaxf(mx1, __shfl_xor_sync(~0u, mx1, 2));
        const float mn0 = fmaxf(m0, mx0), mn1 = fmaxf(m1, mx1);
        const float a0 = exp2f((m0 - mn0) * SC2), a1 = exp2f((m1 - mn1) * SC2);
        l0 *= a0; l1 *= a1;
#pragma unroll
        for (int nf = 0; nf < 17; ++nf) {
            O[nf][0] *= a0; O[nf][1] *= a0; O[nf][2] *= a1; O[nf][3] *= a1;
        }
        float s0 = 0.f, s1 = 0.f;
#pragma unroll
        for (int nf = 0; nf < 16; ++nf) {
            acc[nf][0] = exp2f((acc[nf][0] - mn0) * SC2);
            acc[nf][1] = exp2f((acc[nf][1] - mn0) * SC2);
            acc[nf][2] = exp2f((acc[nf][2] - mn1) * SC2);
            acc[nf][3] = exp2f((acc[nf][3] - mn1) * SC2);
            s0 += acc[nf][0] + acc[nf][1];
            s1 += acc[nf][2] + acc[nf][3];
        }
        s0 += __shfl_xor_sync(~0u, s0, 1); s0 += __shfl_xor_sync(~0u, s0, 2);
        s1 += __shfl_xor_sync(~0u, s1, 1); s1 += __shfl_xor_sync(~0u, s1, 2);
        l0 += s0; l1 += s1; m0 = mn0; m1 = mn1;
#pragma unroll
        for (int kf = 0; kf < 8; ++kf) {
            uint32_t Ph[4], Pl[4];
            Ph[0] = pack_split(acc[2 * kf][0], acc[2 * kf][1], Pl[0]);
            Ph[1] = pack_split(acc[2 * kf][2], acc[2 * kf][3], Pl[1]);
            Ph[2] = pack_split(acc[2 * kf + 1][0], acc[2 * kf + 1][1], Pl[2]);
            Ph[3] = pack_split(acc[2 * kf + 1][2], acc[2 * kf + 1][3], Pl[3]);
#pragma unroll
            for (int nf = 0; nf < 17; ++nf) {
                const uint32_t voff =
                    (uint32_t)((nf * 8 + (lane & 7)) * 272 +
                               (kf * 16 + ((lane >> 3) & 1) * 8) * 2);
                uint32_t vh2[2], vl2[2];
                ldsm_x2(vh2, vsH + voff);
                ldsm_x2(vl2, vsL + voff);
                mma_bf16(O[nf], Ph, vh2);
                mma_bf16(O[nf], Ph, vl2);
                mma_bf16(O[nf], Pl, vh2);
            }
        }
        __syncthreads();
    }
    const float i0 = 1.f / l0, i1 = 1.f / l1;
    float ss0 = 0.f, ss1 = 0.f;
#pragma unroll
    for (int nf = 0; nf < 17; ++nf) {
        O[nf][0] *= i0; O[nf][1] *= i0; O[nf][2] *= i1; O[nf][3] *= i1;
        ss0 += O[nf][0] * O[nf][0] + O[nf][1] * O[nf][1];
        ss1 += O[nf][2] * O[nf][2] + O[nf][3] * O[nf][3];
    }
    ss0 += __shfl_xor_sync(~0u, ss0, 1); ss0 += __shfl_xor_sync(~0u, ss0, 2);
    ss1 += __shfl_xor_sync(~0u, ss1, 1); ss1 += __shfl_xor_sync(~0u, ss1, 2);
    const float t0 = __shfl_sync(~0u, O[0][0], lane & ~3);
    const float t1 = __shfl_sync(~0u, O[0][2], lane & ~3);
    const float d0 = rsqrtf(fmaxf(fabsf(2.f * t0 * t0 - ss0), 1e-8f));
    const float d1 = rsqrtf(fmaxf(fabsf(2.f * t1 * t1 - ss1), 1e-8f));
    const int hh = bh & 15;
    const long long tok0 = (long long)(bh >> 4) * 1024 + iq * 128 + w * 16 + (lane >> 2);
    const long long o0 = tok0 * KCT + hh * 129, o1 = (tok0 + 8) * KCT + hh * 129;
#pragma unroll
    for (int nf = 0; nf < 17; ++nf) {
        const int cc = nf * 8 + (lane & 3) * 2;
        if (cc < 129) {
            hsplit(O[nf][0] * d0, ch, cl, o0 + cc);
            hsplit(O[nf][2] * d1, ch, cl, o1 + cc);
        }
        if (cc + 1 < 129) {
            hsplit(O[nf][1] * d0, ch, cl, o0 + cc + 1);
            hsplit(O[nf][3] * d1, ch, cl, o1 + cc + 1);
        }
    }
}

// ---------- elementwise ----------
__global__ void __launch_bounds__(256)
convert_split_h(const float* __restrict__ src, int lds,
                __half* __restrict__ hi, __half* __restrict__ lo, int ldd, int cols)
{
    const int r = blockIdx.y, c = blockIdx.x * 256 + threadIdx.x;
    if (c < cols) hsplit(src[(long long)r * lds + c], hi, lo, (long long)r * ldd + c);
}
__global__ void __launch_bounds__(256)
convert_h(const float* __restrict__ src, int lds,
          __half* __restrict__ hi, int ldd, int cols)
{
    const int r = blockIdx.y, c = blockIdx.x * 256 + threadIdx.x;
    if (c < cols) hi[(long long)r * ldd + c] = __float2half_rn(src[(long long)r * lds + c]);
}

__global__ void __launch_bounds__(256)
rmsnorm_kpe_kernel(const float* __restrict__ kva, const float* __restrict__ w,
                   const float* __restrict__ fc, const float* __restrict__ fs,
                   __half* __restrict__ kvnh, __half* __restrict__ kvnl,
                   float* __restrict__ kpe)
{
    const int tok = blockIdx.x, s = tok & (S_ - 1), tid = threadIdx.x;
    const float* in = kva + (size_t)tok * 576;
    __shared__ float sp[512];
    __shared__ float sh[8];
    float local = 0.f;
    for (int i = tid; i < 512; i += 256) { float v = in[i]; local += v * v; }
    float r = rsqrtf(block_sum_256(local, sh) * (1.0f / 512.f) + 1e-6f);
    float l2 = 0.f;
    for (int i = tid; i < 512; i += 256) {
        float v = in[i] * r * w[i];
        sp[i] = v;
        l2 += v * v;
    }
    float tot2 = block_sum_256(l2, sh);
    const long long ob = (long long)tok * KVN;
    if (tid == 0) hsplit(sqrtf(tot2 + 1.f), kvnh, kvnl, ob);
    for (int i = tid; i < 512; i += 256) hsplit(sp[i], kvnh, kvnl, ob + 1 + i);
    if (tid < 32) {
        float x1 = in[512 + 2 * tid], x2 = in[512 + 2 * tid + 1];
        float c = fc[s * 32 + tid], sn = fs[s * 32 + tid];
        kpe[(size_t)tok * 64 + 2 * tid]     = x1 * c - x2 * sn;
        kpe[(size_t)tok * 64 + 2 * tid + 1] = x1 * sn + x2 * c;
    }
}

__global__ void __launch_bounds__(256)
post_q_kernel(const float* __restrict__ q, const float* __restrict__ fc,
              const float* __restrict__ fs,
              __nv_bfloat16* __restrict__ qhp, __nv_bfloat16* __restrict__ qlp)
{
    const int gw = (blockIdx.x * blockDim.x + threadIdx.x) >> 5, lane = threadIdx.x & 31;
    if (gw >= M_ * H_) return;
    const int h = gw % H_, tok = gw / H_, b = tok / S_, s = tok & (S_ - 1);
    const float* qr = q + ((size_t)tok * H_ + h) * 192;
    const float c = fc[s * 32 + lane], sn = fs[s * 32 + lane];
    const float x1 = qr[128 + 2 * lane], x2 = qr[128 + 2 * lane + 1];
    const float r0 = x1 * c - x2 * sn, r1 = x1 * sn + x2 * c;
    float ss = r0 * r0 + r1 * r1;
    for (int d = lane; d < 128; d += 32) { float v = qr[d]; ss += v * v; }
    ss = warp_sum(ss);
    const long long ob = (((long long)b * H_ + h) * S_ + s) * KQA;
    if (lane == 0) bsplit(-sqrtf(ss + 1.f), qhp, qlp, ob);
    for (int d = lane; d < 128; d += 32) bsplit(qr[d], qhp, qlp, ob + 1 + d);
    bsplit(r0, qhp, qlp, ob + 129 + 2 * lane);
    bsplit(r1, qhp, qlp, ob + 129 + 2 * lane + 1);
}

__global__ void __launch_bounds__(256)
post_kv_kernel(const float* __restrict__ kv2, const float* __restrict__ kpe,
               __nv_bfloat16* __restrict__ khp, __nv_bfloat16* __restrict__ klp,
               __nv_bfloat16* __restrict__ vhp, __nv_bfloat16* __restrict__ vlp)
{
    const int gw = (blockIdx.x * blockDim.x + threadIdx.x) >> 5, lane = threadIdx.x & 31;
    if (gw >= M_ * H_) return;
    const int h = gw % H_, tok = gw / H_, b = tok / S_, s = tok & (S_ - 1);
    const float* row = kv2 + ((size_t)tok * H_ + h) * 256;
    const float* pe = kpe + (size_t)tok * 64;
    float ss = 0.f;
    for (int d = lane; d < 128; d += 32) { float v = row[d]; ss += v * v; }
    for (int d = lane; d < 64; d += 32) { float v = pe[d]; ss += v * v; }
    ss = warp_sum(ss);
    const long long kb = (((long long)b * H_ + h) * S_ + s) * KQA;
    if (lane == 0) bsplit(sqrtf(ss + 1.f), khp, klp, kb);
    for (int d = lane; d < 128; d += 32) bsplit(row[d], khp, klp, kb + 1 + d);
    for (int d = lane; d < 64; d += 32) bsplit(pe[d], khp, klp, kb + 129 + d);
    float sv = 0.f;
    for (int d = lane; d < 128; d += 32) { float v = row[128 + d]; sv += v * v; }
    sv = warp_sum(sv);
    const long long vb = ((long long)b * H_ + h) * VROWS * S_;
    if (lane == 0) bsplit(sqrtf(sv + 1.f), vhp, vlp, vb + s);
    for (int d = lane; d < 128; d += 32)
        bsplit(row[128 + d], vhp, vlp, vb + (long long)(1 + d) * S_ + s);
}

__global__ void __launch_bounds__(256)
final_t_kernel(float* __restrict__ out)
{
    const int row = blockIdx.x, tid = threadIdx.x;
    float* p = out + (size_t)row * 2048;
    __shared__ float sh[8];
    float local = 0.f;
    for (int i = 1 + tid; i < 2048; i += 256) { float v = p[i]; local += v * v; }
    float tot = block_sum_256(local, sh);
    if (tid == 0) p[0] = sqrtf(tot + 1.f);
}

extern "C" void kernel_launch(void* const* d_in, const int* in_sizes, int n_in,
                              void* d_out, int out_size)
{
    (void)in_sizes; (void)n_in; (void)out_size;
    const float* x      = (const float*)d_in[0];
    const float* fc     = (const float*)d_in[1];
    const float* fs     = (const float*)d_in[2];
    const float* wq_w   = (const float*)d_in[4];
    const float* wq_b   = (const float*)d_in[5];
    const float* wkva_w = (const float*)d_in[6];
    const float* wkva_b = (const float*)d_in[7];
    const float* kvnw   = (const float*)d_in[8];
    const float* wkvb_w = (const float*)d_in[9];
    const float* wkvb_b = (const float*)d_in[10];
    const float* wo_w   = (const float*)d_in[11];
    const float* wo_b   = (const float*)d_in[12];
    float* out = (float*)d_out;

    float *q, *kva, *kpe, *kv2;
    cudaGetSymbolAddress((void**)&q, g_q);
    cudaGetSymbolAddress((void**)&kva, g_kva);
    cudaGetSymbolAddress((void**)&kpe, g_kpe);
    cudaGetSymbolAddress((void**)&kv2, g_kv2);
    __half *xh, *xl, *wqh, *wkvah, *kvnh, *kvnl, *wkvbh, *ch, *cl, *woh;
    __nv_bfloat16 *qah, *qal, *kah, *kal, *vth, *vtl;
    cudaGetSymbolAddress((void**)&xh, g_xh);       cudaGetSymbolAddress((void**)&xl, g_xl);
    cudaGetSymbolAddress((void**)&wqh, g_wqh);
    cudaGetSymbolAddress((void**)&wkvah, g_wkvah);
    cudaGetSymbolAddress((void**)&kvnh, g_kvnh);   cudaGetSymbolAddress((void**)&kvnl, g_kvnl);
    cudaGetSymbolAddress((void**)&wkvbh, g_wkvbh);
    cudaGetSymbolAddress((void**)&ch, g_ch);       cudaGetSymbolAddress((void**)&cl, g_cl);
    cudaGetSymbolAddress((void**)&woh, g_woh);
    cudaGetSymbolAddress((void**)&qah, g_qah);     cudaGetSymbolAddress((void**)&qal, g_qal);
    cudaGetSymbolAddress((void**)&kah, g_kah);     cudaGetSymbolAddress((void**)&kal, g_kal);
    cudaGetSymbolAddress((void**)&vth, g_vth);     cudaGetSymbolAddress((void**)&vtl, g_vtl);

    cudaFuncSetAttribute(gemm_h2, cudaFuncAttributeMaxDynamicSharedMemorySize, (int)DSMEM_H);
    cudaFuncSetAttribute(fused_attn, cudaFuncAttributeMaxDynamicSharedMemorySize, (int)DSMEM_F);

    const dim3 blk(256);
    convert_split_h<<<dim3(8, M_), blk>>>(x, 2048, xh, xl, 2048, 2048);
    convert_h<<<dim3(8, 3072), blk>>>(wq_w, 2048, wqh, 2048, 2048);
    convert_h<<<dim3(8, 576), blk>>>(wkva_w, 2048, wkvah, 2048, 2048);
    convert_h<<<dim3(3, 4096), blk>>>(wkvb_w, 513, wkvbh, KVN, 513);
    convert_h<<<dim3(9, 2047), blk>>>(wo_w, 2064, woh, KCT, 2064);

    // Q proj: (4096x2048) @ (3072x2048)^T
    gemm_h2<<<dim3(24, 32), blk, DSMEM_H>>>(xh, xl, 2048, wqh, 2048,
                                            q, 3072, wq_b, 3072, 2048);
    // KV-A proj: (4096x2048) @ (576x2048)^T
    gemm_h2<<<dim3(5, 32), blk, DSMEM_H>>>(xh, xl, 2048, wkvah, 2048,
                                           kva, 576, wkva_b, 576, 2048);
    rmsnorm_kpe_kernel<<<M_, blk>>>(kva, kvnw, fc, fs, kvnh, kvnl, kpe);
    // KV-B proj: (4096x576) @ (4096x576)^T
    gemm_h2<<<dim3(32, 32), blk, DSMEM_H>>>(kvnh, kvnl, KVN, wkvbh, KVN,
                                            kv2, 4096, wkvb_b, 4096, KVN);
    post_q_kernel<<<(M_ * H_) / 8, blk>>>(q, fc, fs, qah, qal);
    post_kv_kernel<<<(M_ * H_) / 8, blk>>>(kv2, kpe, kah, kal, vth, vtl);
    fused_attn<<<dim3(8, 64), blk, DSMEM_F>>>(qah, qal, kah, kal, vth, vtl, ch, cl);
    // out proj: (4096x2112) @ (2047x2112)^T -> out[:,1:]
    gemm_h2<<<dim3(16, 32), blk, DSMEM_H>>>(ch, cl, KCT, woh, KCT,
                                            out + 1, 2048, wo_b, 2047, KCT);
    final_t_kernel<<<M_, blk>>>(out);
}

// round 7
// speedup vs baseline: 3.6960x; 1.0721x over previous
#include <cuda_runtime.h>
#include <cuda_bf16.h>
#include <cuda_fp16.h>
#include <math.h>
#include <stdint.h>

namespace {
constexpr int B_ = 4, S_ = 1024, H_ = 16;
constexpr int M_ = B_ * S_;
constexpr float SC2 = 0.14396396f * 1.44269504f;    // 2/sqrt(193) * log2(e)
constexpr int KQS = 192, KVN = 576, KCT = 2112, VROWS = 136;
constexpr size_t DSMEM_H = 2 * 3 * 10240;           // fp16 gemm: 2 stages x 3 arrays
// attn: 2 stages x 3 arrays (qh,ql,k) + V hi/lo (136x272B each) + t_k (128 f32)
constexpr size_t DSMEM_F = 61440 + 2 * 36992 + 512; // 135936
}

// fp32 scratch
__device__ float g_q[(size_t)M_ * 3072];
__device__ float g_kva[(size_t)M_ * 576];
__device__ float g_kpe[(size_t)M_ * 64];
__device__ float g_kv2[(size_t)M_ * 4096];
__device__ float g_tq[(size_t)64 * S_], g_tk[(size_t)64 * S_];
// fp16 projection operands
__device__ __half g_xh[(size_t)M_ * 2048], g_xl[(size_t)M_ * 2048];
__device__ __half g_wqh[(size_t)3072 * 2048];
__device__ __half g_wkvah[(size_t)640 * 2048];
__device__ __half g_kvnh[(size_t)M_ * KVN], g_kvnl[(size_t)M_ * KVN];
__device__ __half g_wkvbh[(size_t)4096 * KVN];
__device__ __half g_ch[(size_t)M_ * KCT], g_cl[(size_t)M_ * KCT];
__device__ __half g_woh[(size_t)2048 * KCT];
// fp16 attention operands (spatial only)
__device__ __half g_qsh[(size_t)64 * S_ * KQS], g_qsl[(size_t)64 * S_ * KQS];
__device__ __half g_ksh[(size_t)64 * S_ * KQS];
__device__ __half g_vth[(size_t)64 * VROWS * S_], g_vtl[(size_t)64 * VROWS * S_];

__device__ __forceinline__ uint32_t cvta_smem(const void* p) {
    uint32_t a;
    asm("{ .reg .u64 t; cvta.to.shared.u64 t, %1; cvt.u32.u64 %0, t; }" : "=r"(a) : "l"(p));
    return a;
}
#define CPASYNC16(s, g) asm volatile("cp.async.cg.shared.global [%0], [%1], 16;" :: "r"(s), "l"(g) : "memory")
#define CPCOMMIT()      asm volatile("cp.async.commit_group;" ::: "memory")
#define CPWAIT(n)       asm volatile("cp.async.wait_group %0;" :: "n"(n) : "memory")

__device__ __forceinline__ void ldsm_x4(uint32_t* r, uint32_t a) {
    asm volatile("ldmatrix.sync.aligned.m8n8.x4.shared.b16 {%0,%1,%2,%3}, [%4];"
                 : "=r"(r[0]), "=r"(r[1]), "=r"(r[2]), "=r"(r[3]) : "r"(a));
}
__device__ __forceinline__ void ldsm_x2(uint32_t* r, uint32_t a) {
    asm volatile("ldmatrix.sync.aligned.m8n8.x2.shared.b16 {%0,%1}, [%2];"
                 : "=r"(r[0]), "=r"(r[1]) : "r"(a));
}
__device__ __forceinline__ void mma_f16(float* d, const uint32_t* a, const uint32_t* b) {
    asm volatile("mma.sync.aligned.m16n8k16.row.col.f32.f16.f16.f32 "
                 "{%0,%1,%2,%3}, {%4,%5,%6,%7}, {%8,%9}, {%0,%1,%2,%3};"
                 : "+f"(d[0]), "+f"(d[1]), "+f"(d[2]), "+f"(d[3])
                 : "r"(a[0]), "r"(a[1]), "r"(a[2]), "r"(a[3]), "r"(b[0]), "r"(b[1]));
}
__device__ __forceinline__ uint32_t packh2(float x, float y) {
    __half2 h = __floats2half2_rn(x, y);
    return *reinterpret_cast<uint32_t*>(&h);
}
__device__ __forceinline__ float warp_sum(float v) {
#pragma unroll
    for (int o = 16; o; o >>= 1) v += __shfl_xor_sync(0xffffffffu, v, o);
    return v;
}
__device__ __forceinline__ float block_sum_256(float v, float* sh) {
    int tid = threadIdx.x;
#pragma unroll
    for (int o = 16; o; o >>= 1) v += __shfl_xor_sync(0xffffffffu, v, o);
    __syncthreads();
    if ((tid & 31) == 0) sh[tid >> 5] = v;
    __syncthreads();
    if (tid < 32) {
        float t = (tid < 8) ? sh[tid] : 0.f;
#pragma unroll
        for (int o = 4; o; o >>= 1) t += __shfl_xor_sync(0xffffffffu, t, o);
        if (tid == 0) sh[0] = t;
    }
    __syncthreads();
    return sh[0];
}
__device__ __forceinline__ void hsplit(float v, __half* hi, __half* lo, long long i) {
    __half h = __float2half_rn(v);
    hi[i] = h;
    lo[i] = __float2half_rn(v - __half2float(h));
}

// ============ fp16 2-term GEMM (projections): C = (Ah+Al) @ Bh^T + bias ============
__global__ void __launch_bounds__(256, 1)
gemm_h2(const __half* __restrict__ Ah, const __half* __restrict__ Al, int lda,
        const __half* __restrict__ Bh, int ldb,
        float* __restrict__ C, int ldc,
        const float* __restrict__ bias, int Nreal, int K)
{
    const int bm = blockIdx.y * 128, bn = blockIdx.x * 128;
    const int nch = K >> 5;
    extern __shared__ __align__(16) char smem[];
    const uint32_t sbase = cvta_smem(smem);
    const int tid = threadIdx.x, wid = tid >> 5, lane = tid & 31;
    const int wm = (wid >> 2) * 64, wn = (wid & 3) * 32;

    float acc[4][4][4] = {};
    const __half* srcs[3] = {Ah, Al, Bh};

    auto load_stage = [&](int s, int c) {
        const long long k0 = (long long)c * 32;
#pragma unroll
        for (int arr = 0; arr < 3; ++arr) {
            const __half* src = srcs[arr];
            const int ld = (arr < 2) ? lda : ldb;
            const int ro = (arr < 2) ? bm : bn;
            const uint32_t base = sbase + (uint32_t)s * 30720u + (uint32_t)arr * 10240u;
#pragma unroll
            for (int j = 0; j < 2; ++j) {
                const int cid = tid + j * 256;
                const int row = cid >> 2, ch = cid & 3;
                CPASYNC16(base + (uint32_t)(row * 80 + ch * 16),
                          src + (long long)(ro + row) * ld + k0 + ch * 8);
            }
        }
        CPCOMMIT();
    };

    load_stage(0, 0);
    for (int c = 0; c < nch; ++c) {
        if (c + 1 < nch) { load_stage((c + 1) & 1, c + 1); CPWAIT(1); }
        else             { CPWAIT(0); }
        __syncthreads();
        const uint32_t st = sbase + (uint32_t)(c & 1) * 30720u;
#pragma unroll
        for (int ks = 0; ks < 2; ++ks) {
            uint32_t ah[4][4], al[4][4], bh[4][2];
            const int arow = wm + (lane & 15);
            const int acol = ks * 16 + (lane >> 4) * 8;
#pragma unroll
            for (int mf = 0; mf < 4; ++mf) {
                const uint32_t off = (uint32_t)((arow + mf * 16) * 80 + acol * 2);
                ldsm_x4(ah[mf], st + off);
                ldsm_x4(al[mf], st + 10240u + off);
            }
            const int brow = wn + (lane & 7);
            const int bcol = ks * 16 + ((lane >> 3) & 1) * 8;
#pragma unroll
            for (int nf = 0; nf < 4; ++nf) {
                const uint32_t off = (uint32_t)((brow + nf * 8) * 80 + bcol * 2);
                ldsm_x2(bh[nf], st + 20480u + off);
            }
#pragma unroll
            for (int mf = 0; mf < 4; ++mf)
#pragma unroll
                for (int nf = 0; nf < 4; ++nf) {
                    mma_f16(acc[mf][nf], ah[mf], bh[nf]);
                    mma_f16(acc[mf][nf], al[mf], bh[nf]);
                }
        }
        __syncthreads();
    }
#pragma unroll
    for (int mf = 0; mf < 4; ++mf) {
        const long long r0 = bm + wm + mf * 16 + (lane >> 2);
#pragma unroll
        for (int nf = 0; nf < 4; ++nf) {
            const int col = bn + wn + nf * 8 + (lane & 3) * 2;
            const float b0 = bias ? bias[min(col, Nreal - 1)] : 0.f;
            const float b1 = bias ? bias[min(col + 1, Nreal - 1)] : 0.f;
            if (col < Nreal) {
                C[r0 * ldc + col] = acc[mf][nf][0] + b0;
                C[(r0 + 8) * ldc + col] = acc[mf][nf][2] + b0;
            }
            if (col + 1 < Nreal) {
                C[r0 * ldc + col + 1] = acc[mf][nf][1] + b1;
                C[(r0 + 8) * ldc + col + 1] = acc[mf][nf][3] + b1;
            }
        }
    }
}

// ============ fused flash-attention + Lorentz centroid ============
// spatial QK on tensor cores (fp16, q 2-term, k 1-term); t_q*t_k in fp32 scalars.
// grid (8, 64): x -> q-block (descending), y -> (b*H + h)
__global__ void __launch_bounds__(256, 1)
fused_attn(const __half* __restrict__ qsh, const __half* __restrict__ qsl,
           const __half* __restrict__ ksh,
           const float* __restrict__ tqg, const float* __restrict__ tkg,
           const __half* __restrict__ vh, const __half* __restrict__ vl,
           __half* __restrict__ ch, __half* __restrict__ cl)
{
    const int iq = 7 - (int)blockIdx.x;
    const int bh = (int)blockIdx.y;
    const long long qkbase = (long long)bh * S_ * KQS;
    const long long vgbase = (long long)bh * VROWS * S_;
    extern __shared__ __align__(16) char smem[];
    const uint32_t sbase = cvta_smem(smem);
    const uint32_t vsH = sbase + 61440u, vsL = vsH + 36992u;
    float* tks = (float*)(smem + 61440u + 2 * 36992u);
    const int tid = threadIdx.x, w = tid >> 5, lane = tid & 31;

    const __half* qh_g = qsh + qkbase + (long long)iq * 128 * KQS;
    const __half* ql_g = qsl + qkbase + (long long)iq * 128 * KQS;

    const float tq0 = tqg[(long long)bh * S_ + iq * 128 + w * 16 + (lane >> 2)];
    const float tq1 = tqg[(long long)bh * S_ + iq * 128 + w * 16 + (lane >> 2) + 8];

    float O[17][4] = {};
    float m0 = -1e30f, m1 = -1e30f, l0 = 0.f, l1 = 0.f;

    for (int j = 0; j <= iq; ++j) {
        const __half* kh_g = ksh + qkbase + (long long)j * 128 * KQS;
        // t_k for this key tile -> smem (plain store; ordered by first __syncthreads)
        if (tid < 128) tks[tid] = tkg[(long long)bh * S_ + j * 128 + tid];
        // issue chunk 0 (3 arrays), then V tile as its own group
        {
            const __half* srcs[3] = {qh_g, ql_g, kh_g};
#pragma unroll
            for (int arr = 0; arr < 3; ++arr)
#pragma unroll
                for (int t2 = 0; t2 < 2; ++t2) {
                    const int cid = tid + t2 * 256;
                    const int row = cid >> 2, seg = cid & 3;
                    CPASYNC16(sbase + arr * 10240u + (uint32_t)(row * 80 + seg * 16),
                              srcs[arr] + (long long)row * KQS + seg * 8);
                }
            CPCOMMIT();
            for (int idx = tid; idx < 2176; idx += 256) {
                const int row = idx >> 4, seg = idx & 15;
                const long long g = vgbase + (long long)row * S_ + j * 128 + seg * 8;
                CPASYNC16(vsH + (uint32_t)(row * 272 + seg * 16), vh + g);
                CPASYNC16(vsL + (uint32_t)(row * 272 + seg * 16), vl + g);
            }
            CPCOMMIT();
        }
        float acc[16][4] = {};
        for (int c = 0; c < 6; ++c) {
            if (c < 5) {
                const int s = (c + 1) & 1;
                const long long k0 = (long long)(c + 1) * 32;
                const __half* srcs[3] = {qh_g, ql_g, kh_g};
#pragma unroll
                for (int arr = 0; arr < 3; ++arr)
#pragma unroll
                    for (int t2 = 0; t2 < 2; ++t2) {
                        const int cid = tid + t2 * 256;
                        const int row = cid >> 2, seg = cid & 3;
                        CPASYNC16(sbase + (uint32_t)s * 30720u + arr * 10240u +
                                      (uint32_t)(row * 80 + seg * 16),
                                  srcs[arr] + (long long)row * KQS + k0 + seg * 8);
                    }
                CPCOMMIT();
                if (c == 0) CPWAIT(2); else CPWAIT(1);
            } else {
                CPWAIT(0);
            }
            __syncthreads();
            const uint32_t st = sbase + (uint32_t)(c & 1) * 30720u;
#pragma unroll
            for (int ks = 0; ks < 2; ++ks) {
                uint32_t ah[4], al[4];
                const uint32_t aoff =
                    (uint32_t)((w * 16 + (lane & 15)) * 80 + (ks * 16 + (lane >> 4) * 8) * 2);
                ldsm_x4(ah, st + aoff);
                ldsm_x4(al, st + 10240u + aoff);
#pragma unroll
                for (int nf = 0; nf < 16; ++nf) {
                    const uint32_t boff =
                        (uint32_t)((nf * 8 + (lane & 7)) * 80 +
                                   (ks * 16 + ((lane >> 3) & 1) * 8) * 2);
                    uint32_t kk[2];
                    ldsm_x2(kk, st + 20480u + boff);
                    mma_f16(acc[nf], ah, kk);
                    mma_f16(acc[nf], al, kk);
                }
            }
            __syncthreads();
        }
        // subtract fp32 time-component product
        {
            const int c0b = (lane & 3) * 2;
#pragma unroll
            for (int nf = 0; nf < 16; ++nf) {
                const float k0v = tks[nf * 8 + c0b], k1v = tks[nf * 8 + c0b + 1];
                acc[nf][0] -= tq0 * k0v; acc[nf][1] -= tq0 * k1v;
                acc[nf][2] -= tq1 * k0v; acc[nf][3] -= tq1 * k1v;
            }
        }
        if (j == iq) {   // diagonal tile mask
            const int rt0 = w * 16 + (lane >> 2), rt1 = rt0 + 8;
#pragma unroll
            for (int nf = 0; nf < 16; ++nf) {
                const int ct = nf * 8 + (lane & 3) * 2;
                if (ct > rt0)     acc[nf][0] = -1e30f;
                if (ct + 1 > rt0) acc[nf][1] = -1e30f;
                if (ct > rt1)     acc[nf][2] = -1e30f;
                if (ct + 1 > rt1) acc[nf][3] = -1e30f;
            }
        }
        // online softmax (quad shuffles only)
        float mx0 = -1e30f, mx1 = -1e30f;
#pragma unroll
        for (int nf = 0; nf < 16; ++nf) {
            mx0 = fmaxf(mx0, fmaxf(acc[nf][0], acc[nf][1]));
            mx1 = fmaxf(mx1, fmaxf(acc[nf][2], acc[nf][3]));
        }
        mx0 = fmaxf(mx0, __shfl_xor_sync(~0u, mx0, 1));
        mx0 = fmaxf(mx0, __shfl_xor_sync(~0u, mx0, 2));
        mx1 = fmaxf(mx1, __shfl_xor_sync(~0u, mx1, 1));
        mx1 = fmaxf(mx1, __shfl_xor_sync(~0u, mx1, 2));
        const float mn0 = fmaxf(m0, mx0), mn1 = fmaxf(m1, mx1);
        const float a0 = exp2f((m0 - mn0) * SC2), a1 = exp2f((m1 - mn1) * SC2);
        l0 *= a0; l1 *= a1;
#pragma unroll
        for (int nf = 0; nf < 17; ++nf) {
            O[nf][0] *= a0; O[nf][1] *= a0; O[nf][2] *= a1; O[nf][3] *= a1;
        }
        float s0 = 0.f, s1 = 0.f;
#pragma unroll
        for (int nf = 0; nf < 16; ++nf) {
            acc[nf][0] = exp2f((acc[nf][0] - mn0) * SC2);
            acc[nf][1] = exp2f((acc[nf][1] - mn0) * SC2);
            acc[nf][2] = exp2f((acc[nf][2] - mn1) * SC2);
            acc[nf][3] = exp2f((acc[nf][3] - mn1) * SC2);
            s0 += acc[nf][0] + acc[nf][1];
            s1 += acc[nf][2] + acc[nf][3];
        }
        s0 += __shfl_xor_sync(~0u, s0, 1); s0 += __shfl_xor_sync(~0u, s0, 2);
        s1 += __shfl_xor_sync(~0u, s1, 1); s1 += __shfl_xor_sync(~0u, s1, 2);
        l0 += s0; l1 += s1; m0 = mn0; m1 = mn1;
        // PV: P single fp16 (coherent per-key error), V 2-term fp16
#pragma unroll
        for (int kf = 0; kf < 8; ++kf) {
            uint32_t Ph[4];
            Ph[0] = packh2(acc[2 * kf][0], acc[2 * kf][1]);
            Ph[1] = packh2(acc[2 * kf][2], acc[2 * kf][3]);
            Ph[2] = packh2(acc[2 * kf + 1][0], acc[2 * kf + 1][1]);
            Ph[3] = packh2(acc[2 * kf + 1][2], acc[2 * kf + 1][3]);
#pragma unroll
            for (int nf = 0; nf < 17; ++nf) {
                const uint32_t voff =
                    (uint32_t)((nf * 8 + (lane & 7)) * 272 +
                               (kf * 16 + ((lane >> 3) & 1) * 8) * 2);
                uint32_t vh2[2], vl2[2];
                ldsm_x2(vh2, vsH + voff);
                ldsm_x2(vl2, vsL + voff);
                mma_f16(O[nf], Ph, vh2);
                mma_f16(O[nf], Ph, vl2);
            }
        }
        __syncthreads();
    }
    // epilogue: avg = O/l, Lorentz centroid normalize, write ch/cl
    const float i0 = 1.f / l0, i1 = 1.f / l1;
    float ss0 = 0.f, ss1 = 0.f;
#pragma unroll
    for (int nf = 0; nf < 17; ++nf) {
        O[nf][0] *= i0; O[nf][1] *= i0; O[nf][2] *= i1; O[nf][3] *= i1;
        ss0 += O[nf][0] * O[nf][0] + O[nf][1] * O[nf][1];
        ss1 += O[nf][2] * O[nf][2] + O[nf][3] * O[nf][3];
    }
    ss0 += __shfl_xor_sync(~0u, ss0, 1); ss0 += __shfl_xor_sync(~0u, ss0, 2);
    ss1 += __shfl_xor_sync(~0u, ss1, 1); ss1 += __shfl_xor_sync(~0u, ss1, 2);
    const float t0 = __shfl_sync(~0u, O[0][0], lane & ~3);
    const float t1 = __shfl_sync(~0u, O[0][2], lane & ~3);
    const float d0 = rsqrtf(fmaxf(fabsf(2.f * t0 * t0 - ss0), 1e-8f));
    const float d1 = rsqrtf(fmaxf(fabsf(2.f * t1 * t1 - ss1), 1e-8f));
    const int hh = bh & 15;
    const long long tok0 = (long long)(bh >> 4) * 1024 + iq * 128 + w * 16 + (lane >> 2);
    const long long o0 = tok0 * KCT + hh * 129, o1 = (tok0 + 8) * KCT + hh * 129;
#pragma unroll
    for (int nf = 0; nf < 17; ++nf) {
        const int cc = nf * 8 + (lane & 3) * 2;
        if (cc < 129) {
            hsplit(O[nf][0] * d0, ch, cl, o0 + cc);
            hsplit(O[nf][2] * d1, ch, cl, o1 + cc);
        }
        if (cc + 1 < 129) {
            hsplit(O[nf][1] * d0, ch, cl, o0 + cc + 1);
            hsplit(O[nf][3] * d1, ch, cl, o1 + cc + 1);
        }
    }
}

// ---------- elementwise ----------
__global__ void __launch_bounds__(256)
convert_split_h(const float* __restrict__ src, int lds,
                __half* __restrict__ hi, __half* __restrict__ lo, int ldd, int cols)
{
    const int r = blockIdx.y, c = blockIdx.x * 256 + threadIdx.x;
    if (c < cols) hsplit(src[(long long)r * lds + c], hi, lo, (long long)r * ldd + c);
}
__global__ void __launch_bounds__(256)
convert_h(const float* __restrict__ src, int lds,
          __half* __restrict__ hi, int ldd, int cols)
{
    const int r = blockIdx.y, c = blockIdx.x * 256 + threadIdx.x;
    if (c < cols) hi[(long long)r * ldd + c] = __float2half_rn(src[(long long)r * lds + c]);
}

__global__ void __launch_bounds__(256)
rmsnorm_kpe_kernel(const float* __restrict__ kva, const float* __restrict__ w,
                   const float* __restrict__ fc, const float* __restrict__ fs,
                   __half* __restrict__ kvnh, __half* __restrict__ kvnl,
                   float* __restrict__ kpe)
{
    const int tok = blockIdx.x, s = tok & (S_ - 1), tid = threadIdx.x;
    const float* in = kva + (size_t)tok * 576;
    __shared__ float sp[512];
    __shared__ float sh[8];
    float local = 0.f;
    for (int i = tid; i < 512; i += 256) { float v = in[i]; local += v * v; }
    float r = rsqrtf(block_sum_256(local, sh) * (1.0f / 512.f) + 1e-6f);
    float l2 = 0.f;
    for (int i = tid; i < 512; i += 256) {
        float v = in[i] * r * w[i];
        sp[i] = v;
        l2 += v * v;
    }
    float tot2 = block_sum_256(l2, sh);
    const long long ob = (long long)tok * KVN;
    if (tid == 0) hsplit(sqrtf(tot2 + 1.f), kvnh, kvnl, ob);
    for (int i = tid; i < 512; i += 256) hsplit(sp[i], kvnh, kvnl, ob + 1 + i);
    if (tid < 32) {
        float x1 = in[512 + 2 * tid], x2 = in[512 + 2 * tid + 1];
        float c = fc[s * 32 + tid], sn = fs[s * 32 + tid];
        kpe[(size_t)tok * 64 + 2 * tid]     = x1 * c - x2 * sn;
        kpe[(size_t)tok * 64 + 2 * tid + 1] = x1 * sn + x2 * c;
    }
}

__global__ void __launch_bounds__(256)
post_q_kernel(const float* __restrict__ q, const float* __restrict__ fc,
              const float* __restrict__ fs,
              __half* __restrict__ qsh, __half* __restrict__ qsl,
              float* __restrict__ tq)
{
    const int gw = (blockIdx.x * blockDim.x + threadIdx.x) >> 5, lane = threadIdx.x & 31;
    if (gw >= M_ * H_) return;
    const int h = gw % H_, tok = gw / H_, b = tok / S_, s = tok & (S_ - 1);
    const float* qr = q + ((size_t)tok * H_ + h) * 192;
    const float c = fc[s * 32 + lane], sn = fs[s * 32 + lane];
    const float x1 = qr[128 + 2 * lane], x2 = qr[128 + 2 * lane + 1];
    const float r0 = x1 * c - x2 * sn, r1 = x1 * sn + x2 * c;
    float ss = r0 * r0 + r1 * r1;
    for (int d = lane; d < 128; d += 32) { float v = qr[d]; ss += v * v; }
    ss = warp_sum(ss);
    const long long row = ((long long)b * H_ + h) * S_ + s;
    if (lane == 0) tq[row] = sqrtf(ss + 1.f);
    const long long ob = row * KQS;
    for (int d = lane; d < 128; d += 32) hsplit(qr[d], qsh, qsl, ob + d);
    hsplit(r0, qsh, qsl, ob + 128 + 2 * lane);
    hsplit(r1, qsh, qsl, ob + 128 + 2 * lane + 1);
}

__global__ void __launch_bounds__(256)
post_kv_kernel(const float* __restrict__ kv2, const float* __restrict__ kpe,
               __half* __restrict__ ksh, float* __restrict__ tk,
               __half* __restrict__ vhp, __half* __restrict__ vlp)
{
    const int gw = (blockIdx.x * blockDim.x + threadIdx.x) >> 5, lane = threadIdx.x & 31;
    if (gw >= M_ * H_) return;
    const int h = gw % H_, tok = gw / H_, b = tok / S_, s = tok & (S_ - 1);
    const float* row = kv2 + ((size_t)tok * H_ + h) * 256;
    const float* pe = kpe + (size_t)tok * 64;
    float ss = 0.f;
    for (int d = lane; d < 128; d += 32) { float v = row[d]; ss += v * v; }
    for (int d = lane; d < 64; d += 32) { float v = pe[d]; ss += v * v; }
    ss = warp_sum(ss);
    const long long krow = ((long long)b * H_ + h) * S_ + s;
    if (lane == 0) tk[krow] = sqrtf(ss + 1.f);
    const long long kb = krow * KQS;
    for (int d = lane; d < 128; d += 32) ksh[kb + d] = __float2half_rn(row[d]);
    for (int d = lane; d < 64; d += 32) ksh[kb + 128 + d] = __float2half_rn(pe[d]);
    float sv = 0.f;
    for (int d = lane; d < 128; d += 32) { float v = row[128 + d]; sv += v * v; }
    sv = warp_sum(sv);
    const long long vb = ((long long)b * H_ + h) * VROWS * S_;
    if (lane == 0) hsplit(sqrtf(sv + 1.f), vhp, vlp, vb + s);
    for (int d = lane; d < 128; d += 32)
        hsplit(row[128 + d], vhp, vlp, vb + (long long)(1 + d) * S_ + s);
}

__global__ void __launch_bounds__(256)
final_t_kernel(float* __restrict__ out)
{
    const int row = blockIdx.x, tid = threadIdx.x;
    float* p = out + (size_t)row * 2048;
    __shared__ float sh[8];
    float local = 0.f;
    for (int i = 1 + tid; i < 2048; i += 256) { float v = p[i]; local += v * v; }
    float tot = block_sum_256(local, sh);
    if (tid == 0) p[0] = sqrtf(tot + 1.f);
}

extern "C" void kernel_launch(void* const* d_in, const int* in_sizes, int n_in,
                              void* d_out, int out_size)
{
    (void)in_sizes; (void)n_in; (void)out_size;
    const float* x      = (const float*)d_in[0];
    const float* fc     = (const float*)d_in[1];
    const float* fs     = (const float*)d_in[2];
    const float* wq_w   = (const float*)d_in[4];
    const float* wq_b   = (const float*)d_in[5];
    const float* wkva_w = (const float*)d_in[6];
    const float* wkva_b = (const float*)d_in[7];
    const float* kvnw   = (const float*)d_in[8];
    const float* wkvb_w = (const float*)d_in[9];
    const float* wkvb_b = (const float*)d_in[10];
    const float* wo_w   = (const float*)d_in[11];
    const float* wo_b   = (const float*)d_in[12];
    float* out = (float*)d_out;

    float *q, *kva, *kpe, *kv2, *tq, *tk;
    cudaGetSymbolAddress((void**)&q, g_q);
    cudaGetSymbolAddress((void**)&kva, g_kva);
    cudaGetSymbolAddress((void**)&kpe, g_kpe);
    cudaGetSymbolAddress((void**)&kv2, g_kv2);
    cudaGetSymbolAddress((void**)&tq, g_tq);
    cudaGetSymbolAddress((void**)&tk, g_tk);
    __half *xh, *xl, *wqh, *wkvah, *kvnh, *kvnl, *wkvbh, *ch, *cl, *woh;
    __half *qsh, *qsl, *ksh, *vth, *vtl;
    cudaGetSymbolAddress((void**)&xh, g_xh);       cudaGetSymbolAddress((void**)&xl, g_xl);
    cudaGetSymbolAddress((void**)&wqh, g_wqh);
    cudaGetSymbolAddress((void**)&wkvah, g_wkvah);
    cudaGetSymbolAddress((void**)&kvnh, g_kvnh);   cudaGetSymbolAddress((void**)&kvnl, g_kvnl);
    cudaGetSymbolAddress((void**)&wkvbh, g_wkvbh);
    cudaGetSymbolAddress((void**)&ch, g_ch);       cudaGetSymbolAddress((void**)&cl, g_cl);
    cudaGetSymbolAddress((void**)&woh, g_woh);
    cudaGetSymbolAddress((void**)&qsh, g_qsh);     cudaGetSymbolAddress((void**)&qsl, g_qsl);
    cudaGetSymbolAddress((void**)&ksh, g_ksh);
    cudaGetSymbolAddress((void**)&vth, g_vth);     cudaGetSymbolAddress((void**)&vtl, g_vtl);

    cudaFuncSetAttribute(gemm_h2, cudaFuncAttributeMaxDynamicSharedMemorySize, (int)DSMEM_H);
    cudaFuncSetAttribute(fused_attn, cudaFuncAttributeMaxDynamicSharedMemorySize, (int)DSMEM_F);

    const dim3 blk(256);
    convert_split_h<<<dim3(8, M_), blk>>>(x, 2048, xh, xl, 2048, 2048);
    convert_h<<<dim3(8, 3072), blk>>>(wq_w, 2048, wqh, 2048, 2048);
    convert_h<<<dim3(8, 576), blk>>>(wkva_w, 2048, wkvah, 2048, 2048);
    convert_h<<<dim3(3, 4096), blk>>>(wkvb_w, 513, wkvbh, KVN, 513);
    convert_h<<<dim3(9, 2047), blk>>>(wo_w, 2064, woh, KCT, 2064);

    // Q proj: (4096x2048) @ (3072x2048)^T
    gemm_h2<<<dim3(24, 32), blk, DSMEM_H>>>(xh, xl, 2048, wqh, 2048,
                                            q, 3072, wq_b, 3072, 2048);
    // KV-A proj: (4096x2048) @ (576x2048)^T
    gemm_h2<<<dim3(5, 32), blk, DSMEM_H>>>(xh, xl, 2048, wkvah, 2048,
                                           kva, 576, wkva_b, 576, 2048);
    rmsnorm_kpe_kernel<<<M_, blk>>>(kva, kvnw, fc, fs, kvnh, kvnl, kpe);
    // KV-B proj: (4096x576) @ (4096x576)^T
    gemm_h2<<<dim3(32, 32), blk, DSMEM_H>>>(kvnh, kvnl, KVN, wkvbh, KVN,
                                            kv2, 4096, wkvb_b, 4096, KVN);
    post_q_kernel<<<(M_ * H_) / 8, blk>>>(q, fc, fs, qsh, qsl, tq);
    post_kv_kernel<<<(M_ * H_) / 8, blk>>>(kv2, kpe, ksh, tk, vth, vtl);
    fused_attn<<<dim3(8, 64), blk, DSMEM_F>>>(qsh, qsl, ksh, tq, tk, vth, vtl, ch, cl);
    // out proj: (4096x2112) @ (2047x2112)^T -> out[:,1:]
    gemm_h2<<<dim3(16, 32), blk, DSMEM_H>>>(ch, cl, KCT, woh, KCT,
                                            out + 1, 2048, wo_b, 2047, KCT);
    final_t_kernel<<<M_, blk>>>(out);
}

// round 8
// speedup vs baseline: 4.9508x; 1.3395x over previous
#include <cuda_runtime.h>
#include <cuda_fp16.h>
#include <math.h>
#include <stdint.h>

namespace {
constexpr int B_ = 4, S_ = 1024, H_ = 16;
constexpr int M_ = B_ * S_;
constexpr float SC2 = 0.14396396f * 1.44269504f;    // 2/sqrt(193) * log2(e)
constexpr int KQS = 192, KVN = 576, KCT = 2112, VROWS = 136;
constexpr size_t DSMEM_H = 2 * 2 * 10240;           // fp16 gemm: 2 stages x 2 arrays
// attn: 2 stages x 2 arrays (q,k) + V hi/lo (136x272B each) + t_k (128 f32)
constexpr size_t DSMEM_F = 40960 + 2 * 36992 + 512; // 115456
}

// fp32 scratch
__device__ float g_q[(size_t)M_ * 3072];
__device__ float g_kva[(size_t)M_ * 576];
__device__ float g_kpe[(size_t)M_ * 64];
__device__ float g_kv2[(size_t)M_ * 4096];
__device__ float g_tq[(size_t)64 * S_], g_tk[(size_t)64 * S_];
// fp16 projection operands (single-term)
__device__ __half g_xh[(size_t)M_ * 2048];
__device__ __half g_wqh[(size_t)3072 * 2048];
__device__ __half g_wkvah[(size_t)640 * 2048];
__device__ __half g_kvnh[(size_t)M_ * KVN];
__device__ __half g_wkvbh[(size_t)4096 * KVN];
__device__ __half g_ch[(size_t)M_ * KCT];
__device__ __half g_woh[(size_t)2048 * KCT];
// fp16 attention operands
__device__ __half g_qsh[(size_t)64 * S_ * KQS];
__device__ __half g_ksh[(size_t)64 * S_ * KQS];
__device__ __half g_vth[(size_t)64 * VROWS * S_], g_vtl[(size_t)64 * VROWS * S_];

__device__ __forceinline__ uint32_t cvta_smem(const void* p) {
    uint32_t a;
    asm("{ .reg .u64 t; cvta.to.shared.u64 t, %1; cvt.u32.u64 %0, t; }" : "=r"(a) : "l"(p));
    return a;
}
#define CPASYNC16(s, g) asm volatile("cp.async.cg.shared.global [%0], [%1], 16;" :: "r"(s), "l"(g) : "memory")
#define CPCOMMIT()      asm volatile("cp.async.commit_group;" ::: "memory")
#define CPWAIT(n)       asm volatile("cp.async.wait_group %0;" :: "n"(n) : "memory")

__device__ __forceinline__ void ldsm_x4(uint32_t* r, uint32_t a) {
    asm volatile("ldmatrix.sync.aligned.m8n8.x4.shared.b16 {%0,%1,%2,%3}, [%4];"
                 : "=r"(r[0]), "=r"(r[1]), "=r"(r[2]), "=r"(r[3]) : "r"(a));
}
__device__ __forceinline__ void ldsm_x2(uint32_t* r, uint32_t a) {
    asm volatile("ldmatrix.sync.aligned.m8n8.x2.shared.b16 {%0,%1}, [%2];"
                 : "=r"(r[0]), "=r"(r[1]) : "r"(a));
}
__device__ __forceinline__ void mma_f16(float* d, const uint32_t* a, const uint32_t* b) {
    asm volatile("mma.sync.aligned.m16n8k16.row.col.f32.f16.f16.f32 "
                 "{%0,%1,%2,%3}, {%4,%5,%6,%7}, {%8,%9}, {%0,%1,%2,%3};"
                 : "+f"(d[0]), "+f"(d[1]), "+f"(d[2]), "+f"(d[3])
                 : "r"(a[0]), "r"(a[1]), "r"(a[2]), "r"(a[3]), "r"(b[0]), "r"(b[1]));
}
__device__ __forceinline__ uint32_t packh2(float x, float y) {
    __half2 h = __floats2half2_rn(x, y);
    return *reinterpret_cast<uint32_t*>(&h);
}
__device__ __forceinline__ float warp_sum(float v) {
#pragma unroll
    for (int o = 16; o; o >>= 1) v += __shfl_xor_sync(0xffffffffu, v, o);
    return v;
}
__device__ __forceinline__ float block_sum_256(float v, float* sh) {
    int tid = threadIdx.x;
#pragma unroll
    for (int o = 16; o; o >>= 1) v += __shfl_xor_sync(0xffffffffu, v, o);
    __syncthreads();
    if ((tid & 31) == 0) sh[tid >> 5] = v;
    __syncthreads();
    if (tid < 32) {
        float t = (tid < 8) ? sh[tid] : 0.f;
#pragma unroll
        for (int o = 4; o; o >>= 1) t += __shfl_xor_sync(0xffffffffu, t, o);
        if (tid == 0) sh[0] = t;
    }
    __syncthreads();
    return sh[0];
}
__device__ __forceinline__ void hsplit(float v, __half* hi, __half* lo, long long i) {
    __half h = __float2half_rn(v);
    hi[i] = h;
    lo[i] = __float2half_rn(v - __half2float(h));
}

// ============ single fp16 GEMM (projections): C = A @ B^T + bias ============
__global__ void __launch_bounds__(256, 1)
gemm_h1(const __half* __restrict__ A, int lda,
        const __half* __restrict__ Bm, int ldb,
        float* __restrict__ C, int ldc,
        const float* __restrict__ bias, int Nreal, int K)
{
    const int bm = blockIdx.y * 128, bn = blockIdx.x * 128;
    const int nch = K >> 5;
    extern __shared__ __align__(16) char smem[];
    const uint32_t sbase = cvta_smem(smem);
    const int tid = threadIdx.x, wid = tid >> 5, lane = tid & 31;
    const int wm = (wid >> 2) * 64, wn = (wid & 3) * 32;

    float acc[4][4][4] = {};
    const __half* srcs[2] = {A, Bm};

    auto load_stage = [&](int s, int c) {
        const long long k0 = (long long)c * 32;
#pragma unroll
        for (int arr = 0; arr < 2; ++arr) {
            const __half* src = srcs[arr];
            const int ld = (arr == 0) ? lda : ldb;
            const int ro = (arr == 0) ? bm : bn;
            const uint32_t base = sbase + (uint32_t)s * 20480u + (uint32_t)arr * 10240u;
#pragma unroll
            for (int j = 0; j < 2; ++j) {
                const int cid = tid + j * 256;
                const int row = cid >> 2, ch = cid & 3;
                CPASYNC16(base + (uint32_t)(row * 80 + ch * 16),
                          src + (long long)(ro + row) * ld + k0 + ch * 8);
            }
        }
        CPCOMMIT();
    };

    load_stage(0, 0);
    for (int c = 0; c < nch; ++c) {
        if (c + 1 < nch) { load_stage((c + 1) & 1, c + 1); CPWAIT(1); }
        else             { CPWAIT(0); }
        __syncthreads();
        const uint32_t st = sbase + (uint32_t)(c & 1) * 20480u;
#pragma unroll
        for (int ks = 0; ks < 2; ++ks) {
            uint32_t ah[4][4], bh[4][2];
            const int arow = wm + (lane & 15);
            const int acol = ks * 16 + (lane >> 4) * 8;
#pragma unroll
            for (int mf = 0; mf < 4; ++mf)
                ldsm_x4(ah[mf], st + (uint32_t)((arow + mf * 16) * 80 + acol * 2));
            const int brow = wn + (lane & 7);
            const int bcol = ks * 16 + ((lane >> 3) & 1) * 8;
#pragma unroll
            for (int nf = 0; nf < 4; ++nf)
                ldsm_x2(bh[nf], st + 10240u + (uint32_t)((brow + nf * 8) * 80 + bcol * 2));
#pragma unroll
            for (int mf = 0; mf < 4; ++mf)
#pragma unroll
                for (int nf = 0; nf < 4; ++nf)
                    mma_f16(acc[mf][nf], ah[mf], bh[nf]);
        }
        __syncthreads();
    }
#pragma unroll
    for (int mf = 0; mf < 4; ++mf) {
        const long long r0 = bm + wm + mf * 16 + (lane >> 2);
#pragma unroll
        for (int nf = 0; nf < 4; ++nf) {
            const int col = bn + wn + nf * 8 + (lane & 3) * 2;
            const float b0 = bias ? bias[min(col, Nreal - 1)] : 0.f;
            const float b1 = bias ? bias[min(col + 1, Nreal - 1)] : 0.f;
            if (col < Nreal) {
                C[r0 * ldc + col] = acc[mf][nf][0] + b0;
                C[(r0 + 8) * ldc + col] = acc[mf][nf][2] + b0;
            }
            if (col + 1 < Nreal) {
                C[r0 * ldc + col + 1] = acc[mf][nf][1] + b1;
                C[(r0 + 8) * ldc + col + 1] = acc[mf][nf][3] + b1;
            }
        }
    }
}

// ============ fused flash-attention + Lorentz centroid ============
// spatial QK fp16 single-term; t_q*t_k exact fp32; P single fp16; V 2-term fp16.
// grid (8, 64): x -> q-block (descending), y -> (b*H + h)
__global__ void __launch_bounds__(256, 1)
fused_attn(const __half* __restrict__ qsh, const __half* __restrict__ ksh,
           const float* __restrict__ tqg, const float* __restrict__ tkg,
           const __half* __restrict__ vh, const __half* __restrict__ vl,
           __half* __restrict__ ch)
{
    const int iq = 7 - (int)blockIdx.x;
    const int bh = (int)blockIdx.y;
    const long long qkbase = (long long)bh * S_ * KQS;
    const long long vgbase = (long long)bh * VROWS * S_;
    extern __shared__ __align__(16) char smem[];
    const uint32_t sbase = cvta_smem(smem);
    const uint32_t vsH = sbase + 40960u, vsL = vsH + 36992u;
    float* tks = (float*)(smem + 40960u + 2 * 36992u);
    const int tid = threadIdx.x, w = tid >> 5, lane = tid & 31;

    const __half* qh_g = qsh + qkbase + (long long)iq * 128 * KQS;

    const float tq0 = tqg[(long long)bh * S_ + iq * 128 + w * 16 + (lane >> 2)];
    const float tq1 = tqg[(long long)bh * S_ + iq * 128 + w * 16 + (lane >> 2) + 8];

    float O[17][4] = {};
    float m0 = -1e30f, m1 = -1e30f, l0 = 0.f, l1 = 0.f;

    for (int j = 0; j <= iq; ++j) {
        const __half* kh_g = ksh + qkbase + (long long)j * 128 * KQS;
        if (tid < 128) tks[tid] = tkg[(long long)bh * S_ + j * 128 + tid];
        // chunk 0 (q,k), then V tile as its own group
        {
            const __half* srcs[2] = {qh_g, kh_g};
#pragma unroll
            for (int arr = 0; arr < 2; ++arr)
#pragma unroll
                for (int t2 = 0; t2 < 2; ++t2) {
                    const int cid = tid + t2 * 256;
                    const int row = cid >> 2, seg = cid & 3;
                    CPASYNC16(sbase + arr * 10240u + (uint32_t)(row * 80 + seg * 16),
                              srcs[arr] + (long long)row * KQS + seg * 8);
                }
            CPCOMMIT();
            for (int idx = tid; idx < 2176; idx += 256) {
                const int row = idx >> 4, seg = idx & 15;
                const long long g = vgbase + (long long)row * S_ + j * 128 + seg * 8;
                CPASYNC16(vsH + (uint32_t)(row * 272 + seg * 16), vh + g);
                CPASYNC16(vsL + (uint32_t)(row * 272 + seg * 16), vl + g);
            }
            CPCOMMIT();
        }
        float acc[16][4] = {};
        for (int c = 0; c < 6; ++c) {
            if (c < 5) {
                const int s = (c + 1) & 1;
                const long long k0 = (long long)(c + 1) * 32;
                const __half* srcs[2] = {qh_g, kh_g};
#pragma unroll
                for (int arr = 0; arr < 2; ++arr)
#pragma unroll
                    for (int t2 = 0; t2 < 2; ++t2) {
                        const int cid = tid + t2 * 256;
                        const int row = cid >> 2, seg = cid & 3;
                        CPASYNC16(sbase + (uint32_t)s * 20480u + arr * 10240u +
                                      (uint32_t)(row * 80 + seg * 16),
                                  srcs[arr] + (long long)row * KQS + k0 + seg * 8);
                    }
                CPCOMMIT();
                if (c == 0) CPWAIT(2); else CPWAIT(1);
            } else {
                CPWAIT(0);
            }
            __syncthreads();
            const uint32_t st = sbase + (uint32_t)(c & 1) * 20480u;
#pragma unroll
            for (int ks = 0; ks < 2; ++ks) {
                uint32_t ah[4];
                const uint32_t aoff =
                    (uint32_t)((w * 16 + (lane & 15)) * 80 + (ks * 16 + (lane >> 4) * 8) * 2);
                ldsm_x4(ah, st + aoff);
#pragma unroll
                for (int nf = 0; nf < 16; ++nf) {
                    const uint32_t boff =
                        (uint32_t)((nf * 8 + (lane & 7)) * 80 +
                                   (ks * 16 + ((lane >> 3) & 1) * 8) * 2);
                    uint32_t kk[2];
                    ldsm_x2(kk, st + 10240u + boff);
                    mma_f16(acc[nf], ah, kk);
                }
            }
            __syncthreads();
        }
        // subtract fp32 time-component product
        {
            const int c0b = (lane & 3) * 2;
#pragma unroll
            for (int nf = 0; nf < 16; ++nf) {
                const float k0v = tks[nf * 8 + c0b], k1v = tks[nf * 8 + c0b + 1];
                acc[nf][0] -= tq0 * k0v; acc[nf][1] -= tq0 * k1v;
                acc[nf][2] -= tq1 * k0v; acc[nf][3] -= tq1 * k1v;
            }
        }
        if (j == iq) {   // diagonal tile mask
            const int rt0 = w * 16 + (lane >> 2), rt1 = rt0 + 8;
#pragma unroll
            for (int nf = 0; nf < 16; ++nf) {
                const int ct = nf * 8 + (lane & 3) * 2;
                if (ct > rt0)     acc[nf][0] = -1e30f;
                if (ct + 1 > rt0) acc[nf][1] = -1e30f;
                if (ct > rt1)     acc[nf][2] = -1e30f;
                if (ct + 1 > rt1) acc[nf][3] = -1e30f;
            }
        }
        // online softmax
        float mx0 = -1e30f, mx1 = -1e30f;
#pragma unroll
        for (int nf = 0; nf < 16; ++nf) {
            mx0 = fmaxf(mx0, fmaxf(acc[nf][0], acc[nf][1]));
            mx1 = fmaxf(mx1, fmaxf(acc[nf][2], acc[nf][3]));
        }
        mx0 = fmaxf(mx0, __shfl_xor_sync(~0u, mx0, 1));
        mx0 = fmaxf(mx0, __shfl_xor_sync(~0u, mx0, 2));
        mx1 = fmaxf(mx1, __shfl_xor_sync(~0u, mx1, 1));
        mx1 = fmaxf(mx1, __shfl_xor_sync(~0u, mx1, 2));
        const float mn0 = fmaxf(m0, mx0), mn1 = fmaxf(m1, mx1);
        const float a0 = exp2f((m0 - mn0) * SC2), a1 = exp2f((m1 - mn1) * SC2);
        l0 *= a0; l1 *= a1;
#pragma unroll
        for (int nf = 0; nf < 17; ++nf) {
            O[nf][0] *= a0; O[nf][1] *= a0; O[nf][2] *= a1; O[nf][3] *= a1;
        }
        float s0 = 0.f, s1 = 0.f;
#pragma unroll
        for (int nf = 0; nf < 16; ++nf) {
            acc[nf][0] = exp2f((acc[nf][0] - mn0) * SC2);
            acc[nf][1] = exp2f((acc[nf][1] - mn0) * SC2);
            acc[nf][2] = exp2f((acc[nf][2] - mn1) * SC2);
            acc[nf][3] = exp2f((acc[nf][3] - mn1) * SC2);
            s0 += acc[nf][0] + acc[nf][1];
            s1 += acc[nf][2] + acc[nf][3];
        }
        s0 += __shfl_xor_sync(~0u, s0, 1); s0 += __shfl_xor_sync(~0u, s0, 2);
        s1 += __shfl_xor_sync(~0u, s1, 1); s1 += __shfl_xor_sync(~0u, s1, 2);
        l0 += s0; l1 += s1; m0 = mn0; m1 = mn1;
        // PV
#pragma unroll
        for (int kf = 0; kf < 8; ++kf) {
            uint32_t Ph[4];
            Ph[0] = packh2(acc[2 * kf][0], acc[2 * kf][1]);
            Ph[1] = packh2(acc[2 * kf][2], acc[2 * kf][3]);
            Ph[2] = packh2(acc[2 * kf + 1][0], acc[2 * kf + 1][1]);
            Ph[3] = packh2(acc[2 * kf + 1][2], acc[2 * kf + 1][3]);
#pragma unroll
            for (int nf = 0; nf < 17; ++nf) {
                const uint32_t voff =
                    (uint32_t)((nf * 8 + (lane & 7)) * 272 +
                               (kf * 16 + ((lane >> 3) & 1) * 8) * 2);
                uint32_t vh2[2], vl2[2];
                ldsm_x2(vh2, vsH + voff);
                ldsm_x2(vl2, vsL + voff);
                mma_f16(O[nf], Ph, vh2);
                mma_f16(O[nf], Ph, vl2);
            }
        }
        __syncthreads();
    }
    // epilogue: avg = O/l, Lorentz centroid normalize, write cent (single fp16)
    const float i0 = 1.f / l0, i1 = 1.f / l1;
    float ss0 = 0.f, ss1 = 0.f;
#pragma unroll
    for (int nf = 0; nf < 17; ++nf) {
        O[nf][0] *= i0; O[nf][1] *= i0; O[nf][2] *= i1; O[nf][3] *= i1;
        ss0 += O[nf][0] * O[nf][0] + O[nf][1] * O[nf][1];
        ss1 += O[nf][2] * O[nf][2] + O[nf][3] * O[nf][3];
    }
    ss0 += __shfl_xor_sync(~0u, ss0, 1); ss0 += __shfl_xor_sync(~0u, ss0, 2);
    ss1 += __shfl_xor_sync(~0u, ss1, 1); ss1 += __shfl_xor_sync(~0u, ss1, 2);
    const float t0 = __shfl_sync(~0u, O[0][0], lane & ~3);
    const float t1 = __shfl_sync(~0u, O[0][2], lane & ~3);
    const float d0 = rsqrtf(fmaxf(fabsf(2.f * t0 * t0 - ss0), 1e-8f));
    const float d1 = rsqrtf(fmaxf(fabsf(2.f * t1 * t1 - ss1), 1e-8f));
    const int hh = bh & 15;
    const long long tok0 = (long long)(bh >> 4) * 1024 + iq * 128 + w * 16 + (lane >> 2);
    const long long o0 = tok0 * KCT + hh * 129, o1 = (tok0 + 8) * KCT + hh * 129;
#pragma unroll
    for (int nf = 0; nf < 17; ++nf) {
        const int cc = nf * 8 + (lane & 3) * 2;
        if (cc < 129) {
            ch[o0 + cc] = __float2half_rn(O[nf][0] * d0);
            ch[o1 + cc] = __float2half_rn(O[nf][2] * d1);
        }
        if (cc + 1 < 129) {
            ch[o0 + cc + 1] = __float2half_rn(O[nf][1] * d0);
            ch[o1 + cc + 1] = __float2half_rn(O[nf][3] * d1);
        }
    }
}

// ---------- elementwise ----------
__global__ void __launch_bounds__(256)
convert_h(const float* __restrict__ src, int lds,
          __half* __restrict__ hi, int ldd, int cols)
{
    const int r = blockIdx.y, c = blockIdx.x * 256 + threadIdx.x;
    if (c < cols) hi[(long long)r * ldd + c] = __float2half_rn(src[(long long)r * lds + c]);
}

__global__ void __launch_bounds__(256)
rmsnorm_kpe_kernel(const float* __restrict__ kva, const float* __restrict__ w,
                   const float* __restrict__ fc, const float* __restrict__ fs,
                   __half* __restrict__ kvnh, float* __restrict__ kpe)
{
    const int tok = blockIdx.x, s = tok & (S_ - 1), tid = threadIdx.x;
    const float* in = kva + (size_t)tok * 576;
    __shared__ float sp[512];
    __shared__ float sh[8];
    float local = 0.f;
    for (int i = tid; i < 512; i += 256) { float v = in[i]; local += v * v; }
    float r = rsqrtf(block_sum_256(local, sh) * (1.0f / 512.f) + 1e-6f);
    float l2 = 0.f;
    for (int i = tid; i < 512; i += 256) {
        float v = in[i] * r * w[i];
        sp[i] = v;
        l2 += v * v;
    }
    float tot2 = block_sum_256(l2, sh);
    const long long ob = (long long)tok * KVN;
    if (tid == 0) kvnh[ob] = __float2half_rn(sqrtf(tot2 + 1.f));
    for (int i = tid; i < 512; i += 256) kvnh[ob + 1 + i] = __float2half_rn(sp[i]);
    if (tid < 32) {
        float x1 = in[512 + 2 * tid], x2 = in[512 + 2 * tid + 1];
        float c = fc[s * 32 + tid], sn = fs[s * 32 + tid];
        kpe[(size_t)tok * 64 + 2 * tid]     = x1 * c - x2 * sn;
        kpe[(size_t)tok * 64 + 2 * tid + 1] = x1 * sn + x2 * c;
    }
}

__global__ void __launch_bounds__(256)
post_q_kernel(const float* __restrict__ q, const float* __restrict__ fc,
              const float* __restrict__ fs,
              __half* __restrict__ qsh, float* __restrict__ tq)
{
    const int gw = (blockIdx.x * blockDim.x + threadIdx.x) >> 5, lane = threadIdx.x & 31;
    if (gw >= M_ * H_) return;
    const int h = gw % H_, tok = gw / H_, b = tok / S_, s = tok & (S_ - 1);
    const float* qr = q + ((size_t)tok * H_ + h) * 192;
    const float c = fc[s * 32 + lane], sn = fs[s * 32 + lane];
    const float x1 = qr[128 + 2 * lane], x2 = qr[128 + 2 * lane + 1];
    const float r0 = x1 * c - x2 * sn, r1 = x1 * sn + x2 * c;
    float ss = r0 * r0 + r1 * r1;
    for (int d = lane; d < 128; d += 32) { float v = qr[d]; ss += v * v; }
    ss = warp_sum(ss);
    const long long row = ((long long)b * H_ + h) * S_ + s;
    if (lane == 0) tq[row] = sqrtf(ss + 1.f);
    const long long ob = row * KQS;
    for (int d = lane; d < 128; d += 32) qsh[ob + d] = __float2half_rn(qr[d]);
    qsh[ob + 128 + 2 * lane]     = __float2half_rn(r0);
    qsh[ob + 128 + 2 * lane + 1] = __float2half_rn(r1);
}

__global__ void __launch_bounds__(256)
post_kv_kernel(const float* __restrict__ kv2, const float* __restrict__ kpe,
               __half* __restrict__ ksh, float* __restrict__ tk,
               __half* __restrict__ vhp, __half* __restrict__ vlp)
{
    const int gw = (blockIdx.x * blockDim.x + threadIdx.x) >> 5, lane = threadIdx.x & 31;
    if (gw >= M_ * H_) return;
    const int h = gw % H_, tok = gw / H_, b = tok / S_, s = tok & (S_ - 1);
    const float* row = kv2 + ((size_t)tok * H_ + h) * 256;
    const float* pe = kpe + (size_t)tok * 64;
    float ss = 0.f;
    for (int d = lane; d < 128; d += 32) { float v = row[d]; ss += v * v; }
    for (int d = lane; d < 64; d += 32) { float v = pe[d]; ss += v * v; }
    ss = warp_sum(ss);
    const long long krow = ((long long)b * H_ + h) * S_ + s;
    if (lane == 0) tk[krow] = sqrtf(ss + 1.f);
    const long long kb = krow * KQS;
    for (int d = lane; d < 128; d += 32) ksh[kb + d] = __float2half_rn(row[d]);
    for (int d = lane; d < 64; d += 32) ksh[kb + 128 + d] = __float2half_rn(pe[d]);
    float sv = 0.f;
    for (int d = lane; d < 128; d += 32) { float v = row[128 + d]; sv += v * v; }
    sv = warp_sum(sv);
    const long long vb = ((long long)b * H_ + h) * VROWS * S_;
    if (lane == 0) hsplit(sqrtf(sv + 1.f), vhp, vlp, vb + s);
    for (int d = lane; d < 128; d += 32)
        hsplit(row[128 + d], vhp, vlp, vb + (long long)(1 + d) * S_ + s);
}

__global__ void __launch_bounds__(256)
final_t_kernel(float* __restrict__ out)
{
    const int row = blockIdx.x, tid = threadIdx.x;
    float* p = out + (size_t)row * 2048;
    __shared__ float sh[8];
    float local = 0.f;
    for (int i = 1 + tid; i < 2048; i += 256) { float v = p[i]; local += v * v; }
    float tot = block_sum_256(local, sh);
    if (tid == 0) p[0] = sqrtf(tot + 1.f);
}

extern "C" void kernel_launch(void* const* d_in, const int* in_sizes, int n_in,
                              void* d_out, int out_size)
{
    (void)in_sizes; (void)n_in; (void)out_size;
    const float* x      = (const float*)d_in[0];
    const float* fc     = (const float*)d_in[1];
    const float* fs     = (const float*)d_in[2];
    const float* wq_w   = (const float*)d_in[4];
    const float* wq_b   = (const float*)d_in[5];
    const float* wkva_w = (const float*)d_in[6];
    const float* wkva_b = (const float*)d_in[7];
    const float* kvnw   = (const float*)d_in[8];
    const float* wkvb_w = (const float*)d_in[9];
    const float* wkvb_b = (const float*)d_in[10];
    const float* wo_w   = (const float*)d_in[11];
    const float* wo_b   = (const float*)d_in[12];
    float* out = (float*)d_out;

    float *q, *kva, *kpe, *kv2, *tq, *tk;
    cudaGetSymbolAddress((void**)&q, g_q);
    cudaGetSymbolAddress((void**)&kva, g_kva);
    cudaGetSymbolAddress((void**)&kpe, g_kpe);
    cudaGetSymbolAddress((void**)&kv2, g_kv2);
    cudaGetSymbolAddress((void**)&tq, g_tq);
    cudaGetSymbolAddress((void**)&tk, g_tk);
    __half *xh, *wqh, *wkvah, *kvnh, *wkvbh, *ch, *woh, *qsh, *ksh, *vth, *vtl;
    cudaGetSymbolAddress((void**)&xh, g_xh);
    cudaGetSymbolAddress((void**)&wqh, g_wqh);
    cudaGetSymbolAddress((void**)&wkvah, g_wkvah);
    cudaGetSymbolAddress((void**)&kvnh, g_kvnh);
    cudaGetSymbolAddress((void**)&wkvbh, g_wkvbh);
    cudaGetSymbolAddress((void**)&ch, g_ch);
    cudaGetSymbolAddress((void**)&woh, g_woh);
    cudaGetSymbolAddress((void**)&qsh, g_qsh);
    cudaGetSymbolAddress((void**)&ksh, g_ksh);
    cudaGetSymbolAddress((void**)&vth, g_vth);
    cudaGetSymbolAddress((void**)&vtl, g_vtl);

    cudaFuncSetAttribute(gemm_h1, cudaFuncAttributeMaxDynamicSharedMemorySize, (int)DSMEM_H);
    cudaFuncSetAttribute(fused_attn, cudaFuncAttributeMaxDynamicSharedMemorySize, (int)DSMEM_F);

    const dim3 blk(256);
    convert_h<<<dim3(8, M_), blk>>>(x, 2048, xh, 2048, 2048);
    convert_h<<<dim3(8, 3072), blk>>>(wq_w, 2048, wqh, 2048, 2048);
    convert_h<<<dim3(8, 576), blk>>>(wkva_w, 2048, wkvah, 2048, 2048);
    convert_h<<<dim3(3, 4096), blk>>>(wkvb_w, 513, wkvbh, KVN, 513);
    convert_h<<<dim3(9, 2047), blk>>>(wo_w, 2064, woh, KCT, 2064);

    // Q proj: (4096x2048) @ (3072x2048)^T
    gemm_h1<<<dim3(24, 32), blk, DSMEM_H>>>(xh, 2048, wqh, 2048,
                                            q, 3072, wq_b, 3072, 2048);
    // KV-A proj: (4096x2048) @ (576x2048)^T
    gemm_h1<<<dim3(5, 32), blk, DSMEM_H>>>(xh, 2048, wkvah, 2048,
                                           kva, 576, wkva_b, 576, 2048);
    rmsnorm_kpe_kernel<<<M_, blk>>>(kva, kvnw, fc, fs, kvnh, kpe);
    // KV-B proj: (4096x576) @ (4096x576)^T
    gemm_h1<<<dim3(32, 32), blk, DSMEM_H>>>(kvnh, KVN, wkvbh, KVN,
                                            kv2, 4096, wkvb_b, 4096, KVN);
    post_q_kernel<<<(M_ * H_) / 8, blk>>>(q, fc, fs, qsh, tq);
    post_kv_kernel<<<(M_ * H_) / 8, blk>>>(kv2, kpe, ksh, tk, vth, vtl);
    fused_attn<<<dim3(8, 64), blk, DSMEM_F>>>(qsh, ksh, tq, tk, vth, vtl, ch);
    // out proj: (4096x2112) @ (2047x2112)^T -> out[:,1:]
    gemm_h1<<<dim3(16, 32), blk, DSMEM_H>>>(ch, KCT, woh, KCT,
                                            out + 1, 2048, wo_b, 2047, KCT);
    final_t_kernel<<<M_, blk>>>(out);
}

// round 10
// speedup vs baseline: 6.0994x; 1.2320x over previous
#include <cuda_runtime.h>
#include <cuda_fp16.h>
#include <math.h>
#include <stdint.h>

namespace {
constexpr int B_ = 4, S_ = 1024, H_ = 16;
constexpr int M_ = B_ * S_;
constexpr float SC2 = 0.14396396f * 1.44269504f;    // 2/sqrt(193) * log2(e)
constexpr int KQS = 192, KVN = 576, KCT = 2112, VROWS = 136;
constexpr int NQA = 3712;                            // 3072 (q) + 576 (kva) + 64 pad
constexpr size_t DSMEM_H = 2 * 2 * 10240;            // fp16 gemm: 2 stages x 2 arrays
// attn: 4 K stages (4x10240) + V hi/lo (2x36992) + t_k (512)
constexpr size_t DSMEM_F = 40960 + 2 * 36992 + 512;  // 115456
}

// fp32 scratch
__device__ float g_qkva[(size_t)M_ * NQA];
__device__ float g_kpe[(size_t)M_ * 64];
__device__ float g_kv2[(size_t)M_ * 4096];
__device__ float g_tq[(size_t)64 * S_], g_tk[(size_t)64 * S_];
__device__ float g_biasqa[NQA];
// fp16 projection operands
__device__ __half g_xh[(size_t)M_ * 2048];
__device__ __half g_wqkva[(size_t)NQA * 2048];       // rows 3648..3711 stay 0
__device__ __half g_kvnh[(size_t)M_ * KVN];
__device__ __half g_wkvbh[(size_t)4096 * KVN];
__device__ __half g_ch[(size_t)M_ * KCT];
__device__ __half g_woh[(size_t)2048 * KCT];
// fp16 attention operands
__device__ __half g_qsh[(size_t)64 * S_ * KQS];
__device__ __half g_ksh[(size_t)64 * S_ * KQS];
__device__ __half g_vth[(size_t)64 * VROWS * S_], g_vtl[(size_t)64 * VROWS * S_];

__device__ __forceinline__ uint32_t cvta_smem(const void* p) {
    uint32_t a;
    asm("{ .reg .u64 t; cvta.to.shared.u64 t, %1; cvt.u32.u64 %0, t; }" : "=r"(a) : "l"(p));
    return a;
}
#define CPASYNC16(s, g) asm volatile("cp.async.cg.shared.global [%0], [%1], 16;" :: "r"(s), "l"(g) : "memory")
#define CPCOMMIT()      asm volatile("cp.async.commit_group;" ::: "memory")
#define CPWAIT(n)       asm volatile("cp.async.wait_group %0;" :: "n"(n) : "memory")

__device__ __forceinline__ void ldsm_x4(uint32_t* r, uint32_t a) {
    asm volatile("ldmatrix.sync.aligned.m8n8.x4.shared.b16 {%0,%1,%2,%3}, [%4];"
                 : "=r"(r[0]), "=r"(r[1]), "=r"(r[2]), "=r"(r[3]) : "r"(a));
}
__device__ __forceinline__ void ldsm_x2(uint32_t* r, uint32_t a) {
    asm volatile("ldmatrix.sync.aligned.m8n8.x2.shared.b16 {%0,%1}, [%2];"
                 : "=r"(r[0]), "=r"(r[1]) : "r"(a));
}
__device__ __forceinline__ void mma_f16(float* d, const uint32_t* a, const uint32_t* b) {
    asm volatile("mma.sync.aligned.m16n8k16.row.col.f32.f16.f16.f32 "
                 "{%0,%1,%2,%3}, {%4,%5,%6,%7}, {%8,%9}, {%0,%1,%2,%3};"
                 : "+f"(d[0]), "+f"(d[1]), "+f"(d[2]), "+f"(d[3])
                 : "r"(a[0]), "r"(a[1]), "r"(a[2]), "r"(a[3]), "r"(b[0]), "r"(b[1]));
}
__device__ __forceinline__ uint32_t packh2(float x, float y) {
    __half2 h = __floats2half2_rn(x, y);
    return *reinterpret_cast<uint32_t*>(&h);
}
__device__ __forceinline__ float warp_sum(float v) {
#pragma unroll
    for (int o = 16; o; o >>= 1) v += __shfl_xor_sync(0xffffffffu, v, o);
    return v;
}
__device__ __forceinline__ float block_sum_256(float v, float* sh) {
    int tid = threadIdx.x;
#pragma unroll
    for (int o = 16; o; o >>= 1) v += __shfl_xor_sync(0xffffffffu, v, o);
    __syncthreads();
    if ((tid & 31) == 0) sh[tid >> 5] = v;
    __syncthreads();
    if (tid < 32) {
        float t = (tid < 8) ? sh[tid] : 0.f;
#pragma unroll
        for (int o = 4; o; o >>= 1) t += __shfl_xor_sync(0xffffffffu, t, o);
        if (tid == 0) sh[0] = t;
    }
    __syncthreads();
    return sh[0];
}
__device__ __forceinline__ void hsplit(float v, __half* hi, __half* lo, long long i) {
    __half h = __float2half_rn(v);
    hi[i] = h;
    lo[i] = __float2half_rn(v - __half2float(h));
}

// ============ single fp16 GEMM (projections): C = A @ B^T + bias ============
__global__ void __launch_bounds__(256, 2)
gemm_h1(const __half* __restrict__ A, int lda,
        const __half* __restrict__ Bm, int ldb,
        float* __restrict__ C, int ldc,
        const float* __restrict__ bias, int Nreal, int K)
{
    const int bm = blockIdx.y * 128, bn = blockIdx.x * 128;
    const int nch = K >> 5;
    extern __shared__ __align__(16) char smem[];
    const uint32_t sbase = cvta_smem(smem);
    const int tid = threadIdx.x, wid = tid >> 5, lane = tid & 31;
    const int wm = (wid >> 2) * 64, wn = (wid & 3) * 32;

    float acc[4][4][4] = {};
    const __half* srcs[2] = {A, Bm};

    auto load_stage = [&](int s, int c) {
        const long long k0 = (long long)c * 32;
#pragma unroll
        for (int arr = 0; arr < 2; ++arr) {
            const __half* src = srcs[arr];
            const int ld = (arr == 0) ? lda : ldb;
            const int ro = (arr == 0) ? bm : bn;
            const uint32_t base = sbase + (uint32_t)s * 20480u + (uint32_t)arr * 10240u;
#pragma unroll
            for (int j = 0; j < 2; ++j) {
                const int cid = tid + j * 256;
                const int row = cid >> 2, ch = cid & 3;
                CPASYNC16(base + (uint32_t)(row * 80 + ch * 16),
                          src + (long long)(ro + row) * ld + k0 + ch * 8);
            }
        }
        CPCOMMIT();
    };

    load_stage(0, 0);
    for (int c = 0; c < nch; ++c) {
        if (c + 1 < nch) { load_stage((c + 1) & 1, c + 1); CPWAIT(1); }
        else             { CPWAIT(0); }
        __syncthreads();
        const uint32_t st = sbase + (uint32_t)(c & 1) * 20480u;
#pragma unroll
        for (int ks = 0; ks < 2; ++ks) {
            uint32_t ah[4][4], bh[4][2];
            const int arow = wm + (lane & 15);
            const int acol = ks * 16 + (lane >> 4) * 8;
#pragma unroll
            for (int mf = 0; mf < 4; ++mf)
                ldsm_x4(ah[mf], st + (uint32_t)((arow + mf * 16) * 80 + acol * 2));
            const int brow = wn + (lane & 7);
            const int bcol = ks * 16 + ((lane >> 3) & 1) * 8;
#pragma unroll
            for (int nf = 0; nf < 4; ++nf)
                ldsm_x2(bh[nf], st + 10240u + (uint32_t)((brow + nf * 8) * 80 + bcol * 2));
#pragma unroll
            for (int mf = 0; mf < 4; ++mf)
#pragma unroll
                for (int nf = 0; nf < 4; ++nf)
                    mma_f16(acc[mf][nf], ah[mf], bh[nf]);
        }
        __syncthreads();
    }
#pragma unroll
    for (int mf = 0; mf < 4; ++mf) {
        const long long r0 = bm + wm + mf * 16 + (lane >> 2);
#pragma unroll
        for (int nf = 0; nf < 4; ++nf) {
            const int col = bn + wn + nf * 8 + (lane & 3) * 2;
            const float b0 = bias ? bias[min(col, Nreal - 1)] : 0.f;
            const float b1 = bias ? bias[min(col + 1, Nreal - 1)] : 0.f;
            if (col < Nreal) {
                C[r0 * ldc + col] = acc[mf][nf][0] + b0;
                C[(r0 + 8) * ldc + col] = acc[mf][nf][2] + b0;
            }
            if (col + 1 < Nreal) {
                C[r0 * ldc + col + 1] = acc[mf][nf][1] + b1;
                C[(r0 + 8) * ldc + col + 1] = acc[mf][nf][3] + b1;
            }
        }
    }
}

// ============ fused flash-attention + Lorentz centroid ============
// Q fragments register-resident (loaded once); K 4-stage ring (up to 3 chunks
// in flight -> no overwrite race); V 2-term; t_q*t_k exact fp32.
// grid (8, 64): x -> q-block (descending), y -> (b*H+h)
__global__ void __launch_bounds__(256, 1)
fused_attn(const __half* __restrict__ qsh, const __half* __restrict__ ksh,
           const float* __restrict__ tqg, const float* __restrict__ tkg,
           const __half* __restrict__ vh, const __half* __restrict__ vl,
           __half* __restrict__ ch)
{
    const int iq = 7 - (int)blockIdx.x;
    const int bh = (int)blockIdx.y;
    const long long qkbase = (long long)bh * S_ * KQS;
    const long long vgbase = (long long)bh * VROWS * S_;
    extern __shared__ __align__(16) char smem[];
    const uint32_t sbase = cvta_smem(smem);
    const uint32_t vsH = sbase + 40960u, vsL = vsH + 36992u;
    float* tks = (float*)(smem + 40960u + 2 * 36992u);
    const int tid = threadIdx.x, w = tid >> 5, lane = tid & 31;

    const __half* qh_g = qsh + qkbase + (long long)iq * 128 * KQS;
    const float tq0 = tqg[(long long)bh * S_ + iq * 128 + w * 16 + (lane >> 2)];
    const float tq1 = tqg[(long long)bh * S_ + iq * 128 + w * 16 + (lane >> 2) + 8];

    // ---- stage Q once (into the V region, pitch 400B) and preload A-fragments ----
    uint32_t qf[12][4];
    {
        for (int idx = tid; idx < 128 * 24; idx += 256) {
            const int row = idx / 24, seg = idx % 24;
            CPASYNC16(vsH + (uint32_t)(row * 400 + seg * 16),
                      qh_g + (long long)row * KQS + seg * 8);
        }
        CPCOMMIT();
        CPWAIT(0);
        __syncthreads();
#pragma unroll
        for (int kk = 0; kk < 12; ++kk) {
            const uint32_t aoff =
                (uint32_t)((w * 16 + (lane & 15)) * 400 + (kk * 16 + (lane >> 4) * 8) * 2);
            ldsm_x4(qf[kk], vsH + aoff);
        }
        __syncthreads();   // Q region free for V
    }

    float O[17][4] = {};
    float m0 = -1e30f, m1 = -1e30f, l0 = 0.f, l1 = 0.f;

    for (int j = 0; j <= iq; ++j) {
        const __half* kh_g = ksh + qkbase + (long long)j * 128 * KQS;
        if (tid < 128) tks[tid] = tkg[(long long)bh * S_ + j * 128 + tid];
        // issue K0, K1 (own groups), then V (own group)
        auto issue_k = [&](int c) {
            const uint32_t base = sbase + (uint32_t)(c & 3) * 10240u;
            const long long k0 = (long long)c * 32;
#pragma unroll
            for (int t2 = 0; t2 < 2; ++t2) {
                const int cid = tid + t2 * 256;
                const int row = cid >> 2, seg = cid & 3;
                CPASYNC16(base + (uint32_t)(row * 80 + seg * 16),
                          kh_g + (long long)row * KQS + k0 + seg * 8);
            }
            CPCOMMIT();
        };
        issue_k(0);
        issue_k(1);
        for (int idx = tid; idx < 2176; idx += 256) {
            const int row = idx >> 4, seg = idx & 15;
            const long long g = vgbase + (long long)row * S_ + j * 128 + seg * 8;
            CPASYNC16(vsH + (uint32_t)(row * 272 + seg * 16), vh + g);
            CPASYNC16(vsL + (uint32_t)(row * 272 + seg * 16), vl + g);
        }
        CPCOMMIT();

        float acc[16][4] = {};
#pragma unroll
        for (int c = 0; c < 6; ++c) {
            if (c < 4) issue_k(c + 2);
            if (c == 0 || c == 1)      CPWAIT(3);
            else if (c == 2 || c == 3) CPWAIT(2);
            else if (c == 4)           CPWAIT(1);
            else                       CPWAIT(0);
            __syncthreads();
            const uint32_t st = sbase + (uint32_t)(c & 3) * 10240u;
#pragma unroll
            for (int ks = 0; ks < 2; ++ks) {
#pragma unroll
                for (int nf = 0; nf < 16; ++nf) {
                    const uint32_t boff =
                        (uint32_t)((nf * 8 + (lane & 7)) * 80 +
                                   (ks * 16 + ((lane >> 3) & 1) * 8) * 2);
                    uint32_t kk[2];
                    ldsm_x2(kk, st + boff);
                    mma_f16(acc[nf], qf[c * 2 + ks], kk);
                }
            }
            __syncthreads();
        }
        // subtract fp32 time-component product
        {
            const int c0b = (lane & 3) * 2;
#pragma unroll
            for (int nf = 0; nf < 16; ++nf) {
                const float k0v = tks[nf * 8 + c0b], k1v = tks[nf * 8 + c0b + 1];
                acc[nf][0] -= tq0 * k0v; acc[nf][1] -= tq0 * k1v;
                acc[nf][2] -= tq1 * k0v; acc[nf][3] -= tq1 * k1v;
            }
        }
        if (j == iq) {   // diagonal tile mask
            const int rt0 = w * 16 + (lane >> 2), rt1 = rt0 + 8;
#pragma unroll
            for (int nf = 0; nf < 16; ++nf) {
                const int ct = nf * 8 + (lane & 3) * 2;
                if (ct > rt0)     acc[nf][0] = -1e30f;
                if (ct + 1 > rt0) acc[nf][1] = -1e30f;
                if (ct > rt1)     acc[nf][2] = -1e30f;
                if (ct + 1 > rt1) acc[nf][3] = -1e30f;
            }
        }
        // online softmax (quad shuffles only)
        float mx0 = -1e30f, mx1 = -1e30f;
#pragma unroll
        for (int nf = 0; nf < 16; ++nf) {
            mx0 = fmaxf(mx0, fmaxf(acc[nf][0], acc[nf][1]));
            mx1 = fmaxf(mx1, fmaxf(acc[nf][2], acc[nf][3]));
        }
        mx0 = fmaxf(mx0, __shfl_xor_sync(~0u, mx0, 1));
        mx0 = fmaxf(mx0, __shfl_xor_sync(~0u, mx0, 2));
        mx1 = fmaxf(mx1, __shfl_xor_sync(~0u, mx1, 1));
        mx1 = fmaxf(mx1, __shfl_xor_sync(~0u, mx1, 2));
        const float mn0 = fmaxf(m0, mx0), mn1 = fmaxf(m1, mx1);
        const float a0 = exp2f((m0 - mn0) * SC2), a1 = exp2f((m1 - mn1) * SC2);
        l0 *= a0; l1 *= a1;
#pragma unroll
        for (int nf = 0; nf < 17; ++nf) {
            O[nf][0] *= a0; O[nf][1] *= a0; O[nf][2] *= a1; O[nf][3] *= a1;
        }
        float s0 = 0.f, s1 = 0.f;
#pragma unroll
        for (int nf = 0; nf < 16; ++nf) {
            acc[nf][0] = exp2f((acc[nf][0] - mn0) * SC2);
            acc[nf][1] = exp2f((acc[nf][1] - mn0) * SC2);
            acc[nf][2] = exp2f((acc[nf][2] - mn1) * SC2);
            acc[nf][3] = exp2f((acc[nf][3] - mn1) * SC2);
            s0 += acc[nf][0] + acc[nf][1];
            s1 += acc[nf][2] + acc[nf][3];
        }
        s0 += __shfl_xor_sync(~0u, s0, 1); s0 += __shfl_xor_sync(~0u, s0, 2);
        s1 += __shfl_xor_sync(~0u, s1, 1); s1 += __shfl_xor_sync(~0u, s1, 2);
        l0 += s0; l1 += s1; m0 = mn0; m1 = mn1;
        // PV: P single fp16, V 2-term fp16
#pragma unroll
        for (int kf = 0; kf < 8; ++kf) {
            uint32_t Ph[4];
            Ph[0] = packh2(acc[2 * kf][0], acc[2 * kf][1]);
            Ph[1] = packh2(acc[2 * kf][2], acc[2 * kf][3]);
            Ph[2] = packh2(acc[2 * kf + 1][0], acc[2 * kf + 1][1]);
            Ph[3] = packh2(acc[2 * kf + 1][2], acc[2 * kf + 1][3]);
#pragma unroll
            for (int nf = 0; nf < 17; ++nf) {
                const uint32_t voff =
                    (uint32_t)((nf * 8 + (lane & 7)) * 272 +
                               (kf * 16 + ((lane >> 3) & 1) * 8) * 2);
                uint32_t vh2[2], vl2[2];
                ldsm_x2(vh2, vsH + voff);
                ldsm_x2(vl2, vsL + voff);
                mma_f16(O[nf], Ph, vh2);
                mma_f16(O[nf], Ph, vl2);
            }
        }
        __syncthreads();
    }
    // epilogue: avg = O/l, Lorentz centroid normalize, write cent (fp16)
    const float i0 = 1.f / l0, i1 = 1.f / l1;
    float ss0 = 0.f, ss1 = 0.f;
#pragma unroll
    for (int nf = 0; nf < 17; ++nf) {
        O[nf][0] *= i0; O[nf][1] *= i0; O[nf][2] *= i1; O[nf][3] *= i1;
        ss0 += O[nf][0] * O[nf][0] + O[nf][1] * O[nf][1];
        ss1 += O[nf][2] * O[nf][2] + O[nf][3] * O[nf][3];
    }
    ss0 += __shfl_xor_sync(~0u, ss0, 1); ss0 += __shfl_xor_sync(~0u, ss0, 2);
    ss1 += __shfl_xor_sync(~0u, ss1, 1); ss1 += __shfl_xor_sync(~0u, ss1, 2);
    const float t0 = __shfl_sync(~0u, O[0][0], lane & ~3);
    const float t1 = __shfl_sync(~0u, O[0][2], lane & ~3);
    const float d0 = rsqrtf(fmaxf(fabsf(2.f * t0 * t0 - ss0), 1e-8f));
    const float d1 = rsqrtf(fmaxf(fabsf(2.f * t1 * t1 - ss1), 1e-8f));
    const int hh = bh & 15;
    const long long tok0 = (long long)(bh >> 4) * 1024 + iq * 128 + w * 16 + (lane >> 2);
    const long long o0 = tok0 * KCT + hh * 129, o1 = (tok0 + 8) * KCT + hh * 129;
#pragma unroll
    for (int nf = 0; nf < 17; ++nf) {
        const int cc = nf * 8 + (lane & 3) * 2;
        if (cc < 129) {
            ch[o0 + cc] = __float2half_rn(O[nf][0] * d0);
            ch[o1 + cc] = __float2half_rn(O[nf][2] * d1);
        }
        if (cc + 1 < 129) {
            ch[o0 + cc + 1] = __float2half_rn(O[nf][1] * d0);
            ch[o1 + cc + 1] = __float2half_rn(O[nf][3] * d1);
        }
    }
}

// ---------- elementwise ----------
__global__ void __launch_bounds__(256)
convert_h(const float* __restrict__ src, int lds,
          __half* __restrict__ hi, int ldd, int cols)
{
    const int r = blockIdx.y, c = blockIdx.x * 256 + threadIdx.x;
    if (c < cols) hi[(long long)r * ldd + c] = __float2half_rn(src[(long long)r * lds + c]);
}

__global__ void __launch_bounds__(256)
biascat_kernel(const float* __restrict__ a, const float* __restrict__ b,
               float* __restrict__ dst)
{
    const int i = blockIdx.x * 256 + threadIdx.x;
    if (i >= NQA) return;
    if (i < 3072) dst[i] = a[i];
    else if (i < 3648) dst[i] = b[i - 3072];
    else dst[i] = 0.f;
}

__global__ void __launch_bounds__(256)
rmsnorm_kpe_kernel(const float* __restrict__ qkva, const float* __restrict__ w,
                   const float* __restrict__ fc, const float* __restrict__ fs,
                   __half* __restrict__ kvnh, float* __restrict__ kpe)
{
    const int tok = blockIdx.x, s = tok & (S_ - 1), tid = threadIdx.x;
    const float* in = qkva + (size_t)tok * NQA + 3072;
    __shared__ float sp[512];
    __shared__ float sh[8];
    float local = 0.f;
    for (int i = tid; i < 512; i += 256) { float v = in[i]; local += v * v; }
    float r = rsqrtf(block_sum_256(local, sh) * (1.0f / 512.f) + 1e-6f);
    float l2 = 0.f;
    for (int i = tid; i < 512; i += 256) {
        float v = in[i] * r * w[i];
        sp[i] = v;
        l2 += v * v;
    }
    float tot2 = block_sum_256(l2, sh);
    const long long ob = (long long)tok * KVN;
    if (tid == 0) kvnh[ob] = __float2half_rn(sqrtf(tot2 + 1.f));
    for (int i = tid; i < 512; i += 256) kvnh[ob + 1 + i] = __float2half_rn(sp[i]);
    if (tid < 32) {
        float x1 = in[512 + 2 * tid], x2 = in[512 + 2 * tid + 1];
        float c = fc[s * 32 + tid], sn = fs[s * 32 + tid];
        kpe[(size_t)tok * 64 + 2 * tid]     = x1 * c - x2 * sn;
        kpe[(size_t)tok * 64 + 2 * tid + 1] = x1 * sn + x2 * c;
    }
}

__global__ void __launch_bounds__(256)
post_q_kernel(const float* __restrict__ qkva, const float* __restrict__ fc,
              const float* __restrict__ fs,
              __half* __restrict__ qshp, float* __restrict__ tq)
{
    const int gw = (blockIdx.x * blockDim.x + threadIdx.x) >> 5, lane = threadIdx.x & 31;
    if (gw >= M_ * H_) return;
    const int h = gw % H_, tok = gw / H_, b = tok / S_, s = tok & (S_ - 1);
    const float* qr = qkva + (size_t)tok * NQA + h * 192;
    const float c = fc[s * 32 + lane], sn = fs[s * 32 + lane];
    const float x1 = qr[128 + 2 * lane], x2 = qr[128 + 2 * lane + 1];
    const float r0 = x1 * c - x2 * sn, r1 = x1 * sn + x2 * c;
    float ss = r0 * r0 + r1 * r1;
    for (int d = lane; d < 128; d += 32) { float v = qr[d]; ss += v * v; }
    ss = warp_sum(ss);
    const long long row = ((long long)b * H_ + h) * S_ + s;
    if (lane == 0) tq[row] = sqrtf(ss + 1.f);
    const long long ob = row * KQS;
    for (int d = lane; d < 128; d += 32) qshp[ob + d] = __float2half_rn(qr[d]);
    qshp[ob + 128 + 2 * lane]     = __float2half_rn(r0);
    qshp[ob + 128 + 2 * lane + 1] = __float2half_rn(r1);
}

__global__ void __launch_bounds__(256)
post_kv_kernel(const float* __restrict__ kv2, const float* __restrict__ kpe,
               __half* __restrict__ kshp, float* __restrict__ tk,
               __half* __restrict__ vhp, __half* __restrict__ vlp)
{
    const int gw = (blockIdx.x * blockDim.x + threadIdx.x) >> 5, lane = threadIdx.x & 31;
    if (gw >= M_ * H_) return;
    const int h = gw % H_, tok = gw / H_, b = tok / S_, s = tok & (S_ - 1);
    const float* row = kv2 + ((size_t)tok * H_ + h) * 256;
    const float* pe = kpe + (size_t)tok * 64;
    float ss = 0.f;
    for (int d = lane; d < 128; d += 32) { float v = row[d]; ss += v * v; }
    for (int d = lane; d < 64; d += 32) { float v = pe[d]; ss += v * v; }
    ss = warp_sum(ss);
    const long long krow = ((long long)b * H_ + h) * S_ + s;
    if (lane == 0) tk[krow] = sqrtf(ss + 1.f);
    const long long kb = krow * KQS;
    for (int d = lane; d < 128; d += 32) kshp[kb + d] = __float2half_rn(row[d]);
    for (int d = lane; d < 64; d += 32) kshp[kb + 128 + d] = __float2half_rn(pe[d]);
    float sv = 0.f;
    for (int d = lane; d < 128; d += 32) { float v = row[128 + d]; sv += v * v; }
    sv = warp_sum(sv);
    const long long vb = ((long long)b * H_ + h) * VROWS * S_;
    if (lane == 0) hsplit(sqrtf(sv + 1.f), vhp, vlp, vb + s);
    for (int d = lane; d < 128; d += 32)
        hsplit(row[128 + d], vhp, vlp, vb + (long long)(1 + d) * S_ + s);
}

__global__ void __launch_bounds__(256)
final_t_kernel(float* __restrict__ out)
{
    const int row = blockIdx.x, tid = threadIdx.x;
    float* p = out + (size_t)row * 2048;
    __shared__ float sh[8];
    float local = 0.f;
    for (int i = 1 + tid; i < 2048; i += 256) { float v = p[i]; local += v * v; }
    float tot = block_sum_256(local, sh);
    if (tid == 0) p[0] = sqrtf(tot + 1.f);
}

extern "C" void kernel_launch(void* const* d_in, const int* in_sizes, int n_in,
                              void* d_out, int out_size)
{
    (void)in_sizes; (void)n_in; (void)out_size;
    const float* x      = (const float*)d_in[0];
    const float* fc     = (const float*)d_in[1];
    const float* fs     = (const float*)d_in[2];
    const float* wq_w   = (const float*)d_in[4];
    const float* wq_b   = (const float*)d_in[5];
    const float* wkva_w = (const float*)d_in[6];
    const float* wkva_b = (const float*)d_in[7];
    const float* kvnw   = (const float*)d_in[8];
    const float* wkvb_w = (const float*)d_in[9];
    const float* wkvb_b = (const float*)d_in[10];
    const float* wo_w   = (const float*)d_in[11];
    const float* wo_b   = (const float*)d_in[12];
    float* out = (float*)d_out;

    float *qkva, *kpe, *kv2, *tq, *tk, *biasqa;
    cudaGetSymbolAddress((void**)&qkva, g_qkva);
    cudaGetSymbolAddress((void**)&kpe, g_kpe);
    cudaGetSymbolAddress((void**)&kv2, g_kv2);
    cudaGetSymbolAddress((void**)&tq, g_tq);
    cudaGetSymbolAddress((void**)&tk, g_tk);
    cudaGetSymbolAddress((void**)&biasqa, g_biasqa);
    __half *xh, *wqkva, *kvnh, *wkvbh, *ch, *woh, *qsh, *ksh, *vth, *vtl;
    cudaGetSymbolAddress((void**)&xh, g_xh);
    cudaGetSymbolAddress((void**)&wqkva, g_wqkva);
    cudaGetSymbolAddress((void**)&kvnh, g_kvnh);
    cudaGetSymbolAddress((void**)&wkvbh, g_wkvbh);
    cudaGetSymbolAddress((void**)&ch, g_ch);
    cudaGetSymbolAddress((void**)&woh, g_woh);
    cudaGetSymbolAddress((void**)&qsh, g_qsh);
    cudaGetSymbolAddress((void**)&ksh, g_ksh);
    cudaGetSymbolAddress((void**)&vth, g_vth);
    cudaGetSymbolAddress((void**)&vtl, g_vtl);

    cudaFuncSetAttribute(gemm_h1, cudaFuncAttributeMaxDynamicSharedMemorySize, (int)DSMEM_H);
    cudaFuncSetAttribute(fused_attn, cudaFuncAttributeMaxDynamicSharedMemorySize, (int)DSMEM_F);

    const dim3 blk(256);
    convert_h<<<dim3(8, M_), blk>>>(x, 2048, xh, 2048, 2048);
    convert_h<<<dim3(8, 3072), blk>>>(wq_w, 2048, wqkva, 2048, 2048);
    convert_h<<<dim3(8, 576), blk>>>(wkva_w, 2048, wqkva + (size_t)3072 * 2048, 2048, 2048);
    convert_h<<<dim3(3, 4096), blk>>>(wkvb_w, 513, wkvbh, KVN, 513);
    convert_h<<<dim3(9, 2047), blk>>>(wo_w, 2064, woh, KCT, 2064);
    biascat_kernel<<<15, blk>>>(wq_b, wkva_b, biasqa);

    // fused Q + KV-A projection: (4096x2048) @ (3712x2048)^T
    gemm_h1<<<dim3(29, 32), blk, DSMEM_H>>>(xh, 2048, wqkva, 2048,
                                            qkva, NQA, biasqa, 3648, 2048);
    rmsnorm_kpe_kernel<<<M_, blk>>>(qkva, kvnw, fc, fs, kvnh, kpe);
    // KV-B proj: (4096x576) @ (4096x576)^T
    gemm_h1<<<dim3(32, 32), blk, DSMEM_H>>>(kvnh, KVN, wkvbh, KVN,
                                            kv2, 4096, wkvb_b, 4096, KVN);
    post_q_kernel<<<(M_ * H_) / 8, blk>>>(qkva, fc, fs, qsh, tq);
    post_kv_kernel<<<(M_ * H_) / 8, blk>>>(kv2, kpe, ksh, tk, vth, vtl);
    fused_attn<<<dim3(8, 64), blk, DSMEM_F>>>(qsh, ksh, tq, tk, vth, vtl, ch);
    // out proj: (4096x2112) @ (2047x2112)^T -> out[:,1:]
    gemm_h1<<<dim3(16, 32), blk, DSMEM_H>>>(ch, KCT, woh, KCT,
                                            out + 1, 2048, wo_b, 2047, KCT);
    final_t_kernel<<<M_, blk>>>(out);
}

// round 12
// speedup vs baseline: 7.4865x; 1.2274x over previous
#include <cuda_runtime.h>
#include <cuda_fp16.h>
#include <math.h>
#include <stdint.h>

namespace {
constexpr int B_ = 4, S_ = 1024, H_ = 16;
constexpr int M_ = B_ * S_;
constexpr float SC2 = 0.14396396f * 1.44269504f;    // 2/sqrt(193) * log2(e)
constexpr int KQS = 192, KVN = 576, KCT = 2112, VDIM = 136;
constexpr int NQA = 3712;                            // 3072 (q) + 576 (kva) + 64 pad
constexpr size_t DSMEM_H = 2 * 2 * 10240;            // fp16 gemm: 2 stages x 2 arrays
// attn: 4 K stages (4x10240) + V hi/lo (2 x 128x272B) + t_k (512)
constexpr size_t DSMEM_F = 40960 + 2 * 34816 + 512;  // 111104
}

// fp32 scratch
__device__ float g_qkva[(size_t)M_ * NQA];
__device__ float g_kpe[(size_t)M_ * 64];
__device__ float g_kv2[(size_t)M_ * 4096];
__device__ float g_tq[(size_t)64 * S_], g_tk[(size_t)64 * S_];
__device__ float g_biasqa[NQA];
// fp16 projection operands
__device__ __half g_xh[(size_t)M_ * 2048];
__device__ __half g_wqkva[(size_t)NQA * 2048];       // rows 3648..3711 stay 0
__device__ __half g_kvnh[(size_t)M_ * KVN];
__device__ __half g_wkvbh[(size_t)4096 * KVN];
__device__ __half g_ch[(size_t)M_ * KCT];
__device__ __half g_woh[(size_t)2048 * KCT];
// fp16 attention operands (V natural token-major: [bh][s][136], dims 129..135 stay 0)
__device__ __half g_qsh[(size_t)64 * S_ * KQS];
__device__ __half g_ksh[(size_t)64 * S_ * KQS];
__device__ __half g_vth[(size_t)64 * S_ * VDIM], g_vtl[(size_t)64 * S_ * VDIM];

__device__ __forceinline__ uint32_t cvta_smem(const void* p) {
    uint32_t a;
    asm("{ .reg .u64 t; cvta.to.shared.u64 t, %1; cvt.u32.u64 %0, t; }" : "=r"(a) : "l"(p));
    return a;
}
#define CPASYNC16(s, g) asm volatile("cp.async.cg.shared.global [%0], [%1], 16;" :: "r"(s), "l"(g) : "memory")
#define CPCOMMIT()      asm volatile("cp.async.commit_group;" ::: "memory")
#define CPWAIT(n)       asm volatile("cp.async.wait_group %0;" :: "n"(n) : "memory")

__device__ __forceinline__ void ldsm_x4(uint32_t* r, uint32_t a) {
    asm volatile("ldmatrix.sync.aligned.m8n8.x4.shared.b16 {%0,%1,%2,%3}, [%4];"
                 : "=r"(r[0]), "=r"(r[1]), "=r"(r[2]), "=r"(r[3]) : "r"(a));
}
__device__ __forceinline__ void ldsm_x2(uint32_t* r, uint32_t a) {
    asm volatile("ldmatrix.sync.aligned.m8n8.x2.shared.b16 {%0,%1}, [%2];"
                 : "=r"(r[0]), "=r"(r[1]) : "r"(a));
}
__device__ __forceinline__ void ldsm_x2t(uint32_t* r, uint32_t a) {
    asm volatile("ldmatrix.sync.aligned.m8n8.x2.trans.shared.b16 {%0,%1}, [%2];"
                 : "=r"(r[0]), "=r"(r[1]) : "r"(a));
}
__device__ __forceinline__ void mma_f16(float* d, const uint32_t* a, const uint32_t* b) {
    asm volatile("mma.sync.aligned.m16n8k16.row.col.f32.f16.f16.f32 "
                 "{%0,%1,%2,%3}, {%4,%5,%6,%7}, {%8,%9}, {%0,%1,%2,%3};"
                 : "+f"(d[0]), "+f"(d[1]), "+f"(d[2]), "+f"(d[3])
                 : "r"(a[0]), "r"(a[1]), "r"(a[2]), "r"(a[3]), "r"(b[0]), "r"(b[1]));
}
__device__ __forceinline__ uint32_t packh2(float x, float y) {
    __half2 h = __floats2half2_rn(x, y);
    return *reinterpret_cast<uint32_t*>(&h);
}
__device__ __forceinline__ float warp_sum(float v) {
#pragma unroll
    for (int o = 16; o; o >>= 1) v += __shfl_xor_sync(0xffffffffu, v, o);
    return v;
}
__device__ __forceinline__ float block_sum_256(float v, float* sh) {
    int tid = threadIdx.x;
#pragma unroll
    for (int o = 16; o; o >>= 1) v += __shfl_xor_sync(0xffffffffu, v, o);
    __syncthreads();
    if ((tid & 31) == 0) sh[tid >> 5] = v;
    __syncthreads();
    if (tid < 32) {
        float t = (tid < 8) ? sh[tid] : 0.f;
#pragma unroll
        for (int o = 4; o; o >>= 1) t += __shfl_xor_sync(0xffffffffu, t, o);
        if (tid == 0) sh[0] = t;
    }
    __syncthreads();
    return sh[0];
}
__device__ __forceinline__ void hsplit(float v, __half* hi, __half* lo, long long i) {
    __half h = __float2half_rn(v);
    hi[i] = h;
    lo[i] = __float2half_rn(v - __half2float(h));
}
__device__ __forceinline__ uint2 pack4(float4 v) {
    __half2 a = __floats2half2_rn(v.x, v.y);
    __half2 b = __floats2half2_rn(v.z, v.w);
    uint2 o;
    o.x = *reinterpret_cast<uint32_t*>(&a);
    o.y = *reinterpret_cast<uint32_t*>(&b);
    return o;
}

// ============ single fp16 GEMM (projections): C = A @ B^T + bias ============
__global__ void __launch_bounds__(256, 2)
gemm_h1(const __half* __restrict__ A, int lda,
        const __half* __restrict__ Bm, int ldb,
        float* __restrict__ C, int ldc,
        const float* __restrict__ bias, int Nreal, int K)
{
    const int bm = blockIdx.y * 128, bn = blockIdx.x * 128;
    const int nch = K >> 5;
    extern __shared__ __align__(16) char smem[];
    const uint32_t sbase = cvta_smem(smem);
    const int tid = threadIdx.x, wid = tid >> 5, lane = tid & 31;
    const int wm = (wid >> 2) * 64, wn = (wid & 3) * 32;

    float acc[4][4][4] = {};
    const __half* srcs[2] = {A, Bm};

    auto load_stage = [&](int s, int c) {
        const long long k0 = (long long)c * 32;
#pragma unroll
        for (int arr = 0; arr < 2; ++arr) {
            const __half* src = srcs[arr];
            const int ld = (arr == 0) ? lda : ldb;
            const int ro = (arr == 0) ? bm : bn;
            const uint32_t base = sbase + (uint32_t)s * 20480u + (uint32_t)arr * 10240u;
#pragma unroll
            for (int j = 0; j < 2; ++j) {
                const int cid = tid + j * 256;
                const int row = cid >> 2, ch = cid & 3;
                CPASYNC16(base + (uint32_t)(row * 80 + ch * 16),
                          src + (long long)(ro + row) * ld + k0 + ch * 8);
            }
        }
        CPCOMMIT();
    };

    load_stage(0, 0);
    for (int c = 0; c < nch; ++c) {
        if (c + 1 < nch) { load_stage((c + 1) & 1, c + 1); CPWAIT(1); }
        else             { CPWAIT(0); }
        __syncthreads();
        const uint32_t st = sbase + (uint32_t)(c & 1) * 20480u;
#pragma unroll
        for (int ks = 0; ks < 2; ++ks) {
            uint32_t ah[4][4], bh[4][2];
            const int arow = wm + (lane & 15);
            const int acol = ks * 16 + (lane >> 4) * 8;
#pragma unroll
            for (int mf = 0; mf < 4; ++mf)
                ldsm_x4(ah[mf], st + (uint32_t)((arow + mf * 16) * 80 + acol * 2));
            const int brow = wn + (lane & 7);
            const int bcol = ks * 16 + ((lane >> 3) & 1) * 8;
#pragma unroll
            for (int nf = 0; nf < 4; ++nf)
                ldsm_x2(bh[nf], st + 10240u + (uint32_t)((brow + nf * 8) * 80 + bcol * 2));
#pragma unroll
            for (int mf = 0; mf < 4; ++mf)
#pragma unroll
                for (int nf = 0; nf < 4; ++nf)
                    mma_f16(acc[mf][nf], ah[mf], bh[nf]);
        }
        __syncthreads();
    }
#pragma unroll
    for (int mf = 0; mf < 4; ++mf) {
        const long long r0 = bm + wm + mf * 16 + (lane >> 2);
#pragma unroll
        for (int nf = 0; nf < 4; ++nf) {
            const int col = bn + wn + nf * 8 + (lane & 3) * 2;
            const float b0 = bias ? bias[min(col, Nreal - 1)] : 0.f;
            const float b1 = bias ? bias[min(col + 1, Nreal - 1)] : 0.f;
            if (col < Nreal) {
                C[r0 * ldc + col] = acc[mf][nf][0] + b0;
                C[(r0 + 8) * ldc + col] = acc[mf][nf][2] + b0;
            }
            if (col + 1 < Nreal) {
                C[r0 * ldc + col + 1] = acc[mf][nf][1] + b1;
                C[(r0 + 8) * ldc + col + 1] = acc[mf][nf][3] + b1;
            }
        }
    }
}

// ============ fused flash-attention + Lorentz centroid ============
// Q fragments register-resident; K 4-stage ring; V natural layout + ldmatrix.trans;
// t_q*t_k exact fp32. grid (8, 64): x -> q-block (descending), y -> (b*H+h)
__global__ void __launch_bounds__(256, 1)
fused_attn(const __half* __restrict__ qsh, const __half* __restrict__ ksh,
           const float* __restrict__ tqg, const float* __restrict__ tkg,
           const __half* __restrict__ vh, const __half* __restrict__ vl,
           __half* __restrict__ ch)
{
    const int iq = 7 - (int)blockIdx.x;
    const int bh = (int)blockIdx.y;
    const long long qkbase = (long long)bh * S_ * KQS;
    const long long vgbase = (long long)bh * S_ * VDIM;
    extern __shared__ __align__(16) char smem[];
    const uint32_t sbase = cvta_smem(smem);
    const uint32_t vsH = sbase + 40960u, vsL = vsH + 34816u;
    float* tks = (float*)(smem + 40960u + 2 * 34816u);
    const int tid = threadIdx.x, w = tid >> 5, lane = tid & 31;

    const __half* qh_g = qsh + qkbase + (long long)iq * 128 * KQS;
    const float tq0 = tqg[(long long)bh * S_ + iq * 128 + w * 16 + (lane >> 2)];
    const float tq1 = tqg[(long long)bh * S_ + iq * 128 + w * 16 + (lane >> 2) + 8];

    // ---- stage Q once (into the V region, pitch 400B) and preload A-fragments ----
    uint32_t qf[12][4];
    {
        for (int idx = tid; idx < 128 * 24; idx += 256) {
            const int row = idx / 24, seg = idx % 24;
            CPASYNC16(vsH + (uint32_t)(row * 400 + seg * 16),
                      qh_g + (long long)row * KQS + seg * 8);
        }
        CPCOMMIT();
        CPWAIT(0);
        __syncthreads();
#pragma unroll
        for (int kk = 0; kk < 12; ++kk) {
            const uint32_t aoff =
                (uint32_t)((w * 16 + (lane & 15)) * 400 + (kk * 16 + (lane >> 4) * 8) * 2);
            ldsm_x4(qf[kk], vsH + aoff);
        }
        __syncthreads();   // Q region free for V
    }

    float O[17][4] = {};
    float m0 = -1e30f, m1 = -1e30f, l0 = 0.f, l1 = 0.f;

    for (int j = 0; j <= iq; ++j) {
        const __half* kh_g = ksh + qkbase + (long long)j * 128 * KQS;
        if (tid < 128) tks[tid] = tkg[(long long)bh * S_ + j * 128 + tid];
        auto issue_k = [&](int c) {
            const uint32_t base = sbase + (uint32_t)(c & 3) * 10240u;
            const long long k0 = (long long)c * 32;
#pragma unroll
            for (int t2 = 0; t2 < 2; ++t2) {
                const int cid = tid + t2 * 256;
                const int row = cid >> 2, seg = cid & 3;
                CPASYNC16(base + (uint32_t)(row * 80 + seg * 16),
                          kh_g + (long long)row * KQS + k0 + seg * 8);
            }
            CPCOMMIT();
        };
        issue_k(0);
        issue_k(1);
        // V tile: 128 token rows x 17 segs of 16B (natural layout)
        for (int idx = tid; idx < 2176; idx += 256) {
            const int row = idx / 17, seg = idx % 17;
            const long long g = vgbase + (long long)(j * 128 + row) * VDIM + seg * 8;
            CPASYNC16(vsH + (uint32_t)(row * 272 + seg * 16), vh + g);
            CPASYNC16(vsL + (uint32_t)(row * 272 + seg * 16), vl + g);
        }
        CPCOMMIT();

        float acc[16][4] = {};
#pragma unroll
        for (int c = 0; c < 6; ++c) {
            if (c < 4) issue_k(c + 2);
            if (c == 0 || c == 1)      CPWAIT(3);
            else if (c == 2 || c == 3) CPWAIT(2);
            else if (c == 4)           CPWAIT(1);
            else                       CPWAIT(0);
            __syncthreads();
            const uint32_t st = sbase + (uint32_t)(c & 3) * 10240u;
#pragma unroll
            for (int ks = 0; ks < 2; ++ks) {
#pragma unroll
                for (int nf = 0; nf < 16; ++nf) {
                    const uint32_t boff =
                        (uint32_t)((nf * 8 + (lane & 7)) * 80 +
                                   (ks * 16 + ((lane >> 3) & 1) * 8) * 2);
                    uint32_t kk[2];
                    ldsm_x2(kk, st + boff);
                    mma_f16(acc[nf], qf[c * 2 + ks], kk);
                }
            }
            __syncthreads();
        }
        // subtract fp32 time-component product
        {
            const int c0b = (lane & 3) * 2;
#pragma unroll
            for (int nf = 0; nf < 16; ++nf) {
                const float k0v = tks[nf * 8 + c0b], k1v = tks[nf * 8 + c0b + 1];
                acc[nf][0] -= tq0 * k0v; acc[nf][1] -= tq0 * k1v;
                acc[nf][2] -= tq1 * k0v; acc[nf][3] -= tq1 * k1v;
            }
        }
        if (j == iq) {   // diagonal tile mask
            const int rt0 = w * 16 + (lane >> 2), rt1 = rt0 + 8;
#pragma unroll
            for (int nf = 0; nf < 16; ++nf) {
                const int ct = nf * 8 + (lane & 3) * 2;
                if (ct > rt0)     acc[nf][0] = -1e30f;
                if (ct + 1 > rt0) acc[nf][1] = -1e30f;
                if (ct > rt1)     acc[nf][2] = -1e30f;
                if (ct + 1 > rt1) acc[nf][3] = -1e30f;
            }
        }
        // online softmax (quad shuffles only)
        float mx0 = -1e30f, mx1 = -1e30f;
#pragma unroll
        for (int nf = 0; nf < 16; ++nf) {
            mx0 = fmaxf(mx0, fmaxf(acc[nf][0], acc[nf][1]));
            mx1 = fmaxf(mx1, fmaxf(acc[nf][2], acc[nf][3]));
        }
        mx0 = fmaxf(mx0, __shfl_xor_sync(~0u, mx0, 1));
        mx0 = fmaxf(mx0, __shfl_xor_sync(~0u, mx0, 2));
        mx1 = fmaxf(mx1, __shfl_xor_sync(~0u, mx1, 1));
        mx1 = fmaxf(mx1, __shfl_xor_sync(~0u, mx1, 2));
        const float mn0 = fmaxf(m0, mx0), mn1 = fmaxf(m1, mx1);
        const float a0 = exp2f((m0 - mn0) * SC2), a1 = exp2f((m1 - mn1) * SC2);
        l0 *= a0; l1 *= a1;
#pragma unroll
        for (int nf = 0; nf < 17; ++nf) {
            O[nf][0] *= a0; O[nf][1] *= a0; O[nf][2] *= a1; O[nf][3] *= a1;
        }
        float s0 = 0.f, s1 = 0.f;
#pragma unroll
        for (int nf = 0; nf < 16; ++nf) {
            acc[nf][0] = exp2f((acc[nf][0] - mn0) * SC2);
            acc[nf][1] = exp2f((acc[nf][1] - mn0) * SC2);
            acc[nf][2] = exp2f((acc[nf][2] - mn1) * SC2);
            acc[nf][3] = exp2f((acc[nf][3] - mn1) * SC2);
            s0 += acc[nf][0] + acc[nf][1];
            s1 += acc[nf][2] + acc[nf][3];
        }
        s0 += __shfl_xor_sync(~0u, s0, 1); s0 += __shfl_xor_sync(~0u, s0, 2);
        s1 += __shfl_xor_sync(~0u, s1, 1); s1 += __shfl_xor_sync(~0u, s1, 2);
        l0 += s0; l1 += s1; m0 = mn0; m1 = mn1;
        // PV: P single fp16, V 2-term fp16, B fragments via ldmatrix.trans
#pragma unroll
        for (int kf = 0; kf < 8; ++kf) {
            uint32_t Ph[4];
            Ph[0] = packh2(acc[2 * kf][0], acc[2 * kf][1]);
            Ph[1] = packh2(acc[2 * kf][2], acc[2 * kf][3]);
            Ph[2] = packh2(acc[2 * kf + 1][0], acc[2 * kf + 1][1]);
            Ph[3] = packh2(acc[2 * kf + 1][2], acc[2 * kf + 1][3]);
            const uint32_t vrow = (uint32_t)((kf * 16 + (lane & 15)) * 272);
#pragma unroll
            for (int nf = 0; nf < 17; ++nf) {
                uint32_t vh2[2], vl2[2];
                ldsm_x2t(vh2, vsH + vrow + (uint32_t)(nf * 16));
                ldsm_x2t(vl2, vsL + vrow + (uint32_t)(nf * 16));
                mma_f16(O[nf], Ph, vh2);
                mma_f16(O[nf], Ph, vl2);
            }
        }
        __syncthreads();
    }
    // epilogue: avg = O/l, Lorentz centroid normalize, write cent (fp16)
    const float i0 = 1.f / l0, i1 = 1.f / l1;
    float ss0 = 0.f, ss1 = 0.f;
#pragma unroll
    for (int nf = 0; nf < 17; ++nf) {
        O[nf][0] *= i0; O[nf][1] *= i0; O[nf][2] *= i1; O[nf][3] *= i1;
        ss0 += O[nf][0] * O[nf][0] + O[nf][1] * O[nf][1];
        ss1 += O[nf][2] * O[nf][2] + O[nf][3] * O[nf][3];
    }
    ss0 += __shfl_xor_sync(~0u, ss0, 1); ss0 += __shfl_xor_sync(~0u, ss0, 2);
    ss1 += __shfl_xor_sync(~0u, ss1, 1); ss1 += __shfl_xor_sync(~0u, ss1, 2);
    const float t0 = __shfl_sync(~0u, O[0][0], lane & ~3);
    const float t1 = __shfl_sync(~0u, O[0][2], lane & ~3);
    const float d0 = rsqrtf(fmaxf(fabsf(2.f * t0 * t0 - ss0), 1e-8f));
    const float d1 = rsqrtf(fmaxf(fabsf(2.f * t1 * t1 - ss1), 1e-8f));
    const int hh = bh & 15;
    const long long tok0 = (long long)(bh >> 4) * 1024 + iq * 128 + w * 16 + (lane >> 2);
    const long long o0 = tok0 * KCT + hh * 129, o1 = (tok0 + 8) * KCT + hh * 129;
#pragma unroll
    for (int nf = 0; nf < 17; ++nf) {
        const int cc = nf * 8 + (lane & 3) * 2;
        if (cc < 129) {
            ch[o0 + cc] = __float2half_rn(O[nf][0] * d0);
            ch[o1 + cc] = __float2half_rn(O[nf][2] * d1);
        }
        if (cc + 1 < 129) {
            ch[o0 + cc + 1] = __float2half_rn(O[nf][1] * d0);
            ch[o1 + cc + 1] = __float2half_rn(O[nf][3] * d1);
        }
    }
}

// ---------- elementwise (vectorized) ----------
__global__ void __launch_bounds__(256)
convert_h4_1d(const float4* __restrict__ src, uint2* __restrict__ dst, int n4)
{
    const int i = blockIdx.x * 256 + threadIdx.x;
    if (i < n4) dst[i] = pack4(src[i]);
}

// scalar 32-bit loads (no alignment requirement on odd lds), vector 8B store
__global__ void __launch_bounds__(256)
convert_h4_2d(const float* __restrict__ src, int lds,
              __half* __restrict__ dst, int ldd, int cols)
{
    const int r = blockIdx.y;
    const int c4 = blockIdx.x * 256 + threadIdx.x;
    const int cols4 = cols >> 2;
    if (c4 < cols4) {
        const float* p = src + (long long)r * lds + c4 * 4;
        float4 v;
        v.x = p[0]; v.y = p[1]; v.z = p[2]; v.w = p[3];
        *(uint2*)(dst + (long long)r * ldd + c4 * 4) = pack4(v);
    } else if (c4 < cols4 + (cols & 3)) {
        const int c = cols4 * 4 + (c4 - cols4);
        dst[(long long)r * ldd + c] = __float2half_rn(src[(long long)r * lds + c]);
    }
}

__global__ void __launch_bounds__(256)
biascat_kernel(const float* __restrict__ a, const float* __restrict__ b,
               float* __restrict__ dst)
{
    const int i = blockIdx.x * 256 + threadIdx.x;
    if (i >= NQA) return;
    if (i < 3072) dst[i] = a[i];
    else if (i < 3648) dst[i] = b[i - 3072];
    else dst[i] = 0.f;
}

__global__ void __launch_bounds__(256)
rmsnorm_kpe_kernel(const float* __restrict__ qkva, const float* __restrict__ w,
                   const float* __restrict__ fc, const float* __restrict__ fs,
                   __half* __restrict__ kvnh, float* __restrict__ kpe)
{
    const int tok = blockIdx.x, s = tok & (S_ - 1), tid = threadIdx.x;
    const float* in = qkva + (size_t)tok * NQA + 3072;
    __shared__ float sp[512];
    __shared__ float sh[8];
    float local = 0.f;
    for (int i = tid; i < 512; i += 256) { float v = in[i]; local += v * v; }
    float r = rsqrtf(block_sum_256(local, sh) * (1.0f / 512.f) + 1e-6f);
    float l2 = 0.f;
    for (int i = tid; i < 512; i += 256) {
        float v = in[i] * r * w[i];
        sp[i] = v;
        l2 += v * v;
    }
    float tot2 = block_sum_256(l2, sh);
    const long long ob = (long long)tok * KVN;
    if (tid == 0) kvnh[ob] = __float2half_rn(sqrtf(tot2 + 1.f));
    for (int i = tid; i < 512; i += 256) kvnh[ob + 1 + i] = __float2half_rn(sp[i]);
    if (tid < 32) {
        float x1 = in[512 + 2 * tid], x2 = in[512 + 2 * tid + 1];
        float c = fc[s * 32 + tid], sn = fs[s * 32 + tid];
        kpe[(size_t)tok * 64 + 2 * tid]     = x1 * c - x2 * sn;
        kpe[(size_t)tok * 64 + 2 * tid + 1] = x1 * sn + x2 * c;
    }
}

__global__ void __launch_bounds__(256)
post_q_kernel(const float* __restrict__ qkva, const float* __restrict__ fc,
              const float* __restrict__ fs,
              __half* __restrict__ qshp, float* __restrict__ tq)
{
    const int gw = (blockIdx.x * blockDim.x + threadIdx.x) >> 5, lane = threadIdx.x & 31;
    if (gw >= M_ * H_) return;
    const int h = gw % H_, tok = gw / H_, b = tok / S_, s = tok & (S_ - 1);
    const float* qr = qkva + (size_t)tok * NQA + h * 192;
    const float4 qv = *(const float4*)(qr + lane * 4);
    const float c = fc[s * 32 + lane], sn = fs[s * 32 + lane];
    const float x1 = qr[128 + 2 * lane], x2 = qr[128 + 2 * lane + 1];
    const float r0 = x1 * c - x2 * sn, r1 = x1 * sn + x2 * c;
    float ss = r0 * r0 + r1 * r1 + qv.x * qv.x + qv.y * qv.y + qv.z * qv.z + qv.w * qv.w;
    ss = warp_sum(ss);
    const long long row = ((long long)b * H_ + h) * S_ + s;
    if (lane == 0) tq[row] = sqrtf(ss + 1.f);
    const long long ob = row * KQS;
    *(uint2*)(qshp + ob + lane * 4) = pack4(qv);
    *(__half2*)(qshp + ob + 128 + 2 * lane) = __floats2half2_rn(r0, r1);
}

__global__ void __launch_bounds__(256)
post_kv_kernel(const float* __restrict__ kv2, const float* __restrict__ kpe,
               __half* __restrict__ kshp, float* __restrict__ tk,
               __half* __restrict__ vhp, __half* __restrict__ vlp)
{
    const int gw = (blockIdx.x * blockDim.x + threadIdx.x) >> 5, lane = threadIdx.x & 31;
    if (gw >= M_ * H_) return;
    const int h = gw % H_, tok = gw / H_, b = tok / S_, s = tok & (S_ - 1);
    const float* row = kv2 + ((size_t)tok * H_ + h) * 256;
    const float* pe = kpe + (size_t)tok * 64;
    const float4 kn = *(const float4*)(row + lane * 4);
    const float2 pp = *(const float2*)(pe + lane * 2);
    float ss = kn.x * kn.x + kn.y * kn.y + kn.z * kn.z + kn.w * kn.w + pp.x * pp.x + pp.y * pp.y;
    ss = warp_sum(ss);
    const long long krow = ((long long)b * H_ + h) * S_ + s;
    if (lane == 0) tk[krow] = sqrtf(ss + 1.f);
    const long long kb = krow * KQS;
    *(uint2*)(kshp + kb + lane * 4) = pack4(kn);
    *(__half2*)(kshp + kb + 128 + 2 * lane) = __floats2half2_rn(pp.x, pp.y);
    // V: natural layout [bh][s][136], dim0 = v_t, dims 1..128 spatial (coalesced)
    const float4 vv = *(const float4*)(row + 128 + lane * 4);
    float sv = vv.x * vv.x + vv.y * vv.y + vv.z * vv.z + vv.w * vv.w;
    sv = warp_sum(sv);
    const long long vb = ((long long)b * H_ + h) * S_ * VDIM + (long long)s * VDIM;
    if (lane == 0) hsplit(sqrtf(sv + 1.f), vhp, vlp, vb);
    hsplit(vv.x, vhp, vlp, vb + 1 + lane * 4);
    hsplit(vv.y, vhp, vlp, vb + 2 + lane * 4);
    hsplit(vv.z, vhp, vlp, vb + 3 + lane * 4);
    hsplit(vv.w, vhp, vlp, vb + 4 + lane * 4);
}

__global__ void __launch_bounds__(256)
final_t_kernel(float* __restrict__ out)
{
    const int row = blockIdx.x, tid = threadIdx.x;
    float* p = out + (size_t)row * 2048;
    __shared__ float sh[8];
    float local = 0.f;
    for (int i = 1 + tid; i < 2048; i += 256) { float v = p[i]; local += v * v; }
    float tot = block_sum_256(local, sh);
    if (tid == 0) p[0] = sqrtf(tot + 1.f);
}

extern "C" void kernel_launch(void* const* d_in, const int* in_sizes, int n_in,
                              void* d_out, int out_size)
{
    (void)in_sizes; (void)n_in; (void)out_size;
    const float* x      = (const float*)d_in[0];
    const float* fc     = (const float*)d_in[1];
    const float* fs     = (const float*)d_in[2];
    const float* wq_w   = (const float*)d_in[4];
    const float* wq_b   = (const float*)d_in[5];
    const float* wkva_w = (const float*)d_in[6];
    const float* wkva_b = (const float*)d_in[7];
    const float* kvnw   = (const float*)d_in[8];
    const float* wkvb_w = (const float*)d_in[9];
    const float* wkvb_b = (const float*)d_in[10];
    const float* wo_w   = (const float*)d_in[11];
    const float* wo_b   = (const float*)d_in[12];
    float* out = (float*)d_out;

    float *qkva, *kpe, *kv2, *tq, *tk, *biasqa;
    cudaGetSymbolAddress((void**)&qkva, g_qkva);
    cudaGetSymbolAddress((void**)&kpe, g_kpe);
    cudaGetSymbolAddress((void**)&kv2, g_kv2);
    cudaGetSymbolAddress((void**)&tq, g_tq);
    cudaGetSymbolAddress((void**)&tk, g_tk);
    cudaGetSymbolAddress((void**)&biasqa, g_biasqa);
    __half *xh, *wqkva, *kvnh, *wkvbh, *ch, *woh, *qsh, *ksh, *vth, *vtl;
    cudaGetSymbolAddress((void**)&xh, g_xh);
    cudaGetSymbolAddress((void**)&wqkva, g_wqkva);
    cudaGetSymbolAddress((void**)&kvnh, g_kvnh);
    cudaGetSymbolAddress((void**)&wkvbh, g_wkvbh);
    cudaGetSymbolAddress((void**)&ch, g_ch);
    cudaGetSymbolAddress((void**)&woh, g_woh);
    cudaGetSymbolAddress((void**)&qsh, g_qsh);
    cudaGetSymbolAddress((void**)&ksh, g_ksh);
    cudaGetSymbolAddress((void**)&vth, g_vth);
    cudaGetSymbolAddress((void**)&vtl, g_vtl);

    cudaFuncSetAttribute(gemm_h1, cudaFuncAttributeMaxDynamicSharedMemorySize, (int)DSMEM_H);
    cudaFuncSetAttribute(fused_attn, cudaFuncAttributeMaxDynamicSharedMemorySize, (int)DSMEM_F);

    const dim3 blk(256);
    // vectorized converts: x, wq, wkva are contiguous -> 1D (16B-aligned)
    convert_h4_1d<<<(M_ * 2048 / 4 + 255) / 256, blk>>>(
        (const float4*)x, (uint2*)xh, M_ * 2048 / 4);
    convert_h4_1d<<<(3072 * 2048 / 4 + 255) / 256, blk>>>(
        (const float4*)wq_w, (uint2*)wqkva, 3072 * 2048 / 4);
    convert_h4_1d<<<(576 * 2048 / 4 + 255) / 256, blk>>>(
        (const float4*)wkva_w, (uint2*)(wqkva + (size_t)3072 * 2048), 576 * 2048 / 4);
    convert_h4_2d<<<dim3(1, 4096), blk>>>(wkvb_w, 513, wkvbh, KVN, 513);
    convert_h4_2d<<<dim3(3, 2047), blk>>>(wo_w, 2064, woh, KCT, 2064);
    biascat_kernel<<<15, blk>>>(wq_b, wkva_b, biasqa);

    // fused Q + KV-A projection: (4096x2048) @ (3712x2048)^T
    gemm_h1<<<dim3(29, 32), blk, DSMEM_H>>>(xh, 2048, wqkva, 2048,
                                            qkva, NQA, biasqa, 3648, 2048);
    rmsnorm_kpe_kernel<<<M_, blk>>>(qkva, kvnw, fc, fs, kvnh, kpe);
    // KV-B proj: (4096x576) @ (4096x576)^T
    gemm_h1<<<dim3(32, 32), blk, DSMEM_H>>>(kvnh, KVN, wkvbh, KVN,
                                            kv2, 4096, wkvb_b, 4096, KVN);
    post_q_kernel<<<(M_ * H_) / 8, blk>>>(qkva, fc, fs, qsh, tq);
    post_kv_kernel<<<(M_ * H_) / 8, blk>>>(kv2, kpe, ksh, tk, vth, vtl);
    fused_attn<<<dim3(8, 64), blk, DSMEM_F>>>(qsh, ksh, tq, tk, vth, vtl, ch);
    // out proj: (4096x2112) @ (2047x2112)^T -> out[:,1:]
    gemm_h1<<<dim3(16, 32), blk, DSMEM_H>>>(ch, KCT, woh, KCT,
                                            out + 1, 2048, wo_b, 2047, KCT);
    final_t_kernel<<<M_, blk>>>(out);
}

// round 13
// speedup vs baseline: 7.5598x; 1.0098x over previous
#include <cuda_runtime.h>
#include <cuda_fp16.h>
#include <math.h>
#include <stdint.h>

namespace {
constexpr int B_ = 4, S_ = 1024, H_ = 16;
constexpr int M_ = B_ * S_;
constexpr float SC2 = 0.14396396f * 1.44269504f;    // 2/sqrt(193) * log2(e)
constexpr int KQS = 192, KVN = 576, KCT = 2080, VDIM = 136;
constexpr int NQA = 3712;                            // 3072 (q) + 576 (kva) + 64 pad
constexpr size_t DSMEM_H = 2 * 2 * 10240;            // fp16 gemm: 2 stages x 2 arrays
// attn: 2 full K tiles (2x51200) + V hi/lo (2x34816) + t_k (512)
constexpr size_t DSMEM_F = 2 * 51200 + 2 * 34816 + 512;  // 172544
}

// fp32 scratch
__device__ float g_qkva[(size_t)M_ * NQA];
__device__ float g_kpe[(size_t)M_ * 64];
__device__ float g_kv2[(size_t)M_ * 4096];
__device__ float g_tq[(size_t)64 * S_], g_tk[(size_t)64 * S_];
__device__ float g_biasqa[NQA];
// fp16 projection operands
__device__ __half g_xh[(size_t)M_ * 2048];
__device__ __half g_wqkva[(size_t)NQA * 2048];       // rows 3648..3711 stay 0
__device__ __half g_kvnh[(size_t)M_ * KVN];
__device__ __half g_wkvbh[(size_t)4096 * KVN];
__device__ __half g_ch[(size_t)M_ * KCT];            // cols 2064..2079 stay 0
__device__ __half g_woh[(size_t)2048 * KCT];
// fp16 attention operands (V natural token-major: [bh][s][136], dims 129..135 stay 0)
__device__ __half g_qsh[(size_t)64 * S_ * KQS];
__device__ __half g_ksh[(size_t)64 * S_ * KQS];
__device__ __half g_vth[(size_t)64 * S_ * VDIM], g_vtl[(size_t)64 * S_ * VDIM];

__device__ __forceinline__ uint32_t cvta_smem(const void* p) {
    uint32_t a;
    asm("{ .reg .u64 t; cvta.to.shared.u64 t, %1; cvt.u32.u64 %0, t; }" : "=r"(a) : "l"(p));
    return a;
}
#define CPASYNC16(s, g) asm volatile("cp.async.cg.shared.global [%0], [%1], 16;" :: "r"(s), "l"(g) : "memory")
#define CPCOMMIT()      asm volatile("cp.async.commit_group;" ::: "memory")
#define CPWAIT(n)       asm volatile("cp.async.wait_group %0;" :: "n"(n) : "memory")

__device__ __forceinline__ void ldsm_x4(uint32_t* r, uint32_t a) {
    asm volatile("ldmatrix.sync.aligned.m8n8.x4.shared.b16 {%0,%1,%2,%3}, [%4];"
                 : "=r"(r[0]), "=r"(r[1]), "=r"(r[2]), "=r"(r[3]) : "r"(a));
}
__device__ __forceinline__ void ldsm_x2(uint32_t* r, uint32_t a) {
    asm volatile("ldmatrix.sync.aligned.m8n8.x2.shared.b16 {%0,%1}, [%2];"
                 : "=r"(r[0]), "=r"(r[1]) : "r"(a));
}
__device__ __forceinline__ void ldsm_x2t(uint32_t* r, uint32_t a) {
    asm volatile("ldmatrix.sync.aligned.m8n8.x2.trans.shared.b16 {%0,%1}, [%2];"
                 : "=r"(r[0]), "=r"(r[1]) : "r"(a));
}
__device__ __forceinline__ void mma_f16(float* d, const uint32_t* a, const uint32_t* b) {
    asm volatile("mma.sync.aligned.m16n8k16.row.col.f32.f16.f16.f32 "
                 "{%0,%1,%2,%3}, {%4,%5,%6,%7}, {%8,%9}, {%0,%1,%2,%3};"
                 : "+f"(d[0]), "+f"(d[1]), "+f"(d[2]), "+f"(d[3])
                 : "r"(a[0]), "r"(a[1]), "r"(a[2]), "r"(a[3]), "r"(b[0]), "r"(b[1]));
}
__device__ __forceinline__ uint32_t packh2(float x, float y) {
    __half2 h = __floats2half2_rn(x, y);
    return *reinterpret_cast<uint32_t*>(&h);
}
__device__ __forceinline__ float warp_sum(float v) {
#pragma unroll
    for (int o = 16; o; o >>= 1) v += __shfl_xor_sync(0xffffffffu, v, o);
    return v;
}
__device__ __forceinline__ float block_sum_256(float v, float* sh) {
    int tid = threadIdx.x;
#pragma unroll
    for (int o = 16; o; o >>= 1) v += __shfl_xor_sync(0xffffffffu, v, o);
    __syncthreads();
    if ((tid & 31) == 0) sh[tid >> 5] = v;
    __syncthreads();
    if (tid < 32) {
        float t = (tid < 8) ? sh[tid] : 0.f;
#pragma unroll
        for (int o = 4; o; o >>= 1) t += __shfl_xor_sync(0xffffffffu, t, o);
        if (tid == 0) sh[0] = t;
    }
    __syncthreads();
    return sh[0];
}
__device__ __forceinline__ void hsplit(float v, __half* hi, __half* lo, long long i) {
    __half h = __float2half_rn(v);
    hi[i] = h;
    lo[i] = __float2half_rn(v - __half2float(h));
}
__device__ __forceinline__ uint2 pack4(float4 v) {
    __half2 a = __floats2half2_rn(v.x, v.y);
    __half2 b = __floats2half2_rn(v.z, v.w);
    uint2 o;
    o.x = *reinterpret_cast<uint32_t*>(&a);
    o.y = *reinterpret_cast<uint32_t*>(&b);
    return o;
}

// ============ single fp16 GEMM (projections): C = A @ B^T + bias ============
__global__ void __launch_bounds__(256, 2)
gemm_h1(const __half* __restrict__ A, int lda,
        const __half* __restrict__ Bm, int ldb,
        float* __restrict__ C, int ldc,
        const float* __restrict__ bias, int Nreal, int K)
{
    const int bm = blockIdx.y * 128, bn = blockIdx.x * 128;
    const int nch = K >> 5;
    extern __shared__ __align__(16) char smem[];
    const uint32_t sbase = cvta_smem(smem);
    const int tid = threadIdx.x, wid = tid >> 5, lane = tid & 31;
    const int wm = (wid >> 2) * 64, wn = (wid & 3) * 32;

    float acc[4][4][4] = {};
    const __half* srcs[2] = {A, Bm};

    auto load_stage = [&](int s, int c) {
        const long long k0 = (long long)c * 32;
#pragma unroll
        for (int arr = 0; arr < 2; ++arr) {
            const __half* src = srcs[arr];
            const int ld = (arr == 0) ? lda : ldb;
            const int ro = (arr == 0) ? bm : bn;
            const uint32_t base = sbase + (uint32_t)s * 20480u + (uint32_t)arr * 10240u;
#pragma unroll
            for (int j = 0; j < 2; ++j) {
                const int cid = tid + j * 256;
                const int row = cid >> 2, ch = cid & 3;
                CPASYNC16(base + (uint32_t)(row * 80 + ch * 16),
                          src + (long long)(ro + row) * ld + k0 + ch * 8);
            }
        }
        CPCOMMIT();
    };

    load_stage(0, 0);
    for (int c = 0; c < nch; ++c) {
        if (c + 1 < nch) { load_stage((c + 1) & 1, c + 1); CPWAIT(1); }
        else             { CPWAIT(0); }
        __syncthreads();
        const uint32_t st = sbase + (uint32_t)(c & 1) * 20480u;
#pragma unroll
        for (int ks = 0; ks < 2; ++ks) {
            uint32_t ah[4][4], bh[4][2];
            const int arow = wm + (lane & 15);
            const int acol = ks * 16 + (lane >> 4) * 8;
#pragma unroll
            for (int mf = 0; mf < 4; ++mf)
                ldsm_x4(ah[mf], st + (uint32_t)((arow + mf * 16) * 80 + acol * 2));
            const int brow = wn + (lane & 7);
            const int bcol = ks * 16 + ((lane >> 3) & 1) * 8;
#pragma unroll
            for (int nf = 0; nf < 4; ++nf)
                ldsm_x2(bh[nf], st + 10240u + (uint32_t)((brow + nf * 8) * 80 + bcol * 2));
#pragma unroll
            for (int mf = 0; mf < 4; ++mf)
#pragma unroll
                for (int nf = 0; nf < 4; ++nf)
                    mma_f16(acc[mf][nf], ah[mf], bh[nf]);
        }
        __syncthreads();
    }
#pragma unroll
    for (int mf = 0; mf < 4; ++mf) {
        const long long r0 = bm + wm + mf * 16 + (lane >> 2);
#pragma unroll
        for (int nf = 0; nf < 4; ++nf) {
            const int col = bn + wn + nf * 8 + (lane & 3) * 2;
            const float b0 = bias ? bias[min(col, Nreal - 1)] : 0.f;
            const float b1 = bias ? bias[min(col + 1, Nreal - 1)] : 0.f;
            if (col < Nreal) {
                C[r0 * ldc + col] = acc[mf][nf][0] + b0;
                C[(r0 + 8) * ldc + col] = acc[mf][nf][2] + b0;
            }
            if (col + 1 < Nreal) {
                C[r0 * ldc + col + 1] = acc[mf][nf][1] + b1;
                C[(r0 + 8) * ldc + col + 1] = acc[mf][nf][3] + b1;
            }
        }
    }
}

// ============ fused flash-attention + Lorentz centroid ============
// Q fragments register-resident; K full-tile double-buffered (pitch 400B);
// V natural layout + ldmatrix.trans; t_q*t_k exact fp32.
// grid (8, 64): x -> q-block (descending), y -> (b*H+h)
__global__ void __launch_bounds__(256, 1)
fused_attn(const __half* __restrict__ qsh, const __half* __restrict__ ksh,
           const float* __restrict__ tqg, const float* __restrict__ tkg,
           const __half* __restrict__ vh, const __half* __restrict__ vl,
           __half* __restrict__ ch)
{
    const int iq = 7 - (int)blockIdx.x;
    const int bh = (int)blockIdx.y;
    const long long qkbase = (long long)bh * S_ * KQS;
    const long long vgbase = (long long)bh * S_ * VDIM;
    extern __shared__ __align__(16) char smem[];
    const uint32_t sbase = cvta_smem(smem);
    const uint32_t vsH = sbase + 102400u, vsL = vsH + 34816u;
    float* tks = (float*)(smem + 102400u + 2 * 34816u);
    const int tid = threadIdx.x, w = tid >> 5, lane = tid & 31;

    const __half* qh_g = qsh + qkbase + (long long)iq * 128 * KQS;
    const float tq0 = tqg[(long long)bh * S_ + iq * 128 + w * 16 + (lane >> 2)];
    const float tq1 = tqg[(long long)bh * S_ + iq * 128 + w * 16 + (lane >> 2) + 8];

    // 128x192 fp16 tile loader into pitch-400 smem (one commit group)
    auto load_tile192 = [&](uint32_t dst, const __half* src) {
#pragma unroll
        for (int t2 = 0; t2 < 12; ++t2) {
            const int idx = tid + t2 * 256;
            const int row = idx / 24, seg = idx % 24;
            CPASYNC16(dst + (uint32_t)(row * 400 + seg * 16),
                      src + (long long)row * KQS + seg * 8);
        }
        CPCOMMIT();
    };
    auto load_vtile = [&](int j) {
        for (int idx = tid; idx < 2176; idx += 256) {
            const int row = idx / 17, seg = idx % 17;
            const long long g = vgbase + (long long)(j * 128 + row) * VDIM + seg * 8;
            CPASYNC16(vsH + (uint32_t)(row * 272 + seg * 16), vh + g);
            CPASYNC16(vsL + (uint32_t)(row * 272 + seg * 16), vl + g);
        }
        CPCOMMIT();
    };

    // ---- stage Q once into K-stage0 region and preload A-fragments ----
    uint32_t qf[12][4];
    {
        load_tile192(sbase, qh_g);
        CPWAIT(0);
        __syncthreads();
#pragma unroll
        for (int kk = 0; kk < 12; ++kk) {
            const uint32_t aoff =
                (uint32_t)((w * 16 + (lane & 15)) * 400 + (kk * 16 + (lane >> 4) * 8) * 2);
            ldsm_x4(qf[kk], sbase + aoff);
        }
        __syncthreads();   // K-stage0 free
    }

    float O[17][4] = {};
    float m0 = -1e30f, m1 = -1e30f, l0 = 0.f, l1 = 0.f;

    // prologue: K_0 into stage0, V_0 (groups: [K0, V0])
    load_tile192(sbase, ksh + qkbase);
    load_vtile(0);

    for (int j = 0; j <= iq; ++j) {
        const uint32_t kst = sbase + (uint32_t)(j & 1) * 51200u;
        const int jn = min(j + 1, iq);
        if (tid < 128) tks[tid] = tkg[(long long)bh * S_ + j * 128 + tid];
        // prefetch K_{j+1} into other stage (groups: [K_j, V_j, K_next])
        load_tile192(sbase + (uint32_t)(jn & 1) * 51200u,
                     ksh + qkbase + (long long)jn * 128 * KQS);
        CPWAIT(2);          // K_j resident
        __syncthreads();

        // QK: 12 k-chunks, no intra-tile syncs
        float acc[16][4] = {};
#pragma unroll
        for (int kc = 0; kc < 12; ++kc) {
#pragma unroll
            for (int nf = 0; nf < 16; ++nf) {
                const uint32_t boff =
                    (uint32_t)((nf * 8 + (lane & 7)) * 400 +
                               (kc * 16 + ((lane >> 3) & 1) * 8) * 2);
                uint32_t kk[2];
                ldsm_x2(kk, kst + boff);
                mma_f16(acc[nf], qf[kc], kk);
            }
        }
        // subtract fp32 time-component product
        {
            const int c0b = (lane & 3) * 2;
#pragma unroll
            for (int nf = 0; nf < 16; ++nf) {
                const float k0v = tks[nf * 8 + c0b], k1v = tks[nf * 8 + c0b + 1];
                acc[nf][0] -= tq0 * k0v; acc[nf][1] -= tq0 * k1v;
                acc[nf][2] -= tq1 * k0v; acc[nf][3] -= tq1 * k1v;
            }
        }
        if (j == iq) {   // diagonal tile mask
            const int rt0 = w * 16 + (lane >> 2), rt1 = rt0 + 8;
#pragma unroll
            for (int nf = 0; nf < 16; ++nf) {
                const int ct = nf * 8 + (lane & 3) * 2;
                if (ct > rt0)     acc[nf][0] = -1e30f;
                if (ct + 1 > rt0) acc[nf][1] = -1e30f;
                if (ct > rt1)     acc[nf][2] = -1e30f;
                if (ct + 1 > rt1) acc[nf][3] = -1e30f;
            }
        }
        // online softmax (quad shuffles only)
        float mx0 = -1e30f, mx1 = -1e30f;
#pragma unroll
        for (int nf = 0; nf < 16; ++nf) {
            mx0 = fmaxf(mx0, fmaxf(acc[nf][0], acc[nf][1]));
            mx1 = fmaxf(mx1, fmaxf(acc[nf][2], acc[nf][3]));
        }
        mx0 = fmaxf(mx0, __shfl_xor_sync(~0u, mx0, 1));
        mx0 = fmaxf(mx0, __shfl_xor_sync(~0u, mx0, 2));
        mx1 = fmaxf(mx1, __shfl_xor_sync(~0u, mx1, 1));
        mx1 = fmaxf(mx1, __shfl_xor_sync(~0u, mx1, 2));
        const float mn0 = fmaxf(m0, mx0), mn1 = fmaxf(m1, mx1);
        const float a0 = exp2f((m0 - mn0) * SC2), a1 = exp2f((m1 - mn1) * SC2);
        l0 *= a0; l1 *= a1;
#pragma unroll
        for (int nf = 0; nf < 17; ++nf) {
            O[nf][0] *= a0; O[nf][1] *= a0; O[nf][2] *= a1; O[nf][3] *= a1;
        }
        float s0 = 0.f, s1 = 0.f;
#pragma unroll
        for (int nf = 0; nf < 16; ++nf) {
            acc[nf][0] = exp2f((acc[nf][0] - mn0) * SC2);
            acc[nf][1] = exp2f((acc[nf][1] - mn0) * SC2);
            acc[nf][2] = exp2f((acc[nf][2] - mn1) * SC2);
            acc[nf][3] = exp2f((acc[nf][3] - mn1) * SC2);
            s0 += acc[nf][0] + acc[nf][1];
            s1 += acc[nf][2] + acc[nf][3];
        }
        s0 += __shfl_xor_sync(~0u, s0, 1); s0 += __shfl_xor_sync(~0u, s0, 2);
        s1 += __shfl_xor_sync(~0u, s1, 1); s1 += __shfl_xor_sync(~0u, s1, 2);
        l0 += s0; l1 += s1; m0 = mn0; m1 = mn1;

        CPWAIT(1);          // V_j resident (K_next may still be in flight)
        __syncthreads();
        // PV: P single fp16, V 2-term fp16, B fragments via ldmatrix.trans
#pragma unroll
        for (int kf = 0; kf < 8; ++kf) {
            uint32_t Ph[4];
            Ph[0] = packh2(acc[2 * kf][0], acc[2 * kf][1]);
            Ph[1] = packh2(acc[2 * kf][2], acc[2 * kf][3]);
            Ph[2] = packh2(acc[2 * kf + 1][0], acc[2 * kf + 1][1]);
            Ph[3] = packh2(acc[2 * kf + 1][2], acc[2 * kf + 1][3]);
            const uint32_t vrow = (uint32_t)((kf * 16 + (lane & 15)) * 272);
#pragma unroll
            for (int nf = 0; nf < 17; ++nf) {
                uint32_t vh2[2], vl2[2];
                ldsm_x2t(vh2, vsH + vrow + (uint32_t)(nf * 16));
                ldsm_x2t(vl2, vsL + vrow + (uint32_t)(nf * 16));
                mma_f16(O[nf], Ph, vh2);
                mma_f16(O[nf], Ph, vl2);
            }
        }
        __syncthreads();    // V reads done before reissue
        load_vtile(jn);     // V_{j+1} (hides under next QK); harmless reload on last j
    }
    // epilogue: avg = O/l, Lorentz centroid normalize, write cent (fp16)
    const float i0 = 1.f / l0, i1 = 1.f / l1;
    float ss0 = 0.f, ss1 = 0.f;
#pragma unroll
    for (int nf = 0; nf < 17; ++nf) {
        O[nf][0] *= i0; O[nf][1] *= i0; O[nf][2] *= i1; O[nf][3] *= i1;
        ss0 += O[nf][0] * O[nf][0] + O[nf][1] * O[nf][1];
        ss1 += O[nf][2] * O[nf][2] + O[nf][3] * O[nf][3];
    }
    ss0 += __shfl_xor_sync(~0u, ss0, 1); ss0 += __shfl_xor_sync(~0u, ss0, 2);
    ss1 += __shfl_xor_sync(~0u, ss1, 1); ss1 += __shfl_xor_sync(~0u, ss1, 2);
    const float t0 = __shfl_sync(~0u, O[0][0], lane & ~3);
    const float t1 = __shfl_sync(~0u, O[0][2], lane & ~3);
    const float d0 = rsqrtf(fmaxf(fabsf(2.f * t0 * t0 - ss0), 1e-8f));
    const float d1 = rsqrtf(fmaxf(fabsf(2.f * t1 * t1 - ss1), 1e-8f));
    const int hh = bh & 15;
    const long long tok0 = (long long)(bh >> 4) * 1024 + iq * 128 + w * 16 + (lane >> 2);
    const long long o0 = tok0 * KCT + hh * 129, o1 = (tok0 + 8) * KCT + hh * 129;
#pragma unroll
    for (int nf = 0; nf < 17; ++nf) {
        const int cc = nf * 8 + (lane & 3) * 2;
        if (cc < 129) {
            ch[o0 + cc] = __float2half_rn(O[nf][0] * d0);
            ch[o1 + cc] = __float2half_rn(O[nf][2] * d1);
        }
        if (cc + 1 < 129) {
            ch[o0 + cc + 1] = __float2half_rn(O[nf][1] * d0);
            ch[o1 + cc + 1] = __float2half_rn(O[nf][3] * d1);
        }
    }
}

// ---------- elementwise (vectorized) ----------
__global__ void __launch_bounds__(256)
convert_h4_1d(const float4* __restrict__ src, uint2* __restrict__ dst, int n4)
{
    const int i = blockIdx.x * 256 + threadIdx.x;
    if (i < n4) dst[i] = pack4(src[i]);
}

// scalar 32-bit loads (no alignment requirement on odd lds), vector 8B store
__global__ void __launch_bounds__(256)
convert_h4_2d(const float* __restrict__ src, int lds,
              __half* __restrict__ dst, int ldd, int cols)
{
    const int r = blockIdx.y;
    const int c4 = blockIdx.x * 256 + threadIdx.x;
    const int cols4 = cols >> 2;
    if (c4 < cols4) {
        const float* p = src + (long long)r * lds + c4 * 4;
        float4 v;
        v.x = p[0]; v.y = p[1]; v.z = p[2]; v.w = p[3];
        *(uint2*)(dst + (long long)r * ldd + c4 * 4) = pack4(v);
    } else if (c4 < cols4 + (cols & 3)) {
        const int c = cols4 * 4 + (c4 - cols4);
        dst[(long long)r * ldd + c] = __float2half_rn(src[(long long)r * lds + c]);
    }
}

__global__ void __launch_bounds__(256)
biascat_kernel(const float* __restrict__ a, const float* __restrict__ b,
               float* __restrict__ dst)
{
    const int i = blockIdx.x * 256 + threadIdx.x;
    if (i >= NQA) return;
    if (i < 3072) dst[i] = a[i];
    else if (i < 3648) dst[i] = b[i - 3072];
    else dst[i] = 0.f;
}

__global__ void __launch_bounds__(256)
rmsnorm_kpe_kernel(const float* __restrict__ qkva, const float* __restrict__ w,
                   const float* __restrict__ fc, const float* __restrict__ fs,
                   __half* __restrict__ kvnh, float* __restrict__ kpe)
{
    const int tok = blockIdx.x, s = tok & (S_ - 1), tid = threadIdx.x;
    const float* in = qkva + (size_t)tok * NQA + 3072;
    __shared__ float sp[512];
    __shared__ float sh[8];
    float local = 0.f;
    for (int i = tid; i < 512; i += 256) { float v = in[i]; local += v * v; }
    float r = rsqrtf(block_sum_256(local, sh) * (1.0f / 512.f) + 1e-6f);
    float l2 = 0.f;
    for (int i = tid; i < 512; i += 256) {
        float v = in[i] * r * w[i];
        sp[i] = v;
        l2 += v * v;
    }
    float tot2 = block_sum_256(l2, sh);
    const long long ob = (long long)tok * KVN;
    if (tid == 0) kvnh[ob] = __float2half_rn(sqrtf(tot2 + 1.f));
    for (int i = tid; i < 512; i += 256) kvnh[ob + 1 + i] = __float2half_rn(sp[i]);
    if (tid < 32) {
        float x1 = in[512 + 2 * tid], x2 = in[512 + 2 * tid + 1];
        float c = fc[s * 32 + tid], sn = fs[s * 32 + tid];
        kpe[(size_t)tok * 64 + 2 * tid]     = x1 * c - x2 * sn;
        kpe[(size_t)tok * 64 + 2 * tid + 1] = x1 * sn + x2 * c;
    }
}

__global__ void __launch_bounds__(256)
post_q_kernel(const float* __restrict__ qkva, const float* __restrict__ fc,
              const float* __restrict__ fs,
              __half* __restrict__ qshp, float* __restrict__ tq)
{
    const int gw = (blockIdx.x * blockDim.x + threadIdx.x) >> 5, lane = threadIdx.x & 31;
    if (gw >= M_ * H_) return;
    const int h = gw % H_, tok = gw / H_, b = tok / S_, s = tok & (S_ - 1);
    const float* qr = qkva + (size_t)tok * NQA + h * 192;
    const float4 qv = *(const float4*)(qr + lane * 4);
    const float c = fc[s * 32 + lane], sn = fs[s * 32 + lane];
    const float x1 = qr[128 + 2 * lane], x2 = qr[128 + 2 * lane + 1];
    const float r0 = x1 * c - x2 * sn, r1 = x1 * sn + x2 * c;
    float ss = r0 * r0 + r1 * r1 + qv.x * qv.x + qv.y * qv.y + qv.z * qv.z + qv.w * qv.w;
    ss = warp_sum(ss);
    const long long row = ((long long)b * H_ + h) * S_ + s;
    if (lane == 0) tq[row] = sqrtf(ss + 1.f);
    const long long ob = row * KQS;
    *(uint2*)(qshp + ob + lane * 4) = pack4(qv);
    *(__half2*)(qshp + ob + 128 + 2 * lane) = __floats2half2_rn(r0, r1);
}

__global__ void __launch_bounds__(256)
post_kv_kernel(const float* __restrict__ kv2, const float* __restrict__ kpe,
               __half* __restrict__ kshp, float* __restrict__ tk,
               __half* __restrict__ vhp, __half* __restrict__ vlp)
{
    const int gw = (blockIdx.x * blockDim.x + threadIdx.x) >> 5, lane = threadIdx.x & 31;
    if (gw >= M_ * H_) return;
    const int h = gw % H_, tok = gw / H_, b = tok / S_, s = tok & (S_ - 1);
    const float* row = kv2 + ((size_t)tok * H_ + h) * 256;
    const float* pe = kpe + (size_t)tok * 64;
    const float4 kn = *(const float4*)(row + lane * 4);
    const float2 pp = *(const float2*)(pe + lane * 2);
    float ss = kn.x * kn.x + kn.y * kn.y + kn.z * kn.z + kn.w * kn.w + pp.x * pp.x + pp.y * pp.y;
    ss = warp_sum(ss);
    const long long krow = ((long long)b * H_ + h) * S_ + s;
    if (lane == 0) tk[krow] = sqrtf(ss + 1.f);
    const long long kb = krow * KQS;
    *(uint2*)(kshp + kb + lane * 4) = pack4(kn);
    *(__half2*)(kshp + kb + 128 + 2 * lane) = __floats2half2_rn(pp.x, pp.y);
    const float4 vv = *(const float4*)(row + 128 + lane * 4);
    float sv = vv.x * vv.x + vv.y * vv.y + vv.z * vv.z + vv.w * vv.w;
    sv = warp_sum(sv);
    const long long vb = ((long long)b * H_ + h) * S_ * VDIM + (long long)s * VDIM;
    if (lane == 0) hsplit(sqrtf(sv + 1.f), vhp, vlp, vb);
    hsplit(vv.x, vhp, vlp, vb + 1 + lane * 4);
    hsplit(vv.y, vhp, vlp, vb + 2 + lane * 4);
    hsplit(vv.z, vhp, vlp, vb + 3 + lane * 4);
    hsplit(vv.w, vhp, vlp, vb + 4 + lane * 4);
}

__global__ void __launch_bounds__(256)
final_t_kernel(float* __restrict__ out)
{
    const int row = blockIdx.x, tid = threadIdx.x;
    float* p = out + (size_t)row * 2048;
    __shared__ float sh[8];
    float local = 0.f;
    for (int i = 1 + tid; i < 2048; i += 256) { float v = p[i]; local += v * v; }
    float tot = block_sum_256(local, sh);
    if (tid == 0) p[0] = sqrtf(tot + 1.f);
}

extern "C" void kernel_launch(void* const* d_in, const int* in_sizes, int n_in,
                              void* d_out, int out_size)
{
    (void)in_sizes; (void)n_in; (void)out_size;
    const float* x      = (const float*)d_in[0];
    const float* fc     = (const float*)d_in[1];
    const float* fs     = (const float*)d_in[2];
    const float* wq_w   = (const float*)d_in[4];
    const float* wq_b   = (const float*)d_in[5];
    const float* wkva_w = (const float*)d_in[6];
    const float* wkva_b = (const float*)d_in[7];
    const float* kvnw   = (const float*)d_in[8];
    const float* wkvb_w = (const float*)d_in[9];
    const float* wkvb_b = (const float*)d_in[10];
    const float* wo_w   = (const float*)d_in[11];
    const float* wo_b   = (const float*)d_in[12];
    float* out = (float*)d_out;

    float *qkva, *kpe, *kv2, *tq, *tk, *biasqa;
    cudaGetSymbolAddress((void**)&qkva, g_qkva);
    cudaGetSymbolAddress((void**)&kpe, g_kpe);
    cudaGetSymbolAddress((void**)&kv2, g_kv2);
    cudaGetSymbolAddress((void**)&tq, g_tq);
    cudaGetSymbolAddress((void**)&tk, g_tk);
    cudaGetSymbolAddress((void**)&biasqa, g_biasqa);
    __half *xh, *wqkva, *kvnh, *wkvbh, *ch, *woh, *qsh, *ksh, *vth, *vtl;
    cudaGetSymbolAddress((void**)&xh, g_xh);
    cudaGetSymbolAddress((void**)&wqkva, g_wqkva);
    cudaGetSymbolAddress((void**)&kvnh, g_kvnh);
    cudaGetSymbolAddress((void**)&wkvbh, g_wkvbh);
    cudaGetSymbolAddress((void**)&ch, g_ch);
    cudaGetSymbolAddress((void**)&woh, g_woh);
    cudaGetSymbolAddress((void**)&qsh, g_qsh);
    cudaGetSymbolAddress((void**)&ksh, g_ksh);
    cudaGetSymbolAddress((void**)&vth, g_vth);
    cudaGetSymbolAddress((void**)&vtl, g_vtl);

    cudaFuncSetAttribute(gemm_h1, cudaFuncAttributeMaxDynamicSharedMemorySize, (int)DSMEM_H);
    cudaFuncSetAttribute(fused_attn, cudaFuncAttributeMaxDynamicSharedMemorySize, (int)DSMEM_F);

    const dim3 blk(256);
    convert_h4_1d<<<(M_ * 2048 / 4 + 255) / 256, blk>>>(
        (const float4*)x, (uint2*)xh, M_ * 2048 / 4);
    convert_h4_1d<<<(3072 * 2048 / 4 + 255) / 256, blk>>>(
        (const float4*)wq_w, (uint2*)wqkva, 3072 * 2048 / 4);
    convert_h4_1d<<<(576 * 2048 / 4 + 255) / 256, blk>>>(
        (const float4*)wkva_w, (uint2*)(wqkva + (size_t)3072 * 2048), 576 * 2048 / 4);
    convert_h4_2d<<<dim3(1, 4096), blk>>>(wkvb_w, 513, wkvbh, KVN, 513);
    convert_h4_2d<<<dim3(3, 2047), blk>>>(wo_w, 2064, woh, KCT, 2064);
    biascat_kernel<<<15, blk>>>(wq_b, wkva_b, biasqa);

    // fused Q + KV-A projection: (4096x2048) @ (3712x2048)^T
    gemm_h1<<<dim3(29, 32), blk, DSMEM_H>>>(xh, 2048, wqkva, 2048,
                                            qkva, NQA, biasqa, 3648, 2048);
    rmsnorm_kpe_kernel<<<M_, blk>>>(qkva, kvnw, fc, fs, kvnh, kpe);
    // KV-B proj: (4096x576) @ (4096x576)^T
    gemm_h1<<<dim3(32, 32), blk, DSMEM_H>>>(kvnh, KVN, wkvbh, KVN,
                                            kv2, 4096, wkvb_b, 4096, KVN);
    post_q_kernel<<<(M_ * H_) / 8, blk>>>(qkva, fc, fs, qsh, tq);
    post_kv_kernel<<<(M_ * H_) / 8, blk>>>(kv2, kpe, ksh, tk, vth, vtl);
    fused_attn<<<dim3(8, 64), blk, DSMEM_F>>>(qsh, ksh, tq, tk, vth, vtl, ch);
    // out proj: (4096x2080) @ (2047x2080)^T -> out[:,1:]
    gemm_h1<<<dim3(16, 32), blk, DSMEM_H>>>(ch, KCT, woh, KCT,
                                            out + 1, 2048, wo_b, 2047, KCT);
    final_t_kernel<<<M_, blk>>>(out);
}